// round 3
// baseline (speedup 1.0000x reference)
#include <cuda_runtime.h>
#include <math.h>

#define Bv   16
#define Tv   24
#define Nv   512
#define Dv   64
#define Hv   4
#define HDv  16
#define Fv   256
#define BTv  (Bv*Tv)           // 384
#define BTNv (BTv*Nv)          // 196608
#define RTILES (BTNv/64)       // 3072

// ---------------- scratch (static device globals; no allocation) ----------------
__device__ float g_dinv[Nv];
__device__ float g_Ahat[Nv*Nv];
__device__ float g_q  [BTNv*Dv];
__device__ float g_k  [BTNv*Dv];
__device__ float g_v  [BTNv*Dv];
__device__ float g_att[BTNv*Dv];
__device__ float g_h  [BTNv*Dv];
__device__ float g_p1 [BTNv*Dv];
__device__ float g_p2 [BTNv*Dv];
__device__ float g_h2 [BTNv*Dv];
__device__ float g_u  [BTNv*Fv];

// ---------------- LayerNorm epilogue over a 64x64 smem tile ----------------
// sO: [64][64] row-major (pitch 64). 8 warps, each handles 8 rows; lane covers
// elements (lane, lane+32). Writes normalized rows to out[(r0g+r)*64 + c].
__device__ __forceinline__ void ln_store(const float* sO, int r0g,
                                         const float* __restrict__ g,
                                         const float* __restrict__ b,
                                         float* __restrict__ out) {
    int warp = threadIdx.x >> 5, lane = threadIdx.x & 31;
    float gg0 = g[lane], gg1 = g[lane + 32];
    float bb0 = b[lane], bb1 = b[lane + 32];
    for (int r = warp; r < 64; r += 8) {
        float v0 = sO[r*64 + lane];
        float v1 = sO[r*64 + lane + 32];
        float s = v0 + v1;
        #pragma unroll
        for (int o = 16; o; o >>= 1) s += __shfl_xor_sync(0xffffffffu, s, o);
        float m = s * (1.0f/64.0f);
        float d0 = v0 - m, d1 = v1 - m;
        float vs = d0*d0 + d1*d1;
        #pragma unroll
        for (int o = 16; o; o >>= 1) vs += __shfl_xor_sync(0xffffffffu, vs, o);
        float rs = rsqrtf(vs * (1.0f/64.0f) + 1e-5f);
        out[(r0g + r)*64 + lane]      = d0*rs*gg0 + bb0;
        out[(r0g + r)*64 + lane + 32] = d1*rs*gg1 + bb1;
    }
}

// ---------------- graph normalization ----------------
__global__ __launch_bounds__(128) void k_deg(const float* __restrict__ adj) {
    __shared__ float red[128];
    int m = blockIdx.x;
    float s = 0.f;
    for (int j = threadIdx.x; j < Nv; j += 128) s += adj[m*Nv + j];
    red[threadIdx.x] = s; __syncthreads();
    for (int o = 64; o; o >>= 1) {
        if (threadIdx.x < o) red[threadIdx.x] += red[threadIdx.x + o];
        __syncthreads();
    }
    if (threadIdx.x == 0) {
        float deg = red[0] + 1.0f;                 // A = adj + I
        g_dinv[m] = rsqrtf(fmaxf(deg, 1e-12f));
    }
}

__global__ __launch_bounds__(512) void k_ahat(const float* __restrict__ adj) {
    int i = blockIdx.x * 512 + threadIdx.x;
    int m = i >> 9, n = i & 511;
    float a = adj[i] + (m == n ? 1.0f : 0.0f);
    g_Ahat[i] = g_dinv[m] * a * g_dinv[n];
}

// ---------------- QKV projections (one x-tile, three weight sets) ----------------
__global__ __launch_bounds__(256) void k_qkv(const float* __restrict__ x,
    const float* __restrict__ Wq, const float* __restrict__ bq,
    const float* __restrict__ Wk, const float* __restrict__ bk,
    const float* __restrict__ Wv, const float* __restrict__ bv) {
    __shared__ float sA[64*65];
    __shared__ float sB[64*64];
    int tid = threadIdx.x;
    int r0g = blockIdx.x * 64;
    for (int i = tid; i < 4096; i += 256) {
        int m = i >> 6, k = i & 63;
        sA[m*65 + k] = x[(r0g + m)*64 + k];
    }
    int tr = tid >> 4, tc = tid & 15;
    int r0 = tr * 4, c0 = tc * 4;
    const float* W[3]  = {Wq, Wk, Wv};
    const float* bb[3] = {bq, bk, bv};
    float* outp[3]     = {g_q, g_k, g_v};
    #pragma unroll
    for (int mm = 0; mm < 3; mm++) {
        __syncthreads();
        for (int i = tid; i < 4096; i += 256) sB[i] = W[mm][i];
        __syncthreads();
        float acc[4][4] = {};
        #pragma unroll 16
        for (int k = 0; k < 64; k++) {
            float4 b4 = *(const float4*)&sB[k*64 + c0];
            #pragma unroll
            for (int q = 0; q < 4; q++) {
                float a = sA[(r0+q)*65 + k];
                acc[q][0] = fmaf(a, b4.x, acc[q][0]);
                acc[q][1] = fmaf(a, b4.y, acc[q][1]);
                acc[q][2] = fmaf(a, b4.z, acc[q][2]);
                acc[q][3] = fmaf(a, b4.w, acc[q][3]);
            }
        }
        float4 bi = *(const float4*)&bb[mm][c0];
        #pragma unroll
        for (int q = 0; q < 4; q++) {
            float4 o;
            o.x = acc[q][0] + bi.x; o.y = acc[q][1] + bi.y;
            o.z = acc[q][2] + bi.z; o.w = acc[q][3] + bi.w;
            *(float4*)&outp[mm][(r0g + r0 + q)*64 + c0] = o;
        }
    }
}

// ---------------- temporal attention core (per b,n; all heads) ----------------
__global__ __launch_bounds__(256) void k_attn() {
    __shared__ float sq[Tv*64], sk[Tv*64], sv[Tv*64], so[Tv*64];
    __shared__ float ss[Hv*Tv*25];          // [h][tq][tk] pitch 25
    int tid = threadIdx.x;
    int n = blockIdx.x, b = blockIdx.y;
    for (int i = tid; i < Tv*64; i += 256) {
        int t = i >> 6, d = i & 63;
        int gidx = ((b*Tv + t)*Nv + n)*64 + d;
        sq[i] = g_q[gidx];
        sk[i] = g_k[gidx];
        sv[i] = g_v[gidx];
    }
    __syncthreads();
    // scores (all heads): ss[h][tq][tk]
    for (int i = tid; i < Hv*Tv*Tv; i += 256) {
        int h = i / (Tv*Tv);
        int rem = i - h*Tv*Tv;
        int tq = rem / Tv, tk = rem - tq*Tv;
        float s = 0.f;
        #pragma unroll
        for (int e = 0; e < HDv; e++)
            s = fmaf(sq[tq*64 + h*HDv + e], sk[tk*64 + h*HDv + e], s);
        ss[(h*Tv + tq)*25 + tk] = s * 0.25f;   // scale = hd^-0.5
    }
    __syncthreads();
    // softmax over tk, one (h,tq) row per thread
    if (tid < Hv*Tv) {
        float* row = &ss[tid*25];
        float mx = -1e30f;
        #pragma unroll
        for (int tk = 0; tk < Tv; tk++) mx = fmaxf(mx, row[tk]);
        float sum = 0.f;
        #pragma unroll
        for (int tk = 0; tk < Tv; tk++) { float e = expf(row[tk]-mx); row[tk] = e; sum += e; }
        float inv = 1.0f / sum;
        #pragma unroll
        for (int tk = 0; tk < Tv; tk++) row[tk] *= inv;
    }
    __syncthreads();
    // att = probs @ v
    for (int i = tid; i < Hv*Tv*HDv; i += 256) {
        int h = i / (Tv*HDv);
        int rem = i - h*Tv*HDv;
        int tq = rem / HDv, e = rem - tq*HDv;
        float a = 0.f;
        #pragma unroll
        for (int tk = 0; tk < Tv; tk++)
            a = fmaf(ss[(h*Tv + tq)*25 + tk], sv[tk*64 + h*HDv + e], a);
        so[tq*64 + h*HDv + e] = a;
    }
    __syncthreads();
    for (int i = tid; i < Tv*64; i += 256) {
        int t = i >> 6, d = i & 63;
        g_att[((b*Tv + t)*Nv + n)*64 + d] = so[i];
    }
}

// ---------------- attention output proj + residual + LN -> g_h ----------------
__global__ __launch_bounds__(256) void k_attnout(const float* __restrict__ x,
    const float* __restrict__ Wo, const float* __restrict__ bo,
    const float* __restrict__ gt, const float* __restrict__ bt) {
    __shared__ float sA[64*65];
    __shared__ float sB[64*64];
    int tid = threadIdx.x;
    int r0g = blockIdx.x * 64;
    for (int i = tid; i < 4096; i += 256) {
        int m = i >> 6, k = i & 63;
        sA[m*65 + k] = g_att[(r0g + m)*64 + k];
    }
    for (int i = tid; i < 4096; i += 256) sB[i] = Wo[i];
    __syncthreads();
    int tr = tid >> 4, tc = tid & 15;
    int r0 = tr * 4, c0 = tc * 4;
    float acc[4][4] = {};
    #pragma unroll 16
    for (int k = 0; k < 64; k++) {
        float4 b4 = *(const float4*)&sB[k*64 + c0];
        #pragma unroll
        for (int q = 0; q < 4; q++) {
            float a = sA[(r0+q)*65 + k];
            acc[q][0] = fmaf(a, b4.x, acc[q][0]);
            acc[q][1] = fmaf(a, b4.y, acc[q][1]);
            acc[q][2] = fmaf(a, b4.z, acc[q][2]);
            acc[q][3] = fmaf(a, b4.w, acc[q][3]);
        }
    }
    __syncthreads();            // done reading sB; reuse as output tile
    float4 bi = *(const float4*)&bo[c0];
    #pragma unroll
    for (int q = 0; q < 4; q++) {
        float4 xv = *(const float4*)&x[(r0g + r0 + q)*64 + c0];
        float4 o;
        o.x = acc[q][0] + bi.x + xv.x; o.y = acc[q][1] + bi.y + xv.y;
        o.z = acc[q][2] + bi.z + xv.z; o.w = acc[q][3] + bi.w + xv.w;
        *(float4*)&sB[(r0+q)*64 + c0] = o;
    }
    __syncthreads();
    ln_store(sB, r0g, gt, bt, g_h);
}

// ---------------- batched Ahat @ prop (the big GEMM) ----------------
__global__ __launch_bounds__(256) void k_prop(int pass) {
    const float* __restrict__ in = pass ? g_p1 : g_h;
    float* __restrict__ out      = pass ? g_p2 : g_p1;
    __shared__ float sA[64*65];   // Ahat tile [m][k]
    __shared__ float sB[64*64];   // in tile   [k][d]
    int tid = threadIdx.x;
    int m0 = blockIdx.x * 64;
    int bt = blockIdx.y;
    int tr = tid >> 4, tc = tid & 15;
    int r0 = tr * 4, c0 = tc * 4;
    float acc[4][4] = {};
    for (int k0 = 0; k0 < Nv; k0 += 64) {
        __syncthreads();
        for (int i = tid; i < 4096; i += 256) {
            int m = i >> 6, k = i & 63;
            sA[m*65 + k] = g_Ahat[(m0 + m)*Nv + k0 + k];
        }
        for (int i = tid; i < 4096; i += 256) {
            int k = i >> 6, d = i & 63;
            sB[i] = in[(bt*Nv + k0 + k)*64 + d];
        }
        __syncthreads();
        #pragma unroll 16
        for (int k = 0; k < 64; k++) {
            float4 b4 = *(const float4*)&sB[k*64 + c0];
            #pragma unroll
            for (int q = 0; q < 4; q++) {
                float a = sA[(r0+q)*65 + k];
                acc[q][0] = fmaf(a, b4.x, acc[q][0]);
                acc[q][1] = fmaf(a, b4.y, acc[q][1]);
                acc[q][2] = fmaf(a, b4.z, acc[q][2]);
                acc[q][3] = fmaf(a, b4.w, acc[q][3]);
            }
        }
    }
    #pragma unroll
    for (int q = 0; q < 4; q++) {
        float4 o;
        o.x = acc[q][0]; o.y = acc[q][1]; o.z = acc[q][2]; o.w = acc[q][3];
        *(float4*)&out[(bt*Nv + m0 + r0 + q)*64 + c0] = o;
    }
}

// ---------------- graph mixing: h@W0 + p1@W1 + p2@W2 + bias, residual, LN ----------------
__global__ __launch_bounds__(256) void k_gc(const float* __restrict__ gcW,
    const float* __restrict__ gcb,
    const float* __restrict__ gg, const float* __restrict__ bg) {
    __shared__ float sA[64*65];
    __shared__ float sB[64*64];
    int tid = threadIdx.x;
    int r0g = blockIdx.x * 64;
    int tr = tid >> 4, tc = tid & 15;
    int r0 = tr * 4, c0 = tc * 4;
    float acc[4][4] = {};
    const float* ins[3] = {g_h, g_p1, g_p2};
    #pragma unroll
    for (int mm = 0; mm < 3; mm++) {
        __syncthreads();
        for (int i = tid; i < 4096; i += 256) {
            int m = i >> 6, k = i & 63;
            sA[m*65 + k] = ins[mm][(r0g + m)*64 + k];
        }
        for (int i = tid; i < 4096; i += 256) sB[i] = gcW[mm*4096 + i];
        __syncthreads();
        #pragma unroll 16
        for (int k = 0; k < 64; k++) {
            float4 b4 = *(const float4*)&sB[k*64 + c0];
            #pragma unroll
            for (int q = 0; q < 4; q++) {
                float a = sA[(r0+q)*65 + k];
                acc[q][0] = fmaf(a, b4.x, acc[q][0]);
                acc[q][1] = fmaf(a, b4.y, acc[q][1]);
                acc[q][2] = fmaf(a, b4.z, acc[q][2]);
                acc[q][3] = fmaf(a, b4.w, acc[q][3]);
            }
        }
    }
    __syncthreads();
    float4 bs;
    bs.x = gcb[c0+0] + gcb[64+c0+0] + gcb[128+c0+0];
    bs.y = gcb[c0+1] + gcb[64+c0+1] + gcb[128+c0+1];
    bs.z = gcb[c0+2] + gcb[64+c0+2] + gcb[128+c0+2];
    bs.w = gcb[c0+3] + gcb[64+c0+3] + gcb[128+c0+3];
    #pragma unroll
    for (int q = 0; q < 4; q++) {
        float4 hv = *(const float4*)&g_h[(r0g + r0 + q)*64 + c0];
        float4 o;
        o.x = acc[q][0] + bs.x + hv.x; o.y = acc[q][1] + bs.y + hv.y;
        o.z = acc[q][2] + bs.z + hv.z; o.w = acc[q][3] + bs.w + hv.w;
        *(float4*)&sB[(r0+q)*64 + c0] = o;
    }
    __syncthreads();
    ln_store(sB, r0g, gg, bg, g_h2);
}

// ---------------- FFN layer 1: gelu(h2 @ W1 + b1) -> g_u ----------------
__global__ __launch_bounds__(256) void k_ffn1(const float* __restrict__ W1,
                                              const float* __restrict__ b1) {
    __shared__ float sA[64*65];
    __shared__ float sB[64*64];
    int tid = threadIdx.x;
    int r0g = blockIdx.x * 64;
    int c0g = blockIdx.y * 64;
    for (int i = tid; i < 4096; i += 256) {
        int m = i >> 6, k = i & 63;
        sA[m*65 + k] = g_h2[(r0g + m)*64 + k];
    }
    for (int i = tid; i < 4096; i += 256) {
        int k = i >> 6, c = i & 63;
        sB[i] = W1[k*Fv + c0g + c];
    }
    __syncthreads();
    int tr = tid >> 4, tc = tid & 15;
    int r0 = tr * 4, c0 = tc * 4;
    float acc[4][4] = {};
    #pragma unroll 16
    for (int k = 0; k < 64; k++) {
        float4 b4 = *(const float4*)&sB[k*64 + c0];
        #pragma unroll
        for (int q = 0; q < 4; q++) {
            float a = sA[(r0+q)*65 + k];
            acc[q][0] = fmaf(a, b4.x, acc[q][0]);
            acc[q][1] = fmaf(a, b4.y, acc[q][1]);
            acc[q][2] = fmaf(a, b4.z, acc[q][2]);
            acc[q][3] = fmaf(a, b4.w, acc[q][3]);
        }
    }
    float4 bi = *(const float4*)&b1[c0g + c0];
    #pragma unroll
    for (int q = 0; q < 4; q++) {
        float v[4] = {acc[q][0]+bi.x, acc[q][1]+bi.y, acc[q][2]+bi.z, acc[q][3]+bi.w};
        float4 o;
        float* op = (float*)&o;
        #pragma unroll
        for (int j = 0; j < 4; j++)
            op[j] = 0.5f * v[j] * (1.0f + erff(v[j] * 0.70710678118654752f));
        *(float4*)&g_u[(r0g + r0 + q)*Fv + c0g + c0] = o;
    }
}

// ---------------- FFN layer 2 + residual + LN -> output ----------------
__global__ __launch_bounds__(256) void k_ffn2(const float* __restrict__ W2,
    const float* __restrict__ b2,
    const float* __restrict__ gf, const float* __restrict__ bf,
    float* __restrict__ out) {
    __shared__ float sA[64*65];
    __shared__ float sB[64*64];
    int tid = threadIdx.x;
    int r0g = blockIdx.x * 64;
    int tr = tid >> 4, tc = tid & 15;
    int r0 = tr * 4, c0 = tc * 4;
    float acc[4][4] = {};
    for (int k0 = 0; k0 < Fv; k0 += 64) {
        __syncthreads();
        for (int i = tid; i < 4096; i += 256) {
            int m = i >> 6, k = i & 63;
            sA[m*65 + k] = g_u[(r0g + m)*Fv + k0 + k];
        }
        for (int i = tid; i < 4096; i += 256) {
            int k = i >> 6, c = i & 63;
            sB[i] = W2[(k0 + k)*64 + c];
        }
        __syncthreads();
        #pragma unroll 16
        for (int k = 0; k < 64; k++) {
            float4 b4 = *(const float4*)&sB[k*64 + c0];
            #pragma unroll
            for (int q = 0; q < 4; q++) {
                float a = sA[(r0+q)*65 + k];
                acc[q][0] = fmaf(a, b4.x, acc[q][0]);
                acc[q][1] = fmaf(a, b4.y, acc[q][1]);
                acc[q][2] = fmaf(a, b4.z, acc[q][2]);
                acc[q][3] = fmaf(a, b4.w, acc[q][3]);
            }
        }
    }
    __syncthreads();
    float4 bi = *(const float4*)&b2[c0];
    #pragma unroll
    for (int q = 0; q < 4; q++) {
        float4 hv = *(const float4*)&g_h2[(r0g + r0 + q)*64 + c0];
        float4 o;
        o.x = acc[q][0] + bi.x + hv.x; o.y = acc[q][1] + bi.y + hv.y;
        o.z = acc[q][2] + bi.z + hv.z; o.w = acc[q][3] + bi.w + hv.w;
        *(float4*)&sB[(r0+q)*64 + c0] = o;
    }
    __syncthreads();
    ln_store(sB, r0g, gf, bf, out);
}

// ---------------- launch ----------------
extern "C" void kernel_launch(void* const* d_in, const int* in_sizes, int n_in,
                              void* d_out, int out_size) {
    const float* x   = (const float*)d_in[0];
    const float* adj = (const float*)d_in[1];
    const float* Wq  = (const float*)d_in[2];
    const float* bq  = (const float*)d_in[3];
    const float* Wk  = (const float*)d_in[4];
    const float* bk  = (const float*)d_in[5];
    const float* Wv  = (const float*)d_in[6];
    const float* bv  = (const float*)d_in[7];
    const float* Wo  = (const float*)d_in[8];
    const float* bo  = (const float*)d_in[9];
    const float* gcW = (const float*)d_in[10];
    const float* gcb = (const float*)d_in[11];
    const float* W1  = (const float*)d_in[12];
    const float* b1  = (const float*)d_in[13];
    const float* W2  = (const float*)d_in[14];
    const float* b2  = (const float*)d_in[15];
    const float* g_t = (const float*)d_in[16];
    const float* b_t = (const float*)d_in[17];
    const float* g_g = (const float*)d_in[18];
    const float* b_g = (const float*)d_in[19];
    const float* g_f = (const float*)d_in[20];
    const float* b_f = (const float*)d_in[21];
    float* out = (float*)d_out;

    k_deg <<<Nv, 128>>>(adj);
    k_ahat<<<(Nv*Nv)/512, 512>>>(adj);
    k_qkv <<<RTILES, 256>>>(x, Wq, bq, Wk, bk, Wv, bv);
    k_attn<<<dim3(Nv, Bv), 256>>>();
    k_attnout<<<RTILES, 256>>>(x, Wo, bo, g_t, b_t);
    k_prop<<<dim3(Nv/64, BTv), 256>>>(0);
    k_prop<<<dim3(Nv/64, BTv), 256>>>(1);
    k_gc  <<<RTILES, 256>>>(gcW, gcb, g_g, b_g);
    k_ffn1<<<dim3(RTILES, Fv/64), 256>>>(W1, b1);
    k_ffn2<<<RTILES, 256>>>(W2, b2, g_f, b_f, out);
}

// round 4
// speedup vs baseline: 1.1699x; 1.1699x over previous
#include <cuda_runtime.h>
#include <math.h>

#define Bv   16
#define Tv   24
#define Nv   512
#define Dv   64
#define Hv   4
#define HDv  16
#define Fv   256
#define BTv  (Bv*Tv)           // 384
#define BTNv (BTv*Nv)          // 196608
#define RTILES (BTNv/64)       // 3072

// ---------------- scratch (static device globals; no allocation) ----------------
__device__ float g_dinv[Nv];
__device__ float g_Ahat[Nv*Nv];
__device__ float g_q  [BTNv*Dv];
__device__ float g_k  [BTNv*Dv];
__device__ float g_v  [BTNv*Dv];
__device__ float g_att[BTNv*Dv];
__device__ float g_h  [BTNv*Dv];
__device__ float g_p1 [BTNv*Dv];
__device__ float g_p2 [BTNv*Dv];
__device__ float g_h2 [BTNv*Dv];
__device__ float g_u  [BTNv*Fv];

// ---------------- packed f32x2 microkernel over a 64x64 k-tile ----------------
// sA: [64][65] row-major (A[m][k]), sB: [64][64] (B[k][n]).
// Each thread owns rows r0..r0+3, cols c0..c0+3 as 4x2 f32x2 accumulators.
__device__ __forceinline__ void mm64(const float* __restrict__ sA,
                                     const float* __restrict__ sB,
                                     int r0, int c0,
                                     unsigned long long acc[4][2]) {
    #pragma unroll 16
    for (int k = 0; k < 64; k++) {
        double2 bq = *(const double2*)&sB[k*64 + c0];
        unsigned long long b01 = __double_as_longlong(bq.x);
        unsigned long long b23 = __double_as_longlong(bq.y);
        #pragma unroll
        for (int q = 0; q < 4; q++) {
            float a = sA[(r0+q)*65 + k];
            unsigned long long ap;
            asm("mov.b64 %0, {%1, %1};" : "=l"(ap) : "f"(a));
            asm("fma.rn.f32x2 %0, %1, %2, %0;" : "+l"(acc[q][0]) : "l"(ap), "l"(b01));
            asm("fma.rn.f32x2 %0, %1, %2, %0;" : "+l"(acc[q][1]) : "l"(ap), "l"(b23));
        }
    }
}

__device__ __forceinline__ float4 acc_row(const unsigned long long acc[2]) {
    float2 p0 = *(const float2*)&acc[0];
    float2 p1 = *(const float2*)&acc[1];
    float4 o; o.x = p0.x; o.y = p0.y; o.z = p1.x; o.w = p1.y;
    return o;
}

// ---------------- LayerNorm epilogue over a 64x64 smem tile ----------------
__device__ __forceinline__ void ln_store(const float* sO, int r0g,
                                         const float* __restrict__ g,
                                         const float* __restrict__ b,
                                         float* __restrict__ out) {
    int warp = threadIdx.x >> 5, lane = threadIdx.x & 31;
    float gg0 = g[lane], gg1 = g[lane + 32];
    float bb0 = b[lane], bb1 = b[lane + 32];
    for (int r = warp; r < 64; r += 8) {
        float v0 = sO[r*64 + lane];
        float v1 = sO[r*64 + lane + 32];
        float s = v0 + v1;
        #pragma unroll
        for (int o = 16; o; o >>= 1) s += __shfl_xor_sync(0xffffffffu, s, o);
        float m = s * (1.0f/64.0f);
        float d0 = v0 - m, d1 = v1 - m;
        float vs = d0*d0 + d1*d1;
        #pragma unroll
        for (int o = 16; o; o >>= 1) vs += __shfl_xor_sync(0xffffffffu, vs, o);
        float rs = rsqrtf(vs * (1.0f/64.0f) + 1e-5f);
        out[(r0g + r)*64 + lane]      = d0*rs*gg0 + bb0;
        out[(r0g + r)*64 + lane + 32] = d1*rs*gg1 + bb1;
    }
}

// ---------------- graph normalization ----------------
__global__ __launch_bounds__(128) void k_deg(const float* __restrict__ adj) {
    __shared__ float red[128];
    int m = blockIdx.x;
    float s = 0.f;
    for (int j = threadIdx.x; j < Nv; j += 128) s += adj[m*Nv + j];
    red[threadIdx.x] = s; __syncthreads();
    for (int o = 64; o; o >>= 1) {
        if (threadIdx.x < o) red[threadIdx.x] += red[threadIdx.x + o];
        __syncthreads();
    }
    if (threadIdx.x == 0) {
        float deg = red[0] + 1.0f;                 // A = adj + I
        g_dinv[m] = rsqrtf(fmaxf(deg, 1e-12f));
    }
}

__global__ __launch_bounds__(512) void k_ahat(const float* __restrict__ adj) {
    int i = blockIdx.x * 512 + threadIdx.x;
    int m = i >> 9, n = i & 511;
    float a = adj[i] + (m == n ? 1.0f : 0.0f);
    g_Ahat[i] = g_dinv[m] * a * g_dinv[n];
}

// ---------------- QKV projections (one x-tile, three weight sets) ----------------
__global__ __launch_bounds__(256) void k_qkv(const float* __restrict__ x,
    const float* __restrict__ Wq, const float* __restrict__ bq,
    const float* __restrict__ Wk, const float* __restrict__ bk,
    const float* __restrict__ Wv, const float* __restrict__ bv) {
    __shared__ float sA[64*65];
    __shared__ float sB[64*64];
    int tid = threadIdx.x;
    int r0g = blockIdx.x * 64;
    for (int i = tid; i < 4096; i += 256) {
        int m = i >> 6, k = i & 63;
        sA[m*65 + k] = x[(r0g + m)*64 + k];
    }
    int tr = tid >> 4, tc = tid & 15;
    int r0 = tr * 4, c0 = tc * 4;
    const float* W[3]  = {Wq, Wk, Wv};
    const float* bb[3] = {bq, bk, bv};
    float* outp[3]     = {g_q, g_k, g_v};
    #pragma unroll
    for (int mm = 0; mm < 3; mm++) {
        __syncthreads();
        for (int i = tid; i < 4096; i += 256) sB[i] = W[mm][i];
        __syncthreads();
        unsigned long long acc[4][2] = {};
        mm64(sA, sB, r0, c0, acc);
        float4 bi = *(const float4*)&bb[mm][c0];
        #pragma unroll
        for (int q = 0; q < 4; q++) {
            float4 o = acc_row(acc[q]);
            o.x += bi.x; o.y += bi.y; o.z += bi.z; o.w += bi.w;
            *(float4*)&outp[mm][(r0g + r0 + q)*64 + c0] = o;
        }
    }
}

// ---------------- temporal attention core (per b,n; all heads) ----------------
// q,k stored transposed [d][t] (pitch 25, coprime with 32 banks) -> conflict-free
__global__ __launch_bounds__(256) void k_attn() {
    __shared__ float sqT[64*25];            // [d][t]
    __shared__ float skT[64*25];            // [d][t]
    __shared__ float sv[Tv*64];             // [t][d]
    __shared__ float so[Tv*64];
    __shared__ float ss[Hv*Tv*25];          // [h][tq][tk] pitch 25
    int tid = threadIdx.x;
    int n = blockIdx.x, b = blockIdx.y;
    for (int i = tid; i < Tv*64; i += 256) {
        int t = i >> 6, d = i & 63;
        int gidx = ((b*Tv + t)*Nv + n)*64 + d;
        sqT[d*25 + t] = g_q[gidx];
        skT[d*25 + t] = g_k[gidx];
        sv[i]         = g_v[gidx];
    }
    __syncthreads();
    // scores: ss[h][tq][tk]; lanes walk tk -> consecutive addresses
    for (int i = tid; i < Hv*Tv*Tv; i += 256) {
        int h = i / (Tv*Tv);
        int rem = i - h*Tv*Tv;
        int tq = rem / Tv, tk = rem - tq*Tv;
        const float* qb = &sqT[h*HDv*25];
        const float* kb = &skT[h*HDv*25];
        float s = 0.f;
        #pragma unroll
        for (int e = 0; e < HDv; e++)
            s = fmaf(qb[e*25 + tq], kb[e*25 + tk], s);
        ss[(h*Tv + tq)*25 + tk] = s * 0.25f;   // scale = hd^-0.5
    }
    __syncthreads();
    // softmax over tk, one (h,tq) row per thread
    if (tid < Hv*Tv) {
        float* row = &ss[tid*25];
        float mx = -1e30f;
        #pragma unroll
        for (int tk = 0; tk < Tv; tk++) mx = fmaxf(mx, row[tk]);
        float sum = 0.f;
        #pragma unroll
        for (int tk = 0; tk < Tv; tk++) { float e = expf(row[tk]-mx); row[tk] = e; sum += e; }
        float inv = 1.0f / sum;
        #pragma unroll
        for (int tk = 0; tk < Tv; tk++) row[tk] *= inv;
    }
    __syncthreads();
    // att = probs @ v  (lanes walk e -> consecutive addresses in sv)
    for (int i = tid; i < Hv*Tv*HDv; i += 256) {
        int h = i / (Tv*HDv);
        int rem = i - h*Tv*HDv;
        int tq = rem / HDv, e = rem - tq*HDv;
        float a = 0.f;
        #pragma unroll
        for (int tk = 0; tk < Tv; tk++)
            a = fmaf(ss[(h*Tv + tq)*25 + tk], sv[tk*64 + h*HDv + e], a);
        so[tq*64 + h*HDv + e] = a;
    }
    __syncthreads();
    for (int i = tid; i < Tv*64; i += 256) {
        int t = i >> 6, d = i & 63;
        g_att[((b*Tv + t)*Nv + n)*64 + d] = so[i];
    }
}

// ---------------- attention output proj + residual + LN -> g_h ----------------
__global__ __launch_bounds__(256) void k_attnout(const float* __restrict__ x,
    const float* __restrict__ Wo, const float* __restrict__ bo,
    const float* __restrict__ gt, const float* __restrict__ bt) {
    __shared__ float sA[64*65];
    __shared__ float sB[64*64];
    int tid = threadIdx.x;
    int r0g = blockIdx.x * 64;
    for (int i = tid; i < 4096; i += 256) {
        int m = i >> 6, k = i & 63;
        sA[m*65 + k] = g_att[(r0g + m)*64 + k];
    }
    for (int i = tid; i < 4096; i += 256) sB[i] = Wo[i];
    __syncthreads();
    int tr = tid >> 4, tc = tid & 15;
    int r0 = tr * 4, c0 = tc * 4;
    unsigned long long acc[4][2] = {};
    mm64(sA, sB, r0, c0, acc);
    __syncthreads();            // done reading sB; reuse as output tile
    float4 bi = *(const float4*)&bo[c0];
    #pragma unroll
    for (int q = 0; q < 4; q++) {
        float4 xv = *(const float4*)&x[(r0g + r0 + q)*64 + c0];
        float4 o = acc_row(acc[q]);
        o.x += bi.x + xv.x; o.y += bi.y + xv.y;
        o.z += bi.z + xv.z; o.w += bi.w + xv.w;
        *(float4*)&sB[(r0+q)*64 + c0] = o;
    }
    __syncthreads();
    ln_store(sB, r0g, gt, bt, g_h);
}

// ---------------- batched Ahat @ prop (the big GEMM) ----------------
__global__ __launch_bounds__(256) void k_prop(int pass) {
    const float* __restrict__ in = pass ? g_p1 : g_h;
    float* __restrict__ out      = pass ? g_p2 : g_p1;
    __shared__ float sA[64*65];   // Ahat tile [m][k]
    __shared__ float sB[64*64];   // in tile   [k][d]
    int tid = threadIdx.x;
    int m0 = blockIdx.x * 64;
    int bt = blockIdx.y;
    int tr = tid >> 4, tc = tid & 15;
    int r0 = tr * 4, c0 = tc * 4;
    unsigned long long acc[4][2] = {};
    for (int k0 = 0; k0 < Nv; k0 += 64) {
        __syncthreads();
        for (int i = tid; i < 4096; i += 256) {
            int m = i >> 6, k = i & 63;
            sA[m*65 + k] = g_Ahat[(m0 + m)*Nv + k0 + k];
        }
        for (int i = tid; i < 4096; i += 256) {
            int k = i >> 6, d = i & 63;
            sB[i] = in[(bt*Nv + k0 + k)*64 + d];
        }
        __syncthreads();
        mm64(sA, sB, r0, c0, acc);
    }
    #pragma unroll
    for (int q = 0; q < 4; q++) {
        float4 o = acc_row(acc[q]);
        *(float4*)&out[(bt*Nv + m0 + r0 + q)*64 + c0] = o;
    }
}

// ---------------- graph mixing: h@W0 + p1@W1 + p2@W2 + bias, residual, LN ----------------
__global__ __launch_bounds__(256) void k_gc(const float* __restrict__ gcW,
    const float* __restrict__ gcb,
    const float* __restrict__ gg, const float* __restrict__ bg) {
    __shared__ float sA[64*65];
    __shared__ float sB[64*64];
    int tid = threadIdx.x;
    int r0g = blockIdx.x * 64;
    int tr = tid >> 4, tc = tid & 15;
    int r0 = tr * 4, c0 = tc * 4;
    unsigned long long acc[4][2] = {};
    const float* ins[3] = {g_h, g_p1, g_p2};
    #pragma unroll
    for (int mm = 0; mm < 3; mm++) {
        __syncthreads();
        for (int i = tid; i < 4096; i += 256) {
            int m = i >> 6, k = i & 63;
            sA[m*65 + k] = ins[mm][(r0g + m)*64 + k];
        }
        for (int i = tid; i < 4096; i += 256) sB[i] = gcW[mm*4096 + i];
        __syncthreads();
        mm64(sA, sB, r0, c0, acc);
    }
    __syncthreads();
    float4 bs;
    bs.x = gcb[c0+0] + gcb[64+c0+0] + gcb[128+c0+0];
    bs.y = gcb[c0+1] + gcb[64+c0+1] + gcb[128+c0+1];
    bs.z = gcb[c0+2] + gcb[64+c0+2] + gcb[128+c0+2];
    bs.w = gcb[c0+3] + gcb[64+c0+3] + gcb[128+c0+3];
    #pragma unroll
    for (int q = 0; q < 4; q++) {
        float4 hv = *(const float4*)&g_h[(r0g + r0 + q)*64 + c0];
        float4 o = acc_row(acc[q]);
        o.x += bs.x + hv.x; o.y += bs.y + hv.y;
        o.z += bs.z + hv.z; o.w += bs.w + hv.w;
        *(float4*)&sB[(r0+q)*64 + c0] = o;
    }
    __syncthreads();
    ln_store(sB, r0g, gg, bg, g_h2);
}

// ---------------- FFN layer 1: gelu(h2 @ W1 + b1) -> g_u ----------------
__global__ __launch_bounds__(256) void k_ffn1(const float* __restrict__ W1,
                                              const float* __restrict__ b1) {
    __shared__ float sA[64*65];
    __shared__ float sB[64*64];
    int tid = threadIdx.x;
    int r0g = blockIdx.x * 64;
    int c0g = blockIdx.y * 64;
    for (int i = tid; i < 4096; i += 256) {
        int m = i >> 6, k = i & 63;
        sA[m*65 + k] = g_h2[(r0g + m)*64 + k];
    }
    for (int i = tid; i < 4096; i += 256) {
        int k = i >> 6, c = i & 63;
        sB[i] = W1[k*Fv + c0g + c];
    }
    __syncthreads();
    int tr = tid >> 4, tc = tid & 15;
    int r0 = tr * 4, c0 = tc * 4;
    unsigned long long acc[4][2] = {};
    mm64(sA, sB, r0, c0, acc);
    float4 bi = *(const float4*)&b1[c0g + c0];
    #pragma unroll
    for (int q = 0; q < 4; q++) {
        float4 a4 = acc_row(acc[q]);
        float v[4] = {a4.x+bi.x, a4.y+bi.y, a4.z+bi.z, a4.w+bi.w};
        float4 o;
        float* op = (float*)&o;
        #pragma unroll
        for (int j = 0; j < 4; j++)
            op[j] = 0.5f * v[j] * (1.0f + erff(v[j] * 0.70710678118654752f));
        *(float4*)&g_u[(r0g + r0 + q)*Fv + c0g + c0] = o;
    }
}

// ---------------- FFN layer 2 + residual + LN -> output ----------------
__global__ __launch_bounds__(256) void k_ffn2(const float* __restrict__ W2,
    const float* __restrict__ b2,
    const float* __restrict__ gf, const float* __restrict__ bf,
    float* __restrict__ out) {
    __shared__ float sA[64*65];
    __shared__ float sB[64*64];
    int tid = threadIdx.x;
    int r0g = blockIdx.x * 64;
    int tr = tid >> 4, tc = tid & 15;
    int r0 = tr * 4, c0 = tc * 4;
    unsigned long long acc[4][2] = {};
    for (int k0 = 0; k0 < Fv; k0 += 64) {
        __syncthreads();
        for (int i = tid; i < 4096; i += 256) {
            int m = i >> 6, k = i & 63;
            sA[m*65 + k] = g_u[(r0g + m)*Fv + k0 + k];
        }
        for (int i = tid; i < 4096; i += 256) {
            int k = i >> 6, c = i & 63;
            sB[i] = W2[(k0 + k)*64 + c];
        }
        __syncthreads();
        mm64(sA, sB, r0, c0, acc);
    }
    __syncthreads();
    float4 bi = *(const float4*)&b2[c0];
    #pragma unroll
    for (int q = 0; q < 4; q++) {
        float4 hv = *(const float4*)&g_h2[(r0g + r0 + q)*64 + c0];
        float4 o = acc_row(acc[q]);
        o.x += bi.x + hv.x; o.y += bi.y + hv.y;
        o.z += bi.z + hv.z; o.w += bi.w + hv.w;
        *(float4*)&sB[(r0+q)*64 + c0] = o;
    }
    __syncthreads();
    ln_store(sB, r0g, gf, bf, out);
}

// ---------------- launch ----------------
extern "C" void kernel_launch(void* const* d_in, const int* in_sizes, int n_in,
                              void* d_out, int out_size) {
    const float* x   = (const float*)d_in[0];
    const float* adj = (const float*)d_in[1];
    const float* Wq  = (const float*)d_in[2];
    const float* bq  = (const float*)d_in[3];
    const float* Wk  = (const float*)d_in[4];
    const float* bk  = (const float*)d_in[5];
    const float* Wv  = (const float*)d_in[6];
    const float* bv  = (const float*)d_in[7];
    const float* Wo  = (const float*)d_in[8];
    const float* bo  = (const float*)d_in[9];
    const float* gcW = (const float*)d_in[10];
    const float* gcb = (const float*)d_in[11];
    const float* W1  = (const float*)d_in[12];
    const float* b1  = (const float*)d_in[13];
    const float* W2  = (const float*)d_in[14];
    const float* b2  = (const float*)d_in[15];
    const float* g_t = (const float*)d_in[16];
    const float* b_t = (const float*)d_in[17];
    const float* g_g = (const float*)d_in[18];
    const float* b_g = (const float*)d_in[19];
    const float* g_f = (const float*)d_in[20];
    const float* b_f = (const float*)d_in[21];
    float* out = (float*)d_out;

    k_deg <<<Nv, 128>>>(adj);
    k_ahat<<<(Nv*Nv)/512, 512>>>(adj);
    k_qkv <<<RTILES, 256>>>(x, Wq, bq, Wk, bk, Wv, bv);
    k_attn<<<dim3(Nv, Bv), 256>>>();
    k_attnout<<<RTILES, 256>>>(x, Wo, bo, g_t, b_t);
    k_prop<<<dim3(Nv/64, BTv), 256>>>(0);
    k_prop<<<dim3(Nv/64, BTv), 256>>>(1);
    k_gc  <<<RTILES, 256>>>(gcW, gcb, g_g, b_g);
    k_ffn1<<<dim3(RTILES, Fv/64), 256>>>(W1, b1);
    k_ffn2<<<RTILES, 256>>>(W2, b2, g_f, b_f, out);
}

// round 6
// speedup vs baseline: 1.2489x; 1.0675x over previous
#include <cuda_runtime.h>
#include <math.h>

#define Bv   16
#define Tv   24
#define Nv   512
#define Dv   64
#define Hv   4
#define HDv  16
#define Fv   256
#define BTv  (Bv*Tv)           // 384
#define BTNv (BTv*Nv)          // 196608
#define RT128 (BTNv/128)       // 1536

typedef unsigned long long ull;

// ---------------- scratch (static device globals; no allocation) ----------------
__device__ float g_dinv[Nv];
__device__ float g_Ahat[Nv*Nv];
__device__ float g_q  [BTNv*Dv];
__device__ float g_k  [BTNv*Dv];
__device__ float g_v  [BTNv*Dv];
__device__ float g_att[BTNv*Dv];
__device__ float g_h  [BTNv*Dv];
__device__ float g_p1 [BTNv*Dv];
__device__ float g_p2 [BTNv*Dv];
__device__ float g_h2 [BTNv*Dv];
__device__ float g_u  [BTNv*Fv];

// ================= 128x64-tile GEMM microkernel, 128 threads =================
// sAT: [64][128]  A transposed (k-major). sB: [64][64] (k-major rows of 64 cols).
// thread (tr = tid>>3, tc = tid&7) owns rows r0=tr*8..+7, cols c0=tc*8..+7.
// Accumulators: acc[i][j] = packed f32x2 covering cols (c0+2j, c0+2j+1).
__device__ __forceinline__ void mm128(const float* __restrict__ sAT,
                                      const float* __restrict__ sB,
                                      int r0, int c0, ull acc[8][4]) {
    #pragma unroll 8
    for (int k = 0; k < 64; k++) {
        const float* pB = &sB[k*64 + c0];
        double2 tb0 = *(const double2*)pB;
        double2 tb1 = *(const double2*)(pB + 4);
        ull b0 = __double_as_longlong(tb0.x);
        ull b1 = __double_as_longlong(tb0.y);
        ull b2 = __double_as_longlong(tb1.x);
        ull b3 = __double_as_longlong(tb1.y);
        const float* pA = &sAT[k*128 + r0];
        float4 ta0 = *(const float4*)pA;
        float4 ta1 = *(const float4*)(pA + 4);
        float a[8] = {ta0.x, ta0.y, ta0.z, ta0.w, ta1.x, ta1.y, ta1.z, ta1.w};
        #pragma unroll
        for (int i = 0; i < 8; i++) {
            ull ap;
            asm("mov.b64 %0, {%1, %1};" : "=l"(ap) : "f"(a[i]));
            asm("fma.rn.f32x2 %0, %1, %2, %0;" : "+l"(acc[i][0]) : "l"(ap), "l"(b0));
            asm("fma.rn.f32x2 %0, %1, %2, %0;" : "+l"(acc[i][1]) : "l"(ap), "l"(b1));
            asm("fma.rn.f32x2 %0, %1, %2, %0;" : "+l"(acc[i][2]) : "l"(ap), "l"(b2));
            asm("fma.rn.f32x2 %0, %1, %2, %0;" : "+l"(acc[i][3]) : "l"(ap), "l"(b3));
        }
    }
}

__device__ __forceinline__ void unpack_row(const ull a[4], float4& o0, float4& o1) {
    float2 p0 = *(const float2*)&a[0];
    float2 p1 = *(const float2*)&a[1];
    float2 p2 = *(const float2*)&a[2];
    float2 p3 = *(const float2*)&a[3];
    o0 = make_float4(p0.x, p0.y, p1.x, p1.y);
    o1 = make_float4(p2.x, p2.y, p3.x, p3.y);
}

// load A tile transposed: thread m=tid reads 64 floats of row m (16 float4),
// scatters into sAT[k][m]. Writes vary m across lanes -> conflict-free.
__device__ __forceinline__ void loadAT(float* sAT, const float* __restrict__ src, int ld) {
    int m = threadIdx.x;
    const float4* s4 = (const float4*)(src + m*ld);
    #pragma unroll
    for (int kk = 0; kk < 16; kk++) {
        float4 t = s4[kk];
        sAT[(4*kk+0)*128 + m] = t.x;
        sAT[(4*kk+1)*128 + m] = t.y;
        sAT[(4*kk+2)*128 + m] = t.z;
        sAT[(4*kk+3)*128 + m] = t.w;
    }
}

__device__ __forceinline__ void copyB(float* sB, const float* __restrict__ src) {
    const float4* s4 = (const float4*)src;
    float4* d4 = (float4*)sB;
    #pragma unroll
    for (int i = threadIdx.x; i < 1024; i += 128) d4[i] = s4[i];
}

// ---------------- LayerNorm over a 128x64 smem tile, 128 threads ----------------
__device__ __forceinline__ void ln_store128(const float* sO, int r0g,
                                            const float* __restrict__ g,
                                            const float* __restrict__ b,
                                            float* __restrict__ out) {
    int warp = threadIdx.x >> 5, lane = threadIdx.x & 31;
    float gg0 = g[lane], gg1 = g[lane + 32];
    float bb0 = b[lane], bb1 = b[lane + 32];
    for (int r = warp; r < 128; r += 4) {
        float v0 = sO[r*64 + lane];
        float v1 = sO[r*64 + lane + 32];
        float s = v0 + v1;
        #pragma unroll
        for (int o = 16; o; o >>= 1) s += __shfl_xor_sync(0xffffffffu, s, o);
        float m = s * (1.0f/64.0f);
        float d0 = v0 - m, d1 = v1 - m;
        float vs = d0*d0 + d1*d1;
        #pragma unroll
        for (int o = 16; o; o >>= 1) vs += __shfl_xor_sync(0xffffffffu, vs, o);
        float rs = rsqrtf(vs * (1.0f/64.0f) + 1e-5f);
        out[(r0g + r)*64 + lane]      = d0*rs*gg0 + bb0;
        out[(r0g + r)*64 + lane + 32] = d1*rs*gg1 + bb1;
    }
}

// ---------------- graph normalization ----------------
__global__ __launch_bounds__(128) void k_deg(const float* __restrict__ adj) {
    __shared__ float red[128];
    int m = blockIdx.x;
    float s = 0.f;
    for (int j = threadIdx.x; j < Nv; j += 128) s += adj[m*Nv + j];
    red[threadIdx.x] = s; __syncthreads();
    for (int o = 64; o; o >>= 1) {
        if (threadIdx.x < o) red[threadIdx.x] += red[threadIdx.x + o];
        __syncthreads();
    }
    if (threadIdx.x == 0) {
        float deg = red[0] + 1.0f;
        g_dinv[m] = rsqrtf(fmaxf(deg, 1e-12f));
    }
}

__global__ __launch_bounds__(512) void k_ahat(const float* __restrict__ adj) {
    int i = blockIdx.x * 512 + threadIdx.x;
    int m = i >> 9, n = i & 511;
    float a = adj[i] + (m == n ? 1.0f : 0.0f);
    g_Ahat[i] = g_dinv[m] * a * g_dinv[n];
}

// ---------------- QKV projections ----------------
__global__ __launch_bounds__(128, 4) void k_qkv(const float* __restrict__ x,
    const float* __restrict__ Wq, const float* __restrict__ bq,
    const float* __restrict__ Wk, const float* __restrict__ bk,
    const float* __restrict__ Wv, const float* __restrict__ bv) {
    __shared__ __align__(16) float sm[12288];
    float* sAT = sm;            // 8192
    float* sB  = sm + 8192;     // 4096
    int tid = threadIdx.x;
    int r0g = blockIdx.x * 128;
    int tr = tid >> 3, tc = tid & 7;
    int r0 = tr * 8, c0 = tc * 8;
    loadAT(sAT, x + r0g*64, 64);
    const float* W[3]  = {Wq, Wk, Wv};
    const float* bb[3] = {bq, bk, bv};
    float* outp[3]     = {g_q, g_k, g_v};
    #pragma unroll
    for (int mm = 0; mm < 3; mm++) {
        __syncthreads();
        copyB(sB, W[mm]);
        __syncthreads();
        ull acc[8][4] = {};
        mm128(sAT, sB, r0, c0, acc);
        float4 bi0 = *(const float4*)&bb[mm][c0];
        float4 bi1 = *(const float4*)&bb[mm][c0 + 4];
        #pragma unroll
        for (int i = 0; i < 8; i++) {
            float4 o0, o1; unpack_row(acc[i], o0, o1);
            o0.x += bi0.x; o0.y += bi0.y; o0.z += bi0.z; o0.w += bi0.w;
            o1.x += bi1.x; o1.y += bi1.y; o1.z += bi1.z; o1.w += bi1.w;
            float* dst = &outp[mm][(r0g + r0 + i)*64 + c0];
            *(float4*)dst = o0;
            *(float4*)(dst + 4) = o1;
        }
    }
}

// ---------------- temporal attention core (per b,n; all heads) ----------------
// q,k transposed [d][t] pitch 28 (float4-friendly); 4x4 register blocking.
__global__ __launch_bounds__(256) void k_attn() {
    __shared__ __align__(16) float sqT[64*28];
    __shared__ __align__(16) float skT[64*28];
    __shared__ __align__(16) float sv[Tv*64];
    __shared__ __align__(16) float so[Tv*64];
    __shared__ __align__(16) float ss[Hv*Tv*25];
    int tid = threadIdx.x;
    int n = blockIdx.x, b = blockIdx.y;
    for (int i = tid; i < Tv*64; i += 256) {
        int t = i >> 6, d = i & 63;
        int gidx = ((b*Tv + t)*Nv + n)*64 + d;
        sqT[d*28 + t] = g_q[gidx];
        skT[d*28 + t] = g_k[gidx];
        sv[i]         = g_v[gidx];
    }
    __syncthreads();
    // scores with 4x4 blocking: 144 threads, one (h, 4tq, 4tk) block each
    if (tid < Hv*36) {
        int h = tid / 36, blk = tid % 36;
        int tq0 = (blk / 6) * 4, tk0 = (blk % 6) * 4;
        float s[4][4] = {};
        const float* qb = &sqT[h*HDv*28];
        const float* kb = &skT[h*HDv*28];
        #pragma unroll
        for (int e = 0; e < HDv; e++) {
            float4 q4 = *(const float4*)(qb + e*28 + tq0);
            float4 k4 = *(const float4*)(kb + e*28 + tk0);
            float qa[4] = {q4.x, q4.y, q4.z, q4.w};
            float ka[4] = {k4.x, k4.y, k4.z, k4.w};
            #pragma unroll
            for (int i = 0; i < 4; i++)
                #pragma unroll
                for (int j = 0; j < 4; j++)
                    s[i][j] = fmaf(qa[i], ka[j], s[i][j]);
        }
        #pragma unroll
        for (int i = 0; i < 4; i++)
            #pragma unroll
            for (int j = 0; j < 4; j++)
                ss[(h*Tv + tq0 + i)*25 + tk0 + j] = s[i][j] * 0.25f;
    }
    __syncthreads();
    if (tid < Hv*Tv) {
        float* row = &ss[tid*25];
        float mx = -1e30f;
        #pragma unroll
        for (int tk = 0; tk < Tv; tk++) mx = fmaxf(mx, row[tk]);
        float sum = 0.f;
        #pragma unroll
        for (int tk = 0; tk < Tv; tk++) { float e = expf(row[tk]-mx); row[tk] = e; sum += e; }
        float inv = 1.0f / sum;
        #pragma unroll
        for (int tk = 0; tk < Tv; tk++) row[tk] *= inv;
    }
    __syncthreads();
    // probs @ v with 4x4 blocking: 96 threads, one (h, 4tq, 4e) block each
    if (tid < Hv*24) {
        int h = tid / 24, blk = tid % 24;
        int tq0 = (blk / 4) * 4, e0 = (blk % 4) * 4;
        float o[4][4] = {};
        #pragma unroll
        for (int tk = 0; tk < Tv; tk++) {
            float4 v4 = *(const float4*)&sv[tk*64 + h*HDv + e0];
            float va[4] = {v4.x, v4.y, v4.z, v4.w};
            float pa[4];
            #pragma unroll
            for (int i = 0; i < 4; i++) pa[i] = ss[(h*Tv + tq0 + i)*25 + tk];
            #pragma unroll
            for (int i = 0; i < 4; i++)
                #pragma unroll
                for (int j = 0; j < 4; j++)
                    o[i][j] = fmaf(pa[i], va[j], o[i][j]);
        }
        #pragma unroll
        for (int i = 0; i < 4; i++)
            *(float4*)&so[(tq0 + i)*64 + h*HDv + e0] =
                make_float4(o[i][0], o[i][1], o[i][2], o[i][3]);
    }
    __syncthreads();
    for (int i = tid; i < Tv*64; i += 256) {
        int t = i >> 6, d = i & 63;
        g_att[((b*Tv + t)*Nv + n)*64 + d] = so[i];
    }
}

// ---------------- attention output proj + residual + LN -> g_h ----------------
__global__ __launch_bounds__(128, 4) void k_attnout(const float* __restrict__ x,
    const float* __restrict__ Wo, const float* __restrict__ bo,
    const float* __restrict__ gt, const float* __restrict__ bt) {
    __shared__ __align__(16) float sm[12288];
    float* sAT = sm;
    float* sB  = sm + 8192;
    int tid = threadIdx.x;
    int r0g = blockIdx.x * 128;
    int tr = tid >> 3, tc = tid & 7;
    int r0 = tr * 8, c0 = tc * 8;
    loadAT(sAT, g_att + r0g*64, 64);
    copyB(sB, Wo);
    __syncthreads();
    ull acc[8][4] = {};
    mm128(sAT, sB, r0, c0, acc);
    __syncthreads();                 // done with sAT; reuse as output tile
    float* sO = sAT;
    float4 bi0 = *(const float4*)&bo[c0];
    float4 bi1 = *(const float4*)&bo[c0 + 4];
    #pragma unroll
    for (int i = 0; i < 8; i++) {
        const float* xr = &x[(r0g + r0 + i)*64 + c0];
        float4 x0 = *(const float4*)xr;
        float4 x1 = *(const float4*)(xr + 4);
        float4 o0, o1; unpack_row(acc[i], o0, o1);
        o0.x += bi0.x + x0.x; o0.y += bi0.y + x0.y; o0.z += bi0.z + x0.z; o0.w += bi0.w + x0.w;
        o1.x += bi1.x + x1.x; o1.y += bi1.y + x1.y; o1.z += bi1.z + x1.z; o1.w += bi1.w + x1.w;
        *(float4*)&sO[(r0 + i)*64 + c0]     = o0;
        *(float4*)&sO[(r0 + i)*64 + c0 + 4] = o1;
    }
    __syncthreads();
    ln_store128(sO, r0g, gt, bt, g_h);
}

// ---------------- batched Ahat @ prop (the big GEMM) ----------------
__global__ __launch_bounds__(128, 4) void k_prop(int pass) {
    const float* __restrict__ in = pass ? g_p1 : g_h;
    float* __restrict__ out      = pass ? g_p2 : g_p1;
    __shared__ __align__(16) float sm[12288];
    float* sAT = sm;
    float* sB  = sm + 8192;
    int tid = threadIdx.x;
    int m0 = blockIdx.x * 128;
    int bt = blockIdx.y;
    int tr = tid >> 3, tc = tid & 7;
    int r0 = tr * 8, c0 = tc * 8;
    ull acc[8][4] = {};
    for (int k0 = 0; k0 < Nv; k0 += 64) {
        __syncthreads();
        loadAT(sAT, g_Ahat + m0*Nv + k0, Nv);
        copyB(sB, in + (bt*Nv + k0)*64);
        __syncthreads();
        mm128(sAT, sB, r0, c0, acc);
    }
    #pragma unroll
    for (int i = 0; i < 8; i++) {
        float4 o0, o1; unpack_row(acc[i], o0, o1);
        float* dst = &out[(bt*Nv + m0 + r0 + i)*64 + c0];
        *(float4*)dst = o0;
        *(float4*)(dst + 4) = o1;
    }
}

// ---------------- graph mixing: h@W0 + p1@W1 + p2@W2 + bias, residual, LN ----------------
__global__ __launch_bounds__(128, 4) void k_gc(const float* __restrict__ gcW,
    const float* __restrict__ gcb,
    const float* __restrict__ gg, const float* __restrict__ bg) {
    __shared__ __align__(16) float sm[12288];
    float* sAT = sm;
    float* sB  = sm + 8192;
    int tid = threadIdx.x;
    int r0g = blockIdx.x * 128;
    int tr = tid >> 3, tc = tid & 7;
    int r0 = tr * 8, c0 = tc * 8;
    ull acc[8][4] = {};
    const float* ins[3] = {g_h, g_p1, g_p2};
    #pragma unroll
    for (int mm = 0; mm < 3; mm++) {
        __syncthreads();
        loadAT(sAT, ins[mm] + r0g*64, 64);
        copyB(sB, gcW + mm*4096);
        __syncthreads();
        mm128(sAT, sB, r0, c0, acc);
    }
    __syncthreads();
    float* sO = sAT;
    float bsum[8];
    #pragma unroll
    for (int j = 0; j < 8; j++)
        bsum[j] = gcb[c0+j] + gcb[64 + c0+j] + gcb[128 + c0+j];
    #pragma unroll
    for (int i = 0; i < 8; i++) {
        const float* hr = &g_h[(r0g + r0 + i)*64 + c0];
        float4 h0 = *(const float4*)hr;
        float4 h1 = *(const float4*)(hr + 4);
        float4 o0, o1; unpack_row(acc[i], o0, o1);
        o0.x += bsum[0] + h0.x; o0.y += bsum[1] + h0.y; o0.z += bsum[2] + h0.z; o0.w += bsum[3] + h0.w;
        o1.x += bsum[4] + h1.x; o1.y += bsum[5] + h1.y; o1.z += bsum[6] + h1.z; o1.w += bsum[7] + h1.w;
        *(float4*)&sO[(r0 + i)*64 + c0]     = o0;
        *(float4*)&sO[(r0 + i)*64 + c0 + 4] = o1;
    }
    __syncthreads();
    ln_store128(sO, r0g, gg, bg, g_h2);
}

// ---------------- FFN layer 1: gelu(h2 @ W1 + b1) -> g_u ----------------
__global__ __launch_bounds__(128, 4) void k_ffn1(const float* __restrict__ W1,
                                                 const float* __restrict__ b1) {
    __shared__ __align__(16) float sm[12288];
    float* sAT = sm;
    float* sB  = sm + 8192;
    int tid = threadIdx.x;
    int r0g = blockIdx.x * 128;
    int c0g = blockIdx.y * 64;
    int tr = tid >> 3, tc = tid & 7;
    int r0 = tr * 8, c0 = tc * 8;
    loadAT(sAT, g_h2 + r0g*64, 64);
    #pragma unroll
    for (int i = tid; i < 1024; i += 128) {
        int k = i >> 4, c4 = i & 15;
        ((float4*)sB)[i] = *(const float4*)&W1[k*Fv + c0g + c4*4];
    }
    __syncthreads();
    ull acc[8][4] = {};
    mm128(sAT, sB, r0, c0, acc);
    float4 bi0 = *(const float4*)&b1[c0g + c0];
    float4 bi1 = *(const float4*)&b1[c0g + c0 + 4];
    #pragma unroll
    for (int i = 0; i < 8; i++) {
        float4 o0, o1; unpack_row(acc[i], o0, o1);
        float v[8] = {o0.x+bi0.x, o0.y+bi0.y, o0.z+bi0.z, o0.w+bi0.w,
                      o1.x+bi1.x, o1.y+bi1.y, o1.z+bi1.z, o1.w+bi1.w};
        float r[8];
        #pragma unroll
        for (int j = 0; j < 8; j++)
            r[j] = 0.5f * v[j] * (1.0f + erff(v[j] * 0.70710678118654752f));
        float* dst = &g_u[(r0g + r0 + i)*Fv + c0g + c0];
        *(float4*)dst = make_float4(r[0], r[1], r[2], r[3]);
        *(float4*)(dst + 4) = make_float4(r[4], r[5], r[6], r[7]);
    }
}

// ---------------- FFN layer 2 + residual + LN -> output ----------------
__global__ __launch_bounds__(128, 4) void k_ffn2(const float* __restrict__ W2,
    const float* __restrict__ b2,
    const float* __restrict__ gf, const float* __restrict__ bf,
    float* __restrict__ out) {
    __shared__ __align__(16) float sm[12288];
    float* sAT = sm;
    float* sB  = sm + 8192;
    int tid = threadIdx.x;
    int r0g = blockIdx.x * 128;
    int tr = tid >> 3, tc = tid & 7;
    int r0 = tr * 8, c0 = tc * 8;
    ull acc[8][4] = {};
    for (int k0 = 0; k0 < Fv; k0 += 64) {
        __syncthreads();
        loadAT(sAT, g_u + r0g*Fv + k0, Fv);
        copyB(sB, W2 + k0*64);
        __syncthreads();
        mm128(sAT, sB, r0, c0, acc);
    }
    __syncthreads();
    float* sO = sAT;
    float4 bi0 = *(const float4*)&b2[c0];
    float4 bi1 = *(const float4*)&b2[c0 + 4];
    #pragma unroll
    for (int i = 0; i < 8; i++) {
        const float* hr = &g_h2[(r0g + r0 + i)*64 + c0];
        float4 h0 = *(const float4*)hr;
        float4 h1 = *(const float4*)(hr + 4);
        float4 o0, o1; unpack_row(acc[i], o0, o1);
        o0.x += bi0.x + h0.x; o0.y += bi0.y + h0.y; o0.z += bi0.z + h0.z; o0.w += bi0.w + h0.w;
        o1.x += bi1.x + h1.x; o1.y += bi1.y + h1.y; o1.z += bi1.z + h1.z; o1.w += bi1.w + h1.w;
        *(float4*)&sO[(r0 + i)*64 + c0]     = o0;
        *(float4*)&sO[(r0 + i)*64 + c0 + 4] = o1;
    }
    __syncthreads();
    ln_store128(sO, r0g, gf, bf, out);
}

// ---------------- launch ----------------
extern "C" void kernel_launch(void* const* d_in, const int* in_sizes, int n_in,
                              void* d_out, int out_size) {
    const float* x   = (const float*)d_in[0];
    const float* adj = (const float*)d_in[1];
    const float* Wq  = (const float*)d_in[2];
    const float* bq  = (const float*)d_in[3];
    const float* Wk  = (const float*)d_in[4];
    const float* bk  = (const float*)d_in[5];
    const float* Wv  = (const float*)d_in[6];
    const float* bv  = (const float*)d_in[7];
    const float* Wo  = (const float*)d_in[8];
    const float* bo  = (const float*)d_in[9];
    const float* gcW = (const float*)d_in[10];
    const float* gcb = (const float*)d_in[11];
    const float* W1  = (const float*)d_in[12];
    const float* b1  = (const float*)d_in[13];
    const float* W2  = (const float*)d_in[14];
    const float* b2  = (const float*)d_in[15];
    const float* g_t = (const float*)d_in[16];
    const float* b_t = (const float*)d_in[17];
    const float* g_g = (const float*)d_in[18];
    const float* b_g = (const float*)d_in[19];
    const float* g_f = (const float*)d_in[20];
    const float* b_f = (const float*)d_in[21];
    float* out = (float*)d_out;

    k_deg <<<Nv, 128>>>(adj);
    k_ahat<<<(Nv*Nv)/512, 512>>>(adj);
    k_qkv <<<RT128, 128>>>(x, Wq, bq, Wk, bk, Wv, bv);
    k_attn<<<dim3(Nv, Bv), 256>>>();
    k_attnout<<<RT128, 128>>>(x, Wo, bo, g_t, b_t);
    k_prop<<<dim3(Nv/128, BTv), 128>>>(0);
    k_prop<<<dim3(Nv/128, BTv), 128>>>(1);
    k_gc  <<<RT128, 128>>>(gcW, gcb, g_g, b_g);
    k_ffn1<<<dim3(RT128, Fv/64), 128>>>(W1, b1);
    k_ffn2<<<RT128, 128>>>(W2, b2, g_f, b_f, out);
}

// round 8
// speedup vs baseline: 1.6966x; 1.3584x over previous
#include <cuda_runtime.h>
#include <cuda_bf16.h>
#include <math.h>
#include <cstdint>

#define Bv   16
#define Tv   24
#define Nv   512
#define Dv   64
#define Hv   4
#define HDv  16
#define Fv   256
#define BTv  (Bv*Tv)           // 384
#define BTNv (BTv*Nv)          // 196608
#define RT128 (BTNv/128)       // 1536

typedef unsigned long long ull;

// ---------------- scratch (static device globals; no allocation) ----------------
__device__ float g_dinv[Nv];
__device__ float g_Ahat[Nv*Nv];
__device__ float g_q  [BTNv*Dv];
__device__ float g_k  [BTNv*Dv];
__device__ float g_v  [BTNv*Dv];
__device__ float g_att[BTNv*Dv];
__device__ float g_h  [BTNv*Dv];
__device__ float g_p1 [BTNv*Dv];
__device__ float g_p2 [BTNv*Dv];
__device__ float g_h2 [BTNv*Dv];
__device__ float g_u  [BTNv*Fv];
// bf16 split buffers for tensor-core prop
__device__ __nv_bfloat16 g_Ahi[Nv*Nv];
__device__ __nv_bfloat16 g_Alo[Nv*Nv];
__device__ __nv_bfloat16 g_Bhi[BTNv*Dv];
__device__ __nv_bfloat16 g_Blo[BTNv*Dv];

// ================= mma.sync helpers (sm_80-class; valid on plain sm_103) =====
__device__ __forceinline__ uint32_t smem_u32(const void* p) {
    uint32_t a;
    asm("{ .reg .u64 t; cvta.to.shared.u64 t, %1; cvt.u32.u64 %0, t; }" : "=r"(a) : "l"(p));
    return a;
}
#define LDMX4(r, addr) \
    asm volatile("ldmatrix.sync.aligned.m8n8.x4.shared.b16 {%0,%1,%2,%3}, [%4];" \
        : "=r"((r)[0]), "=r"((r)[1]), "=r"((r)[2]), "=r"((r)[3]) : "r"(addr))
#define LDMX2T(r, addr) \
    asm volatile("ldmatrix.sync.aligned.m8n8.x2.trans.shared.b16 {%0,%1}, [%2];" \
        : "=r"((r)[0]), "=r"((r)[1]) : "r"(addr))
#define MMA_BF16(d, a, b) \
    asm volatile("mma.sync.aligned.m16n8k16.row.col.f32.bf16.bf16.f32 " \
        "{%0,%1,%2,%3}, {%4,%5,%6,%7}, {%8,%9}, {%0,%1,%2,%3};" \
        : "+f"((d)[0]), "+f"((d)[1]), "+f"((d)[2]), "+f"((d)[3]) \
        : "r"((a)[0]), "r"((a)[1]), "r"((a)[2]), "r"((a)[3]), \
          "r"((b)[0]), "r"((b)[1]))

// ================= hi/lo bf16 split =================
__device__ __forceinline__ void sp2(float x, __nv_bfloat16& h, __nv_bfloat16& l) {
    h = __float2bfloat16(x);
    l = __float2bfloat16(x - __bfloat162float(h));
}

__global__ __launch_bounds__(256) void k_split(int mode) {
    const float* src;
    __nv_bfloat16 *hi, *lo;
    int n;
    if (mode == 0) { src = g_Ahat; hi = g_Ahi; lo = g_Alo; n = Nv*Nv; }
    else { hi = g_Bhi; lo = g_Blo; n = BTNv*Dv; src = (mode == 1) ? g_h : g_p1; }
    int i = (blockIdx.x * 256 + threadIdx.x) * 4;
    if (i < n) {
        float4 v = *(const float4*)&src[i];
        __nv_bfloat16 h0,h1,h2,h3,l0,l1,l2,l3;
        sp2(v.x,h0,l0); sp2(v.y,h1,l1); sp2(v.z,h2,l2); sp2(v.w,h3,l3);
        *(__nv_bfloat162*)&hi[i]   = __nv_bfloat162(h0,h1);
        *(__nv_bfloat162*)&hi[i+2] = __nv_bfloat162(h2,h3);
        *(__nv_bfloat162*)&lo[i]   = __nv_bfloat162(l0,l1);
        *(__nv_bfloat162*)&lo[i+2] = __nv_bfloat162(l2,l3);
    }
}

// ================= tensor-core prop via mma.sync =================
// out[bt] = Ahat @ in[bt];   grid (Nv/128, BTv), 256 threads (8 warps = 4M x 2N).
// 3-product compensated bf16: Ah*Bh + Ah*Bl + Al*Bh.
__global__ __launch_bounds__(256) void k_prop_mma(int pass) {
    float* __restrict__ out = pass ? g_p2 : g_p1;
    __shared__ __align__(16) __nv_bfloat16 sAh[128*40];   // stride 40 (pad 8)
    __shared__ __align__(16) __nv_bfloat16 sAl[128*40];
    __shared__ __align__(16) __nv_bfloat16 sBh[32*72];    // stride 72 (pad 8)
    __shared__ __align__(16) __nv_bfloat16 sBl[32*72];
    int tid = threadIdx.x, lane = tid & 31, wid = tid >> 5;
    int wm = wid & 3, wn = wid >> 2;
    int m0 = blockIdx.x * 128, bt = blockIdx.y;

    float acc[2][4][4] = {};
    uint32_t baseAh = smem_u32(sAh), baseAl = smem_u32(sAl);
    uint32_t baseBh = smem_u32(sBh), baseBl = smem_u32(sBl);

    // per-thread ldmatrix address components
    int arow = wm*32 + (lane & 15);            // + mi*16
    int acolL = (lane >> 4) * 8;               // + ks*16
    int brow = lane & 15;                      // + ks*16
    int bcol = wn*32;                          // + ni*8

    for (int kc = 0; kc < 16; kc++) {
        int k0 = kc * 32;
        // ---- stage tiles ----
        for (int i = tid; i < 512; i += 256) {          // A: 128x32, 16B chunks
            int r = i >> 2, c8 = (i & 3) * 8;
            int gi = (m0 + r)*Nv + k0 + c8;
            *(uint4*)&sAh[r*40 + c8] = *(const uint4*)&g_Ahi[gi];
            *(uint4*)&sAl[r*40 + c8] = *(const uint4*)&g_Alo[gi];
        }
        {                                                // B: 32x64, 1 chunk/thread
            int k = tid >> 3, n8 = (tid & 7) * 8;
            int gi = (bt*Nv + k0 + k)*64 + n8;
            *(uint4*)&sBh[k*72 + n8] = *(const uint4*)&g_Bhi[gi];
            *(uint4*)&sBl[k*72 + n8] = *(const uint4*)&g_Blo[gi];
        }
        __syncthreads();
        // ---- compute ----
        #pragma unroll
        for (int ks = 0; ks < 2; ks++) {
            uint32_t aH[2][4], aL[2][4], bH[4][2], bL[4][2];
            int acol = ks*16 + acolL;
            #pragma unroll
            for (int mi = 0; mi < 2; mi++) {
                uint32_t off = ((arow + mi*16)*40 + acol)*2;
                LDMX4(aH[mi], baseAh + off);
                LDMX4(aL[mi], baseAl + off);
            }
            #pragma unroll
            for (int ni = 0; ni < 4; ni++) {
                uint32_t off = ((ks*16 + brow)*72 + bcol + ni*8)*2;
                LDMX2T(bH[ni], baseBh + off);
                LDMX2T(bL[ni], baseBl + off);
            }
            #pragma unroll
            for (int mi = 0; mi < 2; mi++)
                #pragma unroll
                for (int ni = 0; ni < 4; ni++) {
                    MMA_BF16(acc[mi][ni], aH[mi], bH[ni]);
                    MMA_BF16(acc[mi][ni], aH[mi], bL[ni]);
                    MMA_BF16(acc[mi][ni], aL[mi], bH[ni]);
                }
        }
        __syncthreads();
    }
    // ---- epilogue ----
    int r = lane >> 2, cb = (lane & 3) * 2;
    #pragma unroll
    for (int mi = 0; mi < 2; mi++)
        #pragma unroll
        for (int ni = 0; ni < 4; ni++) {
            int m = m0 + wm*32 + mi*16 + r;
            int n = wn*32 + ni*8 + cb;
            float* d0 = &out[(bt*Nv + m)*64 + n];
            float* d1 = &out[(bt*Nv + m + 8)*64 + n];
            *(float2*)d0 = make_float2(acc[mi][ni][0], acc[mi][ni][1]);
            *(float2*)d1 = make_float2(acc[mi][ni][2], acc[mi][ni][3]);
        }
}

// ================= 128x64-tile SIMT GEMM microkernel =================
__device__ __forceinline__ void mm128(const float* __restrict__ sAT,
                                      const float* __restrict__ sB,
                                      int r0, int c0, ull acc[8][4]) {
    #pragma unroll 8
    for (int k = 0; k < 64; k++) {
        const float* pB = &sB[k*64 + c0];
        double2 tb0 = *(const double2*)pB;
        double2 tb1 = *(const double2*)(pB + 4);
        ull b0 = __double_as_longlong(tb0.x);
        ull b1 = __double_as_longlong(tb0.y);
        ull b2 = __double_as_longlong(tb1.x);
        ull b3 = __double_as_longlong(tb1.y);
        const float* pA = &sAT[k*128 + r0];
        float4 ta0 = *(const float4*)pA;
        float4 ta1 = *(const float4*)(pA + 4);
        float a[8] = {ta0.x, ta0.y, ta0.z, ta0.w, ta1.x, ta1.y, ta1.z, ta1.w};
        #pragma unroll
        for (int i = 0; i < 8; i++) {
            ull ap;
            asm("mov.b64 %0, {%1, %1};" : "=l"(ap) : "f"(a[i]));
            asm("fma.rn.f32x2 %0, %1, %2, %0;" : "+l"(acc[i][0]) : "l"(ap), "l"(b0));
            asm("fma.rn.f32x2 %0, %1, %2, %0;" : "+l"(acc[i][1]) : "l"(ap), "l"(b1));
            asm("fma.rn.f32x2 %0, %1, %2, %0;" : "+l"(acc[i][2]) : "l"(ap), "l"(b2));
            asm("fma.rn.f32x2 %0, %1, %2, %0;" : "+l"(acc[i][3]) : "l"(ap), "l"(b3));
        }
    }
}

__device__ __forceinline__ void unpack_row(const ull a[4], float4& o0, float4& o1) {
    float2 p0 = *(const float2*)&a[0];
    float2 p1 = *(const float2*)&a[1];
    float2 p2 = *(const float2*)&a[2];
    float2 p3 = *(const float2*)&a[3];
    o0 = make_float4(p0.x, p0.y, p1.x, p1.y);
    o1 = make_float4(p2.x, p2.y, p3.x, p3.y);
}

__device__ __forceinline__ void loadAT(float* sAT, const float* __restrict__ src, int ld) {
    int m = threadIdx.x;
    const float4* s4 = (const float4*)(src + m*ld);
    #pragma unroll
    for (int kk = 0; kk < 16; kk++) {
        float4 t = s4[kk];
        sAT[(4*kk+0)*128 + m] = t.x;
        sAT[(4*kk+1)*128 + m] = t.y;
        sAT[(4*kk+2)*128 + m] = t.z;
        sAT[(4*kk+3)*128 + m] = t.w;
    }
}

__device__ __forceinline__ void copyB(float* sB, const float* __restrict__ src) {
    const float4* s4 = (const float4*)src;
    float4* d4 = (float4*)sB;
    #pragma unroll
    for (int i = threadIdx.x; i < 1024; i += 128) d4[i] = s4[i];
}

// ---------------- LayerNorm over a 128x64 smem tile, 128 threads ----------------
__device__ __forceinline__ void ln_store128(const float* sO, int r0g,
                                            const float* __restrict__ g,
                                            const float* __restrict__ b,
                                            float* __restrict__ out) {
    int warp = threadIdx.x >> 5, lane = threadIdx.x & 31;
    float gg0 = g[lane], gg1 = g[lane + 32];
    float bb0 = b[lane], bb1 = b[lane + 32];
    for (int r = warp; r < 128; r += 4) {
        float v0 = sO[r*64 + lane];
        float v1 = sO[r*64 + lane + 32];
        float s = v0 + v1;
        #pragma unroll
        for (int o = 16; o; o >>= 1) s += __shfl_xor_sync(0xffffffffu, s, o);
        float m = s * (1.0f/64.0f);
        float d0 = v0 - m, d1 = v1 - m;
        float vs = d0*d0 + d1*d1;
        #pragma unroll
        for (int o = 16; o; o >>= 1) vs += __shfl_xor_sync(0xffffffffu, vs, o);
        float rs = rsqrtf(vs * (1.0f/64.0f) + 1e-5f);
        out[(r0g + r)*64 + lane]      = d0*rs*gg0 + bb0;
        out[(r0g + r)*64 + lane + 32] = d1*rs*gg1 + bb1;
    }
}

// ---------------- graph normalization ----------------
__global__ __launch_bounds__(128) void k_deg(const float* __restrict__ adj) {
    __shared__ float red[128];
    int m = blockIdx.x;
    float s = 0.f;
    for (int j = threadIdx.x; j < Nv; j += 128) s += adj[m*Nv + j];
    red[threadIdx.x] = s; __syncthreads();
    for (int o = 64; o; o >>= 1) {
        if (threadIdx.x < o) red[threadIdx.x] += red[threadIdx.x + o];
        __syncthreads();
    }
    if (threadIdx.x == 0) {
        float deg = red[0] + 1.0f;
        g_dinv[m] = rsqrtf(fmaxf(deg, 1e-12f));
    }
}

__global__ __launch_bounds__(512) void k_ahat(const float* __restrict__ adj) {
    int i = blockIdx.x * 512 + threadIdx.x;
    int m = i >> 9, n = i & 511;
    float a = adj[i] + (m == n ? 1.0f : 0.0f);
    g_Ahat[i] = g_dinv[m] * a * g_dinv[n];
}

// ---------------- QKV projections ----------------
__global__ __launch_bounds__(128, 4) void k_qkv(const float* __restrict__ x,
    const float* __restrict__ Wq, const float* __restrict__ bq,
    const float* __restrict__ Wk, const float* __restrict__ bk,
    const float* __restrict__ Wv, const float* __restrict__ bv) {
    __shared__ __align__(16) float sm[12288];
    float* sAT = sm;
    float* sB  = sm + 8192;
    int tid = threadIdx.x;
    int r0g = blockIdx.x * 128;
    int tr = tid >> 3, tc = tid & 7;
    int r0 = tr * 8, c0 = tc * 8;
    loadAT(sAT, x + r0g*64, 64);
    const float* W[3]  = {Wq, Wk, Wv};
    const float* bb[3] = {bq, bk, bv};
    float* outp[3]     = {g_q, g_k, g_v};
    #pragma unroll
    for (int mm = 0; mm < 3; mm++) {
        __syncthreads();
        copyB(sB, W[mm]);
        __syncthreads();
        ull acc[8][4] = {};
        mm128(sAT, sB, r0, c0, acc);
        float4 bi0 = *(const float4*)&bb[mm][c0];
        float4 bi1 = *(const float4*)&bb[mm][c0 + 4];
        #pragma unroll
        for (int i = 0; i < 8; i++) {
            float4 o0, o1; unpack_row(acc[i], o0, o1);
            o0.x += bi0.x; o0.y += bi0.y; o0.z += bi0.z; o0.w += bi0.w;
            o1.x += bi1.x; o1.y += bi1.y; o1.z += bi1.z; o1.w += bi1.w;
            float* dst = &outp[mm][(r0g + r0 + i)*64 + c0];
            *(float4*)dst = o0;
            *(float4*)(dst + 4) = o1;
        }
    }
}

// ---------------- temporal attention core ----------------
__global__ __launch_bounds__(256) void k_attn() {
    __shared__ __align__(16) float sqT[64*28];
    __shared__ __align__(16) float skT[64*28];
    __shared__ __align__(16) float sv[Tv*64];
    __shared__ __align__(16) float so[Tv*64];
    __shared__ __align__(16) float ss[Hv*Tv*25];
    int tid = threadIdx.x;
    int n = blockIdx.x, b = blockIdx.y;
    for (int i = tid; i < Tv*64; i += 256) {
        int t = i >> 6, d = i & 63;
        int gidx = ((b*Tv + t)*Nv + n)*64 + d;
        sqT[d*28 + t] = g_q[gidx];
        skT[d*28 + t] = g_k[gidx];
        sv[i]         = g_v[gidx];
    }
    __syncthreads();
    if (tid < Hv*36) {
        int h = tid / 36, blk = tid % 36;
        int tq0 = (blk / 6) * 4, tk0 = (blk % 6) * 4;
        float s[4][4] = {};
        const float* qb = &sqT[h*HDv*28];
        const float* kb = &skT[h*HDv*28];
        #pragma unroll
        for (int e = 0; e < HDv; e++) {
            float4 q4 = *(const float4*)(qb + e*28 + tq0);
            float4 k4 = *(const float4*)(kb + e*28 + tk0);
            float qa[4] = {q4.x, q4.y, q4.z, q4.w};
            float ka[4] = {k4.x, k4.y, k4.z, k4.w};
            #pragma unroll
            for (int i = 0; i < 4; i++)
                #pragma unroll
                for (int j = 0; j < 4; j++)
                    s[i][j] = fmaf(qa[i], ka[j], s[i][j]);
        }
        #pragma unroll
        for (int i = 0; i < 4; i++)
            #pragma unroll
            for (int j = 0; j < 4; j++)
                ss[(h*Tv + tq0 + i)*25 + tk0 + j] = s[i][j] * 0.25f;
    }
    __syncthreads();
    if (tid < Hv*Tv) {
        float* row = &ss[tid*25];
        float mx = -1e30f;
        #pragma unroll
        for (int tk = 0; tk < Tv; tk++) mx = fmaxf(mx, row[tk]);
        float sum = 0.f;
        #pragma unroll
        for (int tk = 0; tk < Tv; tk++) { float e = expf(row[tk]-mx); row[tk] = e; sum += e; }
        float inv = 1.0f / sum;
        #pragma unroll
        for (int tk = 0; tk < Tv; tk++) row[tk] *= inv;
    }
    __syncthreads();
    if (tid < Hv*24) {
        int h = tid / 24, blk = tid % 24;
        int tq0 = (blk / 4) * 4, e0 = (blk % 4) * 4;
        float o[4][4] = {};
        #pragma unroll
        for (int tk = 0; tk < Tv; tk++) {
            float4 v4 = *(const float4*)&sv[tk*64 + h*HDv + e0];
            float va[4] = {v4.x, v4.y, v4.z, v4.w};
            float pa[4];
            #pragma unroll
            for (int i = 0; i < 4; i++) pa[i] = ss[(h*Tv + tq0 + i)*25 + tk];
            #pragma unroll
            for (int i = 0; i < 4; i++)
                #pragma unroll
                for (int j = 0; j < 4; j++)
                    o[i][j] = fmaf(pa[i], va[j], o[i][j]);
        }
        #pragma unroll
        for (int i = 0; i < 4; i++)
            *(float4*)&so[(tq0 + i)*64 + h*HDv + e0] =
                make_float4(o[i][0], o[i][1], o[i][2], o[i][3]);
    }
    __syncthreads();
    for (int i = tid; i < Tv*64; i += 256) {
        int t = i >> 6, d = i & 63;
        g_att[((b*Tv + t)*Nv + n)*64 + d] = so[i];
    }
}

// ---------------- attention output proj + residual + LN -> g_h ----------------
__global__ __launch_bounds__(128, 4) void k_attnout(const float* __restrict__ x,
    const float* __restrict__ Wo, const float* __restrict__ bo,
    const float* __restrict__ gt, const float* __restrict__ bt) {
    __shared__ __align__(16) float sm[12288];
    float* sAT = sm;
    float* sB  = sm + 8192;
    int tid = threadIdx.x;
    int r0g = blockIdx.x * 128;
    int tr = tid >> 3, tc = tid & 7;
    int r0 = tr * 8, c0 = tc * 8;
    loadAT(sAT, g_att + r0g*64, 64);
    copyB(sB, Wo);
    __syncthreads();
    ull acc[8][4] = {};
    mm128(sAT, sB, r0, c0, acc);
    __syncthreads();
    float* sO = sAT;
    float4 bi0 = *(const float4*)&bo[c0];
    float4 bi1 = *(const float4*)&bo[c0 + 4];
    #pragma unroll
    for (int i = 0; i < 8; i++) {
        const float* xr = &x[(r0g + r0 + i)*64 + c0];
        float4 x0 = *(const float4*)xr;
        float4 x1 = *(const float4*)(xr + 4);
        float4 o0, o1; unpack_row(acc[i], o0, o1);
        o0.x += bi0.x + x0.x; o0.y += bi0.y + x0.y; o0.z += bi0.z + x0.z; o0.w += bi0.w + x0.w;
        o1.x += bi1.x + x1.x; o1.y += bi1.y + x1.y; o1.z += bi1.z + x1.z; o1.w += bi1.w + x1.w;
        *(float4*)&sO[(r0 + i)*64 + c0]     = o0;
        *(float4*)&sO[(r0 + i)*64 + c0 + 4] = o1;
    }
    __syncthreads();
    ln_store128(sO, r0g, gt, bt, g_h);
}

// ---------------- graph mixing: h@W0 + p1@W1 + p2@W2 + bias, residual, LN ----------------
__global__ __launch_bounds__(128, 4) void k_gc(const float* __restrict__ gcW,
    const float* __restrict__ gcb,
    const float* __restrict__ gg, const float* __restrict__ bg) {
    __shared__ __align__(16) float sm[12288];
    float* sAT = sm;
    float* sB  = sm + 8192;
    int tid = threadIdx.x;
    int r0g = blockIdx.x * 128;
    int tr = tid >> 3, tc = tid & 7;
    int r0 = tr * 8, c0 = tc * 8;
    ull acc[8][4] = {};
    const float* ins[3] = {g_h, g_p1, g_p2};
    #pragma unroll
    for (int mm = 0; mm < 3; mm++) {
        __syncthreads();
        loadAT(sAT, ins[mm] + r0g*64, 64);
        copyB(sB, gcW + mm*4096);
        __syncthreads();
        mm128(sAT, sB, r0, c0, acc);
    }
    __syncthreads();
    float* sO = sAT;
    float bsum[8];
    #pragma unroll
    for (int j = 0; j < 8; j++)
        bsum[j] = gcb[c0+j] + gcb[64 + c0+j] + gcb[128 + c0+j];
    #pragma unroll
    for (int i = 0; i < 8; i++) {
        const float* hr = &g_h[(r0g + r0 + i)*64 + c0];
        float4 h0 = *(const float4*)hr;
        float4 h1 = *(const float4*)(hr + 4);
        float4 o0, o1; unpack_row(acc[i], o0, o1);
        o0.x += bsum[0] + h0.x; o0.y += bsum[1] + h0.y; o0.z += bsum[2] + h0.z; o0.w += bsum[3] + h0.w;
        o1.x += bsum[4] + h1.x; o1.y += bsum[5] + h1.y; o1.z += bsum[6] + h1.z; o1.w += bsum[7] + h1.w;
        *(float4*)&sO[(r0 + i)*64 + c0]     = o0;
        *(float4*)&sO[(r0 + i)*64 + c0 + 4] = o1;
    }
    __syncthreads();
    ln_store128(sO, r0g, gg, bg, g_h2);
}

// ---------------- FFN layer 1 ----------------
__global__ __launch_bounds__(128, 4) void k_ffn1(const float* __restrict__ W1,
                                                 const float* __restrict__ b1) {
    __shared__ __align__(16) float sm[12288];
    float* sAT = sm;
    float* sB  = sm + 8192;
    int tid = threadIdx.x;
    int r0g = blockIdx.x * 128;
    int c0g = blockIdx.y * 64;
    int tr = tid >> 3, tc = tid & 7;
    int r0 = tr * 8, c0 = tc * 8;
    loadAT(sAT, g_h2 + r0g*64, 64);
    #pragma unroll
    for (int i = tid; i < 1024; i += 128) {
        int k = i >> 4, c4 = i & 15;
        ((float4*)sB)[i] = *(const float4*)&W1[k*Fv + c0g + c4*4];
    }
    __syncthreads();
    ull acc[8][4] = {};
    mm128(sAT, sB, r0, c0, acc);
    float4 bi0 = *(const float4*)&b1[c0g + c0];
    float4 bi1 = *(const float4*)&b1[c0g + c0 + 4];
    #pragma unroll
    for (int i = 0; i < 8; i++) {
        float4 o0, o1; unpack_row(acc[i], o0, o1);
        float v[8] = {o0.x+bi0.x, o0.y+bi0.y, o0.z+bi0.z, o0.w+bi0.w,
                      o1.x+bi1.x, o1.y+bi1.y, o1.z+bi1.z, o1.w+bi1.w};
        float r[8];
        #pragma unroll
        for (int j = 0; j < 8; j++)
            r[j] = 0.5f * v[j] * (1.0f + erff(v[j] * 0.70710678118654752f));
        float* dst = &g_u[(r0g + r0 + i)*Fv + c0g + c0];
        *(float4*)dst = make_float4(r[0], r[1], r[2], r[3]);
        *(float4*)(dst + 4) = make_float4(r[4], r[5], r[6], r[7]);
    }
}

// ---------------- FFN layer 2 + residual + LN -> output ----------------
__global__ __launch_bounds__(128, 4) void k_ffn2(const float* __restrict__ W2,
    const float* __restrict__ b2,
    const float* __restrict__ gf, const float* __restrict__ bf,
    float* __restrict__ out) {
    __shared__ __align__(16) float sm[12288];
    float* sAT = sm;
    float* sB  = sm + 8192;
    int tid = threadIdx.x;
    int r0g = blockIdx.x * 128;
    int tr = tid >> 3, tc = tid & 7;
    int r0 = tr * 8, c0 = tc * 8;
    ull acc[8][4] = {};
    for (int k0 = 0; k0 < Fv; k0 += 64) {
        __syncthreads();
        loadAT(sAT, g_u + r0g*Fv + k0, Fv);
        copyB(sB, W2 + k0*64);
        __syncthreads();
        mm128(sAT, sB, r0, c0, acc);
    }
    __syncthreads();
    float* sO = sAT;
    float4 bi0 = *(const float4*)&b2[c0];
    float4 bi1 = *(const float4*)&b2[c0 + 4];
    #pragma unroll
    for (int i = 0; i < 8; i++) {
        const float* hr = &g_h2[(r0g + r0 + i)*64 + c0];
        float4 h0 = *(const float4*)hr;
        float4 h1 = *(const float4*)(hr + 4);
        float4 o0, o1; unpack_row(acc[i], o0, o1);
        o0.x += bi0.x + h0.x; o0.y += bi0.y + h0.y; o0.z += bi0.z + h0.z; o0.w += bi0.w + h0.w;
        o1.x += bi1.x + h1.x; o1.y += bi1.y + h1.y; o1.z += bi1.z + h1.z; o1.w += bi1.w + h1.w;
        *(float4*)&sO[(r0 + i)*64 + c0]     = o0;
        *(float4*)&sO[(r0 + i)*64 + c0 + 4] = o1;
    }
    __syncthreads();
    ln_store128(sO, r0g, gf, bf, out);
}

// ---------------- launch ----------------
extern "C" void kernel_launch(void* const* d_in, const int* in_sizes, int n_in,
                              void* d_out, int out_size) {
    const float* x   = (const float*)d_in[0];
    const float* adj = (const float*)d_in[1];
    const float* Wq  = (const float*)d_in[2];
    const float* bq  = (const float*)d_in[3];
    const float* Wk  = (const float*)d_in[4];
    const float* bk  = (const float*)d_in[5];
    const float* Wv  = (const float*)d_in[6];
    const float* bv  = (const float*)d_in[7];
    const float* Wo  = (const float*)d_in[8];
    const float* bo  = (const float*)d_in[9];
    const float* gcW = (const float*)d_in[10];
    const float* gcb = (const float*)d_in[11];
    const float* W1  = (const float*)d_in[12];
    const float* b1  = (const float*)d_in[13];
    const float* W2  = (const float*)d_in[14];
    const float* b2  = (const float*)d_in[15];
    const float* g_t = (const float*)d_in[16];
    const float* b_t = (const float*)d_in[17];
    const float* g_g = (const float*)d_in[18];
    const float* b_g = (const float*)d_in[19];
    const float* g_f = (const float*)d_in[20];
    const float* b_f = (const float*)d_in[21];
    float* out = (float*)d_out;

    k_deg <<<Nv, 128>>>(adj);
    k_ahat<<<(Nv*Nv)/512, 512>>>(adj);
    k_split<<<(Nv*Nv)/1024, 256>>>(0);
    k_qkv <<<RT128, 128>>>(x, Wq, bq, Wk, bk, Wv, bv);
    k_attn<<<dim3(Nv, Bv), 256>>>();
    k_attnout<<<RT128, 128>>>(x, Wo, bo, g_t, b_t);
    k_split<<<(BTNv*Dv)/1024, 256>>>(1);
    k_prop_mma<<<dim3(Nv/128, BTv), 256>>>(0);
    k_split<<<(BTNv*Dv)/1024, 256>>>(2);
    k_prop_mma<<<dim3(Nv/128, BTv), 256>>>(1);
    k_gc  <<<RT128, 128>>>(gcW, gcb, g_g, b_g);
    k_ffn1<<<dim3(RT128, Fv/64), 128>>>(W1, b1);
    k_ffn2<<<RT128, 128>>>(W2, b2, g_f, b_f, out);
}

// round 10
// speedup vs baseline: 2.2177x; 1.3071x over previous
#include <cuda_runtime.h>
#include <cuda_bf16.h>
#include <math.h>
#include <cstdint>

#define Bv   16
#define Tv   24
#define Nv   512
#define Dv   64
#define Hv   4
#define HDv  16
#define Fv   256
#define BTv  (Bv*Tv)           // 384
#define BTNv (BTv*Nv)          // 196608
#define RT128 (BTNv/128)       // 1536

typedef unsigned long long ull;
typedef __nv_bfloat16 bf16;

// ---------------- scratch (static device globals; no allocation) ----------------
__device__ float g_dinv[Nv];
__device__ float g_q  [BTNv*Dv];
__device__ float g_k  [BTNv*Dv];
__device__ float g_v  [BTNv*Dv];
__device__ float g_h  [BTNv*Dv];
__device__ float g_h2 [BTNv*Dv];
// bf16 hi/lo pairs
__device__ bf16 g_Ahi[Nv*Nv],     g_Alo[Nv*Nv];
__device__ bf16 g_xh [BTNv*Dv],   g_xl [BTNv*Dv];
__device__ bf16 g_atth[BTNv*Dv],  g_attl[BTNv*Dv];
__device__ bf16 g_hh [BTNv*Dv],   g_hl [BTNv*Dv];
__device__ bf16 g_p1h[BTNv*Dv],   g_p1l[BTNv*Dv];
__device__ bf16 g_p2h[BTNv*Dv],   g_p2l[BTNv*Dv];
__device__ bf16 g_h2h[BTNv*Dv],   g_h2l[BTNv*Dv];
__device__ bf16 g_uh [BTNv*Fv],   g_ul [BTNv*Fv];
// weight splits
__device__ bf16 g_Wqh[4096], g_Wql[4096];
__device__ bf16 g_Wkh[4096], g_Wkl[4096];
__device__ bf16 g_Wvh[4096], g_Wvl[4096];
__device__ bf16 g_Woh[4096], g_Wol[4096];
__device__ bf16 g_gcWh[3*4096], g_gcWl[3*4096];
__device__ bf16 g_W1h[64*Fv], g_W1l[64*Fv];
__device__ bf16 g_W2h[Fv*64], g_W2l[Fv*64];

// ================= mma.sync helpers =================
__device__ __forceinline__ uint32_t smem_u32(const void* p) {
    uint32_t a;
    asm("{ .reg .u64 t; cvta.to.shared.u64 t, %1; cvt.u32.u64 %0, t; }" : "=r"(a) : "l"(p));
    return a;
}
#define LDMX4(r, addr) \
    asm volatile("ldmatrix.sync.aligned.m8n8.x4.shared.b16 {%0,%1,%2,%3}, [%4];" \
        : "=r"((r)[0]), "=r"((r)[1]), "=r"((r)[2]), "=r"((r)[3]) : "r"(addr))
#define LDMX2T(r, addr) \
    asm volatile("ldmatrix.sync.aligned.m8n8.x2.trans.shared.b16 {%0,%1}, [%2];" \
        : "=r"((r)[0]), "=r"((r)[1]) : "r"(addr))
#define MMA_BF16(d, a, b) \
    asm volatile("mma.sync.aligned.m16n8k16.row.col.f32.bf16.bf16.f32 " \
        "{%0,%1,%2,%3}, {%4,%5,%6,%7}, {%8,%9}, {%0,%1,%2,%3};" \
        : "+f"((d)[0]), "+f"((d)[1]), "+f"((d)[2]), "+f"((d)[3]) \
        : "r"((a)[0]), "r"((a)[1]), "r"((a)[2]), "r"((a)[3]), \
          "r"((b)[0]), "r"((b)[1]))

__device__ __forceinline__ void sp2(float x, bf16& h, bf16& l) {
    h = __float2bfloat16(x);
    l = __float2bfloat16(x - __bfloat162float(h));
}

// ---- smem layout for the mma kernels (aliased staging / f32 epilogue tile) ----
// sAh  [128*40] bf16 @0      (10240 B)
// sAl  [128*40] bf16 @10240
// sBh  [32*72]  bf16 @20480  (4608 B)
// sBl  [32*72]  bf16 @25088  -> staging ends 29696
// sO   [128*64] f32  @0      (32768 B)  -- used only after staging is dead
#define SMEM_BYTES 33280

__device__ __forceinline__ void stage_A(char* sm, const bf16* __restrict__ gh,
                                        const bf16* __restrict__ gl,
                                        int rowBase, int ldA, int k0, int tid) {
    bf16* sAh = (bf16*)sm;
    bf16* sAl = (bf16*)(sm + 10240);
    #pragma unroll
    for (int i = tid; i < 512; i += 256) {
        int r = i >> 2, c8 = (i & 3) * 8;
        int gi = (rowBase + r)*ldA + k0 + c8;
        *(uint4*)&sAh[r*40 + c8] = *(const uint4*)&gh[gi];
        *(uint4*)&sAl[r*40 + c8] = *(const uint4*)&gl[gi];
    }
}
__device__ __forceinline__ void stage_B(char* sm, const bf16* __restrict__ gh,
                                        const bf16* __restrict__ gl,
                                        int rowBase, int ldB, int colBase, int k0, int tid) {
    bf16* sBh = (bf16*)(sm + 20480);
    bf16* sBl = (bf16*)(sm + 25088);
    int k = tid >> 3, n8 = (tid & 7) * 8;
    int gi = (rowBase + k0 + k)*ldB + colBase + n8;
    *(uint4*)&sBh[k*72 + n8] = *(const uint4*)&gh[gi];
    *(uint4*)&sBl[k*72 + n8] = *(const uint4*)&gl[gi];
}

__device__ __forceinline__ void mma_compute(char* sm, float acc[2][4][4],
                                            int lane, int wm, int wn) {
    uint32_t baseAh = smem_u32(sm), baseAl = smem_u32(sm + 10240);
    uint32_t baseBh = smem_u32(sm + 20480), baseBl = smem_u32(sm + 25088);
    int arow = wm*32 + (lane & 15);
    int acolL = (lane >> 4) * 8;
    int brow = lane & 15;
    int bcol = wn*32;
    #pragma unroll
    for (int ks = 0; ks < 2; ks++) {
        uint32_t aH[2][4], aL[2][4], bH[4][2], bL[4][2];
        int acol = ks*16 + acolL;
        #pragma unroll
        for (int mi = 0; mi < 2; mi++) {
            uint32_t off = ((arow + mi*16)*40 + acol)*2;
            LDMX4(aH[mi], baseAh + off);
            LDMX4(aL[mi], baseAl + off);
        }
        #pragma unroll
        for (int ni = 0; ni < 4; ni++) {
            uint32_t off = ((ks*16 + brow)*72 + bcol + ni*8)*2;
            LDMX2T(bH[ni], baseBh + off);
            LDMX2T(bL[ni], baseBl + off);
        }
        #pragma unroll
        for (int mi = 0; mi < 2; mi++)
            #pragma unroll
            for (int ni = 0; ni < 4; ni++) {
                MMA_BF16(acc[mi][ni], aH[mi], bH[ni]);
                MMA_BF16(acc[mi][ni], aH[mi], bL[ni]);
                MMA_BF16(acc[mi][ni], aL[mi], bH[ni]);
            }
    }
}

// 256-thread LN over sO[128][64]; optional f32 out and/or bf16 hi/lo out
__device__ __forceinline__ void ln256(const float* sO, int r0g,
                                      const float* __restrict__ g,
                                      const float* __restrict__ b,
                                      float* outf, bf16* outh, bf16* outl) {
    int wid = threadIdx.x >> 5, lane = threadIdx.x & 31;
    float gg0 = g[lane], gg1 = g[lane + 32];
    float bb0 = b[lane], bb1 = b[lane + 32];
    for (int r = wid; r < 128; r += 8) {
        float v0 = sO[r*64 + lane];
        float v1 = sO[r*64 + lane + 32];
        float s = v0 + v1;
        #pragma unroll
        for (int o = 16; o; o >>= 1) s += __shfl_xor_sync(0xffffffffu, s, o);
        float m = s * (1.0f/64.0f);
        float d0 = v0 - m, d1 = v1 - m;
        float vs = d0*d0 + d1*d1;
        #pragma unroll
        for (int o = 16; o; o >>= 1) vs += __shfl_xor_sync(0xffffffffu, vs, o);
        float rs = rsqrtf(vs * (1.0f/64.0f) + 1e-5f);
        float o0 = d0*rs*gg0 + bb0;
        float o1 = d1*rs*gg1 + bb1;
        int gi0 = (r0g + r)*64 + lane, gi1 = gi0 + 32;
        if (outf) { outf[gi0] = o0; outf[gi1] = o1; }
        if (outh) {
            bf16 h0, l0, h1, l1;
            sp2(o0, h0, l0); sp2(o1, h1, l1);
            outh[gi0] = h0; outl[gi0] = l0;
            outh[gi1] = h1; outl[gi1] = l1;
        }
    }
}

// ---------------- graph normalization ----------------
__global__ __launch_bounds__(128) void k_deg(const float* __restrict__ adj) {
    __shared__ float red[128];
    int m = blockIdx.x;
    float s = 0.f;
    for (int j = threadIdx.x; j < Nv; j += 128) s += adj[m*Nv + j];
    red[threadIdx.x] = s; __syncthreads();
    for (int o = 64; o; o >>= 1) {
        if (threadIdx.x < o) red[threadIdx.x] += red[threadIdx.x + o];
        __syncthreads();
    }
    if (threadIdx.x == 0) g_dinv[m] = rsqrtf(fmaxf(red[0] + 1.0f, 1e-12f));
}

__global__ __launch_bounds__(512) void k_ahat(const float* __restrict__ adj) {
    int i = blockIdx.x * 512 + threadIdx.x;
    int m = i >> 9, n = i & 511;
    float a = adj[i] + (m == n ? 1.0f : 0.0f);
    float v = g_dinv[m] * a * g_dinv[n];
    bf16 h, l; sp2(v, h, l);
    g_Ahi[i] = h; g_Alo[i] = l;
}

// ---------------- input / weight splits ----------------
__global__ __launch_bounds__(256) void k_splitx(const float* __restrict__ x) {
    int i = (blockIdx.x * 256 + threadIdx.x) * 4;
    float4 v = *(const float4*)&x[i];
    bf16 h0,h1,h2,h3,l0,l1,l2,l3;
    sp2(v.x,h0,l0); sp2(v.y,h1,l1); sp2(v.z,h2,l2); sp2(v.w,h3,l3);
    *(__nv_bfloat162*)&g_xh[i]   = __nv_bfloat162(h0,h1);
    *(__nv_bfloat162*)&g_xh[i+2] = __nv_bfloat162(h2,h3);
    *(__nv_bfloat162*)&g_xl[i]   = __nv_bfloat162(l0,l1);
    *(__nv_bfloat162*)&g_xl[i+2] = __nv_bfloat162(l2,l3);
}

__global__ __launch_bounds__(256) void k_splitw(
    const float* __restrict__ Wq, const float* __restrict__ Wk,
    const float* __restrict__ Wv, const float* __restrict__ Wo,
    const float* __restrict__ gcW, const float* __restrict__ W1,
    const float* __restrict__ W2) {
    int i = blockIdx.x * 256 + threadIdx.x;
    const float* src; bf16 *dh, *dl; int off;
    if      (i < 4096)  { src = Wq;  dh = g_Wqh;  dl = g_Wql;  off = i; }
    else if (i < 8192)  { src = Wk;  dh = g_Wkh;  dl = g_Wkl;  off = i - 4096; }
    else if (i < 12288) { src = Wv;  dh = g_Wvh;  dl = g_Wvl;  off = i - 8192; }
    else if (i < 16384) { src = Wo;  dh = g_Woh;  dl = g_Wol;  off = i - 12288; }
    else if (i < 28672) { src = gcW; dh = g_gcWh; dl = g_gcWl; off = i - 16384; }
    else if (i < 45056) { src = W1;  dh = g_W1h;  dl = g_W1l;  off = i - 28672; }
    else if (i < 61440) { src = W2;  dh = g_W2h;  dl = g_W2l;  off = i - 45056; }
    else return;
    bf16 h, l; sp2(src[off], h, l);
    dh[off] = h; dl[off] = l;
}

// ---------------- QKV: x @ {Wq,Wk,Wv} + bias -> f32 q/k/v ----------------
__global__ __launch_bounds__(256) void k_qkv_mma(const float* __restrict__ bq,
                                                 const float* __restrict__ bk,
                                                 const float* __restrict__ bv) {
    __shared__ __align__(16) char sm[SMEM_BYTES];
    int tid = threadIdx.x, lane = tid & 31, wid = tid >> 5;
    int wm = wid & 3, wn = wid >> 2;
    int r0g = blockIdx.x * 128;
    int sel = blockIdx.y;
    const bf16* Wh = sel == 0 ? g_Wqh : sel == 1 ? g_Wkh : g_Wvh;
    const bf16* Wl = sel == 0 ? g_Wql : sel == 1 ? g_Wkl : g_Wvl;
    const float* bias = sel == 0 ? bq : sel == 1 ? bk : bv;
    float* out = sel == 0 ? g_q : sel == 1 ? g_k : g_v;

    float acc[2][4][4] = {};
    #pragma unroll
    for (int kc = 0; kc < 2; kc++) {
        stage_A(sm, g_xh, g_xl, r0g, 64, kc*32, tid);
        stage_B(sm, Wh, Wl, 0, 64, 0, kc*32, tid);
        __syncthreads();
        mma_compute(sm, acc, lane, wm, wn);
        __syncthreads();
    }
    int r = lane >> 2, cb = (lane & 3)*2;
    #pragma unroll
    for (int mi = 0; mi < 2; mi++)
        #pragma unroll
        for (int ni = 0; ni < 4; ni++) {
            int m = r0g + wm*32 + mi*16 + r;
            int n = wn*32 + ni*8 + cb;
            float b0 = bias[n], b1 = bias[n+1];
            *(float2*)&out[m*64 + n]     = make_float2(acc[mi][ni][0] + b0, acc[mi][ni][1] + b1);
            *(float2*)&out[(m+8)*64 + n] = make_float2(acc[mi][ni][2] + b0, acc[mi][ni][3] + b1);
        }
}

// ---------------- temporal attention -> att hi/lo ----------------
__global__ __launch_bounds__(256) void k_attn() {
    __shared__ __align__(16) float sqT[64*28];
    __shared__ __align__(16) float skT[64*28];
    __shared__ __align__(16) float sv[Tv*64];
    __shared__ __align__(16) float so[Tv*64];
    __shared__ __align__(16) float ss[Hv*Tv*25];
    int tid = threadIdx.x;
    int n = blockIdx.x, b = blockIdx.y;
    for (int i = tid; i < Tv*64; i += 256) {
        int t = i >> 6, d = i & 63;
        int gidx = ((b*Tv + t)*Nv + n)*64 + d;
        sqT[d*28 + t] = g_q[gidx];
        skT[d*28 + t] = g_k[gidx];
        sv[i]         = g_v[gidx];
    }
    __syncthreads();
    if (tid < Hv*36) {
        int h = tid / 36, blk = tid % 36;
        int tq0 = (blk / 6) * 4, tk0 = (blk % 6) * 4;
        float s[4][4] = {};
        const float* qb = &sqT[h*HDv*28];
        const float* kb = &skT[h*HDv*28];
        #pragma unroll
        for (int e = 0; e < HDv; e++) {
            float4 q4 = *(const float4*)(qb + e*28 + tq0);
            float4 k4 = *(const float4*)(kb + e*28 + tk0);
            float qa[4] = {q4.x, q4.y, q4.z, q4.w};
            float ka[4] = {k4.x, k4.y, k4.z, k4.w};
            #pragma unroll
            for (int i = 0; i < 4; i++)
                #pragma unroll
                for (int j = 0; j < 4; j++)
                    s[i][j] = fmaf(qa[i], ka[j], s[i][j]);
        }
        #pragma unroll
        for (int i = 0; i < 4; i++)
            #pragma unroll
            for (int j = 0; j < 4; j++)
                ss[(h*Tv + tq0 + i)*25 + tk0 + j] = s[i][j] * 0.25f;
    }
    __syncthreads();
    if (tid < Hv*Tv) {
        float* row = &ss[tid*25];
        float mx = -1e30f;
        #pragma unroll
        for (int tk = 0; tk < Tv; tk++) mx = fmaxf(mx, row[tk]);
        float sum = 0.f;
        #pragma unroll
        for (int tk = 0; tk < Tv; tk++) { float e = expf(row[tk]-mx); row[tk] = e; sum += e; }
        float inv = 1.0f / sum;
        #pragma unroll
        for (int tk = 0; tk < Tv; tk++) row[tk] *= inv;
    }
    __syncthreads();
    if (tid < Hv*24) {
        int h = tid / 24, blk = tid % 24;
        int tq0 = (blk / 4) * 4, e0 = (blk % 4) * 4;
        float o[4][4] = {};
        #pragma unroll
        for (int tk = 0; tk < Tv; tk++) {
            float4 v4 = *(const float4*)&sv[tk*64 + h*HDv + e0];
            float va[4] = {v4.x, v4.y, v4.z, v4.w};
            float pa[4];
            #pragma unroll
            for (int i = 0; i < 4; i++) pa[i] = ss[(h*Tv + tq0 + i)*25 + tk];
            #pragma unroll
            for (int i = 0; i < 4; i++)
                #pragma unroll
                for (int j = 0; j < 4; j++)
                    o[i][j] = fmaf(pa[i], va[j], o[i][j]);
        }
        #pragma unroll
        for (int i = 0; i < 4; i++)
            *(float4*)&so[(tq0 + i)*64 + h*HDv + e0] =
                make_float4(o[i][0], o[i][1], o[i][2], o[i][3]);
    }
    __syncthreads();
    for (int i = tid; i < Tv*64; i += 256) {
        int t = i >> 6, d = i & 63;
        int gi = ((b*Tv + t)*Nv + n)*64 + d;
        bf16 h, l; sp2(so[i], h, l);
        g_atth[gi] = h; g_attl[gi] = l;
    }
}

// ---------------- attnout: att @ Wo + bo + x -> LN -> g_h (f32 + hi/lo) ----------------
__global__ __launch_bounds__(256) void k_attnout_mma(const float* __restrict__ x,
    const float* __restrict__ bo,
    const float* __restrict__ gt, const float* __restrict__ bt) {
    __shared__ __align__(16) char sm[SMEM_BYTES];
    int tid = threadIdx.x, lane = tid & 31, wid = tid >> 5;
    int wm = wid & 3, wn = wid >> 2;
    int r0g = blockIdx.x * 128;

    float acc[2][4][4] = {};
    #pragma unroll
    for (int kc = 0; kc < 2; kc++) {
        stage_A(sm, g_atth, g_attl, r0g, 64, kc*32, tid);
        stage_B(sm, g_Woh, g_Wol, 0, 64, 0, kc*32, tid);
        __syncthreads();
        mma_compute(sm, acc, lane, wm, wn);
        __syncthreads();
    }
    float* sO = (float*)sm;
    int r = lane >> 2, cb = (lane & 3)*2;
    #pragma unroll
    for (int mi = 0; mi < 2; mi++)
        #pragma unroll
        for (int ni = 0; ni < 4; ni++) {
            int m = wm*32 + mi*16 + r;
            int n = wn*32 + ni*8 + cb;
            float b0 = bo[n], b1 = bo[n+1];
            float2 x0 = *(const float2*)&x[(r0g + m)*64 + n];
            float2 x1 = *(const float2*)&x[(r0g + m + 8)*64 + n];
            *(float2*)&sO[m*64 + n]     = make_float2(acc[mi][ni][0] + b0 + x0.x, acc[mi][ni][1] + b1 + x0.y);
            *(float2*)&sO[(m+8)*64 + n] = make_float2(acc[mi][ni][2] + b0 + x1.x, acc[mi][ni][3] + b1 + x1.y);
        }
    __syncthreads();
    ln256(sO, r0g, gt, bt, g_h, g_hh, g_hl);
}

// ---------------- prop: out = Ahat @ in (hi/lo -> hi/lo) ----------------
__global__ __launch_bounds__(256) void k_prop_mma(int pass) {
    __shared__ __align__(16) char sm[SMEM_BYTES];
    const bf16* inh = pass ? g_p1h : g_hh;
    const bf16* inl = pass ? g_p1l : g_hl;
    bf16* outh = pass ? g_p2h : g_p1h;
    bf16* outl = pass ? g_p2l : g_p1l;
    int tid = threadIdx.x, lane = tid & 31, wid = tid >> 5;
    int wm = wid & 3, wn = wid >> 2;
    int m0 = blockIdx.x * 128, bt = blockIdx.y;

    float acc[2][4][4] = {};
    for (int kc = 0; kc < 16; kc++) {
        stage_A(sm, g_Ahi, g_Alo, m0, Nv, kc*32, tid);
        stage_B(sm, inh, inl, bt*Nv, 64, 0, kc*32, tid);
        __syncthreads();
        mma_compute(sm, acc, lane, wm, wn);
        __syncthreads();
    }
    int r = lane >> 2, cb = (lane & 3)*2;
    #pragma unroll
    for (int mi = 0; mi < 2; mi++)
        #pragma unroll
        for (int ni = 0; ni < 4; ni++) {
            int m = m0 + wm*32 + mi*16 + r;
            int n = wn*32 + ni*8 + cb;
            bf16 h0,l0,h1,l1,h2,l2,h3,l3;
            sp2(acc[mi][ni][0], h0, l0); sp2(acc[mi][ni][1], h1, l1);
            sp2(acc[mi][ni][2], h2, l2); sp2(acc[mi][ni][3], h3, l3);
            *(__nv_bfloat162*)&outh[(bt*Nv + m)*64 + n]     = __nv_bfloat162(h0, h1);
            *(__nv_bfloat162*)&outl[(bt*Nv + m)*64 + n]     = __nv_bfloat162(l0, l1);
            *(__nv_bfloat162*)&outh[(bt*Nv + m + 8)*64 + n] = __nv_bfloat162(h2, h3);
            *(__nv_bfloat162*)&outl[(bt*Nv + m + 8)*64 + n] = __nv_bfloat162(l2, l3);
        }
}

// ---------------- gc: h@W0 + p1@W1 + p2@W2 + bias + h -> LN -> g_h2 (f32 + hi/lo) ----
__global__ __launch_bounds__(256) void k_gc_mma(const float* __restrict__ gcb,
    const float* __restrict__ gg, const float* __restrict__ bg) {
    __shared__ __align__(16) char sm[SMEM_BYTES];
    int tid = threadIdx.x, lane = tid & 31, wid = tid >> 5;
    int wm = wid & 3, wn = wid >> 2;
    int r0g = blockIdx.x * 128;

    float acc[2][4][4] = {};
    const bf16* ih[3] = {g_hh, g_p1h, g_p2h};
    const bf16* il[3] = {g_hl, g_p1l, g_p2l};
    #pragma unroll
    for (int mm = 0; mm < 3; mm++)
        #pragma unroll
        for (int kc = 0; kc < 2; kc++) {
            stage_A(sm, ih[mm], il[mm], r0g, 64, kc*32, tid);
            stage_B(sm, g_gcWh + mm*4096, g_gcWl + mm*4096, 0, 64, 0, kc*32, tid);
            __syncthreads();
            mma_compute(sm, acc, lane, wm, wn);
            __syncthreads();
        }
    float* sO = (float*)sm;
    int r = lane >> 2, cb = (lane & 3)*2;
    #pragma unroll
    for (int mi = 0; mi < 2; mi++)
        #pragma unroll
        for (int ni = 0; ni < 4; ni++) {
            int m = wm*32 + mi*16 + r;
            int n = wn*32 + ni*8 + cb;
            float b0 = gcb[n] + gcb[64+n] + gcb[128+n];
            float b1 = gcb[n+1] + gcb[64+n+1] + gcb[128+n+1];
            float2 h0 = *(const float2*)&g_h[(r0g + m)*64 + n];
            float2 h1 = *(const float2*)&g_h[(r0g + m + 8)*64 + n];
            *(float2*)&sO[m*64 + n]     = make_float2(acc[mi][ni][0] + b0 + h0.x, acc[mi][ni][1] + b1 + h0.y);
            *(float2*)&sO[(m+8)*64 + n] = make_float2(acc[mi][ni][2] + b0 + h1.x, acc[mi][ni][3] + b1 + h1.y);
        }
    __syncthreads();
    ln256(sO, r0g, gg, bg, g_h2, g_h2h, g_h2l);
}

// ---------------- ffn1: gelu(h2 @ W1 + b1) -> u hi/lo ----------------
__global__ __launch_bounds__(256) void k_ffn1_mma(const float* __restrict__ b1) {
    __shared__ __align__(16) char sm[SMEM_BYTES];
    int tid = threadIdx.x, lane = tid & 31, wid = tid >> 5;
    int wm = wid & 3, wn = wid >> 2;
    int r0g = blockIdx.x * 128;
    int c0g = blockIdx.y * 64;

    float acc[2][4][4] = {};
    #pragma unroll
    for (int kc = 0; kc < 2; kc++) {
        stage_A(sm, g_h2h, g_h2l, r0g, 64, kc*32, tid);
        stage_B(sm, g_W1h, g_W1l, 0, Fv, c0g, kc*32, tid);
        __syncthreads();
        mma_compute(sm, acc, lane, wm, wn);
        __syncthreads();
    }
    int r = lane >> 2, cb = (lane & 3)*2;
    #pragma unroll
    for (int mi = 0; mi < 2; mi++)
        #pragma unroll
        for (int ni = 0; ni < 4; ni++) {
            int m = r0g + wm*32 + mi*16 + r;
            int n = wn*32 + ni*8 + cb;
            float b0 = b1[c0g + n], b1v = b1[c0g + n + 1];
            float v[4] = {acc[mi][ni][0] + b0, acc[mi][ni][1] + b1v,
                          acc[mi][ni][2] + b0, acc[mi][ni][3] + b1v};
            #pragma unroll
            for (int j = 0; j < 4; j++)
                v[j] = 0.5f * v[j] * (1.0f + erff(v[j] * 0.70710678118654752f));
            bf16 h0,l0,h1,l1,h2,l2,h3,l3;
            sp2(v[0],h0,l0); sp2(v[1],h1,l1); sp2(v[2],h2,l2); sp2(v[3],h3,l3);
            *(__nv_bfloat162*)&g_uh[m*Fv + c0g + n]     = __nv_bfloat162(h0, h1);
            *(__nv_bfloat162*)&g_ul[m*Fv + c0g + n]     = __nv_bfloat162(l0, l1);
            *(__nv_bfloat162*)&g_uh[(m+8)*Fv + c0g + n] = __nv_bfloat162(h2, h3);
            *(__nv_bfloat162*)&g_ul[(m+8)*Fv + c0g + n] = __nv_bfloat162(l2, l3);
        }
}

// ---------------- ffn2: u @ W2 + b2 + h2 -> LN -> out ----------------
__global__ __launch_bounds__(256) void k_ffn2_mma(const float* __restrict__ b2,
    const float* __restrict__ gf, const float* __restrict__ bf,
    float* __restrict__ out) {
    __shared__ __align__(16) char sm[SMEM_BYTES];
    int tid = threadIdx.x, lane = tid & 31, wid = tid >> 5;
    int wm = wid & 3, wn = wid >> 2;
    int r0g = blockIdx.x * 128;

    float acc[2][4][4] = {};
    #pragma unroll
    for (int kc = 0; kc < 8; kc++) {
        stage_A(sm, g_uh, g_ul, r0g, Fv, kc*32, tid);
        stage_B(sm, g_W2h, g_W2l, 0, 64, 0, kc*32, tid);
        __syncthreads();
        mma_compute(sm, acc, lane, wm, wn);
        __syncthreads();
    }
    float* sO = (float*)sm;
    int r = lane >> 2, cb = (lane & 3)*2;
    #pragma unroll
    for (int mi = 0; mi < 2; mi++)
        #pragma unroll
        for (int ni = 0; ni < 4; ni++) {
            int m = wm*32 + mi*16 + r;
            int n = wn*32 + ni*8 + cb;
            float b0 = b2[n], b1 = b2[n+1];
            float2 h0 = *(const float2*)&g_h2[(r0g + m)*64 + n];
            float2 h1 = *(const float2*)&g_h2[(r0g + m + 8)*64 + n];
            *(float2*)&sO[m*64 + n]     = make_float2(acc[mi][ni][0] + b0 + h0.x, acc[mi][ni][1] + b1 + h0.y);
            *(float2*)&sO[(m+8)*64 + n] = make_float2(acc[mi][ni][2] + b0 + h1.x, acc[mi][ni][3] + b1 + h1.y);
        }
    __syncthreads();
    ln256(sO, r0g, gf, bf, out, (bf16*)0, (bf16*)0);
}

// ---------------- launch ----------------
extern "C" void kernel_launch(void* const* d_in, const int* in_sizes, int n_in,
                              void* d_out, int out_size) {
    const float* x   = (const float*)d_in[0];
    const float* adj = (const float*)d_in[1];
    const float* Wq  = (const float*)d_in[2];
    const float* bq  = (const float*)d_in[3];
    const float* Wk  = (const float*)d_in[4];
    const float* bk  = (const float*)d_in[5];
    const float* Wv  = (const float*)d_in[6];
    const float* bv  = (const float*)d_in[7];
    const float* Wo  = (const float*)d_in[8];
    const float* bo  = (const float*)d_in[9];
    const float* gcW = (const float*)d_in[10];
    const float* gcb = (const float*)d_in[11];
    const float* W1  = (const float*)d_in[12];
    const float* b1  = (const float*)d_in[13];
    const float* W2  = (const float*)d_in[14];
    const float* b2  = (const float*)d_in[15];
    const float* g_t = (const float*)d_in[16];
    const float* b_t = (const float*)d_in[17];
    const float* g_g = (const float*)d_in[18];
    const float* b_g = (const float*)d_in[19];
    const float* g_f = (const float*)d_in[20];
    const float* b_f = (const float*)d_in[21];
    float* out = (float*)d_out;

    k_deg   <<<Nv, 128>>>(adj);
    k_ahat  <<<(Nv*Nv)/512, 512>>>(adj);
    k_splitx<<<(BTNv*Dv)/1024, 256>>>(x);
    k_splitw<<<240, 256>>>(Wq, Wk, Wv, Wo, gcW, W1, W2);
    k_qkv_mma<<<dim3(RT128, 3), 256>>>(bq, bk, bv);
    k_attn  <<<dim3(Nv, Bv), 256>>>();
    k_attnout_mma<<<RT128, 256>>>(x, bo, g_t, b_t);
    k_prop_mma<<<dim3(Nv/128, BTv), 256>>>(0);
    k_prop_mma<<<dim3(Nv/128, BTv), 256>>>(1);
    k_gc_mma<<<RT128, 256>>>(gcb, g_g, b_g);
    k_ffn1_mma<<<dim3(RT128, Fv/64), 256>>>(b1);
    k_ffn2_mma<<<RT128, 256>>>(b2, g_f, b_f, out);
}

// round 11
// speedup vs baseline: 2.3291x; 1.0502x over previous
#include <cuda_runtime.h>
#include <cuda_bf16.h>
#include <math.h>
#include <cstdint>

#define Bv   16
#define Tv   24
#define Nv   512
#define Dv   64
#define Hv   4
#define HDv  16
#define Fv   256
#define BTv  (Bv*Tv)           // 384
#define BTNv (BTv*Nv)          // 196608
#define RT128 (BTNv/128)       // 1536

typedef unsigned long long ull;
typedef __nv_bfloat16 bf16;

// ---------------- scratch (static device globals; no allocation) ----------------
__device__ float g_dinv[Nv];
__device__ float g_q  [BTNv*Dv];
__device__ float g_k  [BTNv*Dv];
__device__ float g_v  [BTNv*Dv];
__device__ float g_h  [BTNv*Dv];
__device__ float g_h2 [BTNv*Dv];
// bf16 hi/lo pairs
__device__ bf16 g_Ahi[Nv*Nv],     g_Alo[Nv*Nv];
__device__ bf16 g_xh [BTNv*Dv],   g_xl [BTNv*Dv];
__device__ bf16 g_atth[BTNv*Dv],  g_attl[BTNv*Dv];
__device__ bf16 g_hh [BTNv*Dv],   g_hl [BTNv*Dv];
__device__ bf16 g_p1h[BTNv*Dv],   g_p1l[BTNv*Dv];
__device__ bf16 g_p2h[BTNv*Dv],   g_p2l[BTNv*Dv];
__device__ bf16 g_h2h[BTNv*Dv],   g_h2l[BTNv*Dv];
__device__ bf16 g_uh [BTNv*Fv],   g_ul [BTNv*Fv];
// weight splits
__device__ bf16 g_Wqh[4096], g_Wql[4096];
__device__ bf16 g_Wkh[4096], g_Wkl[4096];
__device__ bf16 g_Wvh[4096], g_Wvl[4096];
__device__ bf16 g_Woh[4096], g_Wol[4096];
__device__ bf16 g_gcWh[3*4096], g_gcWl[3*4096];
__device__ bf16 g_W1h[64*Fv], g_W1l[64*Fv];
__device__ bf16 g_W2h[Fv*64], g_W2l[Fv*64];

// ================= mma.sync / cp.async helpers =================
__device__ __forceinline__ uint32_t smem_u32(const void* p) {
    uint32_t a;
    asm("{ .reg .u64 t; cvta.to.shared.u64 t, %1; cvt.u32.u64 %0, t; }" : "=r"(a) : "l"(p));
    return a;
}
#define LDMX4(r, addr) \
    asm volatile("ldmatrix.sync.aligned.m8n8.x4.shared.b16 {%0,%1,%2,%3}, [%4];" \
        : "=r"((r)[0]), "=r"((r)[1]), "=r"((r)[2]), "=r"((r)[3]) : "r"(addr))
#define LDMX2T(r, addr) \
    asm volatile("ldmatrix.sync.aligned.m8n8.x2.trans.shared.b16 {%0,%1}, [%2];" \
        : "=r"((r)[0]), "=r"((r)[1]) : "r"(addr))
#define MMA_BF16(d, a, b) \
    asm volatile("mma.sync.aligned.m16n8k16.row.col.f32.bf16.bf16.f32 " \
        "{%0,%1,%2,%3}, {%4,%5,%6,%7}, {%8,%9}, {%0,%1,%2,%3};" \
        : "+f"((d)[0]), "+f"((d)[1]), "+f"((d)[2]), "+f"((d)[3]) \
        : "r"((a)[0]), "r"((a)[1]), "r"((a)[2]), "r"((a)[3]), \
          "r"((b)[0]), "r"((b)[1]))
#define CP16(saddr, gptr) \
    asm volatile("cp.async.ca.shared.global [%0], [%1], 16;" :: "r"(saddr), "l"(gptr))
#define CP_COMMIT() asm volatile("cp.async.commit_group;" ::: "memory")
#define CP_WAIT0()  asm volatile("cp.async.wait_group 0;" ::: "memory")
#define CP_WAIT1()  asm volatile("cp.async.wait_group 1;" ::: "memory")

__device__ __forceinline__ void sp2(float x, bf16& h, bf16& l) {
    h = __float2bfloat16(x);
    l = __float2bfloat16(x - __bfloat162float(h));
}

// ---- smem layout for the generic mma kernels (aliased staging / f32 tile) ----
// sAh  [128*40] bf16 @0      (10240 B)
// sAl  [128*40] bf16 @10240
// sBh  [32*72]  bf16 @20480  (4608 B)
// sBl  [32*72]  bf16 @25088  -> staging ends 29696
// sO   [128*64] f32  @0      (32768 B)  -- used only after staging is dead
#define SMEM_BYTES 33280

__device__ __forceinline__ void stage_A(char* sm, const bf16* __restrict__ gh,
                                        const bf16* __restrict__ gl,
                                        int rowBase, int ldA, int k0, int tid) {
    uint32_t sAh = smem_u32(sm);
    uint32_t sAl = sAh + 10240;
    #pragma unroll
    for (int i = tid; i < 512; i += 256) {
        int r = i >> 2, c8 = (i & 3) * 8;
        int gi = (rowBase + r)*ldA + k0 + c8;
        uint32_t off = (r*40 + c8)*2;
        CP16(sAh + off, &gh[gi]);
        CP16(sAl + off, &gl[gi]);
    }
}
__device__ __forceinline__ void stage_B(char* sm, const bf16* __restrict__ gh,
                                        const bf16* __restrict__ gl,
                                        int rowBase, int ldB, int colBase, int k0, int tid) {
    uint32_t sBh = smem_u32(sm) + 20480;
    uint32_t sBl = sBh + 4608;
    int k = tid >> 3, n8 = (tid & 7) * 8;
    int gi = (rowBase + k0 + k)*ldB + colBase + n8;
    uint32_t off = (k*72 + n8)*2;
    CP16(sBh + off, &gh[gi]);
    CP16(sBl + off, &gl[gi]);
}

__device__ __forceinline__ void mma_compute(char* sm, float acc[2][4][4],
                                            int lane, int wm, int wn) {
    uint32_t baseAh = smem_u32(sm), baseAl = smem_u32(sm + 10240);
    uint32_t baseBh = smem_u32(sm + 20480), baseBl = smem_u32(sm + 25088);
    int arow = wm*32 + (lane & 15);
    int acolL = (lane >> 4) * 8;
    int brow = lane & 15;
    int bcol = wn*32;
    #pragma unroll
    for (int ks = 0; ks < 2; ks++) {
        uint32_t aH[2][4], aL[2][4], bH[4][2], bL[4][2];
        int acol = ks*16 + acolL;
        #pragma unroll
        for (int mi = 0; mi < 2; mi++) {
            uint32_t off = ((arow + mi*16)*40 + acol)*2;
            LDMX4(aH[mi], baseAh + off);
            LDMX4(aL[mi], baseAl + off);
        }
        #pragma unroll
        for (int ni = 0; ni < 4; ni++) {
            uint32_t off = ((ks*16 + brow)*72 + bcol + ni*8)*2;
            LDMX2T(bH[ni], baseBh + off);
            LDMX2T(bL[ni], baseBl + off);
        }
        #pragma unroll
        for (int mi = 0; mi < 2; mi++)
            #pragma unroll
            for (int ni = 0; ni < 4; ni++) {
                MMA_BF16(acc[mi][ni], aH[mi], bH[ni]);
                MMA_BF16(acc[mi][ni], aH[mi], bL[ni]);
                MMA_BF16(acc[mi][ni], aL[mi], bH[ni]);
            }
    }
}

// 256-thread LN over sO[128][64]; optional f32 out and/or bf16 hi/lo out
__device__ __forceinline__ void ln256(const float* sO, int r0g,
                                      const float* __restrict__ g,
                                      const float* __restrict__ b,
                                      float* outf, bf16* outh, bf16* outl) {
    int wid = threadIdx.x >> 5, lane = threadIdx.x & 31;
    float gg0 = g[lane], gg1 = g[lane + 32];
    float bb0 = b[lane], bb1 = b[lane + 32];
    for (int r = wid; r < 128; r += 8) {
        float v0 = sO[r*64 + lane];
        float v1 = sO[r*64 + lane + 32];
        float s = v0 + v1;
        #pragma unroll
        for (int o = 16; o; o >>= 1) s += __shfl_xor_sync(0xffffffffu, s, o);
        float m = s * (1.0f/64.0f);
        float d0 = v0 - m, d1 = v1 - m;
        float vs = d0*d0 + d1*d1;
        #pragma unroll
        for (int o = 16; o; o >>= 1) vs += __shfl_xor_sync(0xffffffffu, vs, o);
        float rs = rsqrtf(vs * (1.0f/64.0f) + 1e-5f);
        float o0 = d0*rs*gg0 + bb0;
        float o1 = d1*rs*gg1 + bb1;
        int gi0 = (r0g + r)*64 + lane, gi1 = gi0 + 32;
        if (outf) { outf[gi0] = o0; outf[gi1] = o1; }
        if (outh) {
            bf16 h0, l0, h1, l1;
            sp2(o0, h0, l0); sp2(o1, h1, l1);
            outh[gi0] = h0; outl[gi0] = l0;
            outh[gi1] = h1; outl[gi1] = l1;
        }
    }
}

// ---------------- graph normalization ----------------
__global__ __launch_bounds__(128) void k_deg(const float* __restrict__ adj) {
    __shared__ float red[128];
    int m = blockIdx.x;
    float s = 0.f;
    for (int j = threadIdx.x; j < Nv; j += 128) s += adj[m*Nv + j];
    red[threadIdx.x] = s; __syncthreads();
    for (int o = 64; o; o >>= 1) {
        if (threadIdx.x < o) red[threadIdx.x] += red[threadIdx.x + o];
        __syncthreads();
    }
    if (threadIdx.x == 0) g_dinv[m] = rsqrtf(fmaxf(red[0] + 1.0f, 1e-12f));
}

__global__ __launch_bounds__(512) void k_ahat(const float* __restrict__ adj) {
    int i = blockIdx.x * 512 + threadIdx.x;
    int m = i >> 9, n = i & 511;
    float a = adj[i] + (m == n ? 1.0f : 0.0f);
    float v = g_dinv[m] * a * g_dinv[n];
    bf16 h, l; sp2(v, h, l);
    g_Ahi[i] = h; g_Alo[i] = l;
}

// ---------------- input / weight splits ----------------
__global__ __launch_bounds__(256) void k_splitx(const float* __restrict__ x) {
    int i = (blockIdx.x * 256 + threadIdx.x) * 4;
    float4 v = *(const float4*)&x[i];
    bf16 h0,h1,h2,h3,l0,l1,l2,l3;
    sp2(v.x,h0,l0); sp2(v.y,h1,l1); sp2(v.z,h2,l2); sp2(v.w,h3,l3);
    *(__nv_bfloat162*)&g_xh[i]   = __nv_bfloat162(h0,h1);
    *(__nv_bfloat162*)&g_xh[i+2] = __nv_bfloat162(h2,h3);
    *(__nv_bfloat162*)&g_xl[i]   = __nv_bfloat162(l0,l1);
    *(__nv_bfloat162*)&g_xl[i+2] = __nv_bfloat162(l2,l3);
}

__global__ __launch_bounds__(256) void k_splitw(
    const float* __restrict__ Wq, const float* __restrict__ Wk,
    const float* __restrict__ Wv, const float* __restrict__ Wo,
    const float* __restrict__ gcW, const float* __restrict__ W1,
    const float* __restrict__ W2) {
    int i = blockIdx.x * 256 + threadIdx.x;
    const float* src; bf16 *dh, *dl; int off;
    if      (i < 4096)  { src = Wq;  dh = g_Wqh;  dl = g_Wql;  off = i; }
    else if (i < 8192)  { src = Wk;  dh = g_Wkh;  dl = g_Wkl;  off = i - 4096; }
    else if (i < 12288) { src = Wv;  dh = g_Wvh;  dl = g_Wvl;  off = i - 8192; }
    else if (i < 16384) { src = Wo;  dh = g_Woh;  dl = g_Wol;  off = i - 12288; }
    else if (i < 28672) { src = gcW; dh = g_gcWh; dl = g_gcWl; off = i - 16384; }
    else if (i < 45056) { src = W1;  dh = g_W1h;  dl = g_W1l;  off = i - 28672; }
    else if (i < 61440) { src = W2;  dh = g_W2h;  dl = g_W2l;  off = i - 45056; }
    else return;
    bf16 h, l; sp2(src[off], h, l);
    dh[off] = h; dl[off] = l;
}

// ---------------- QKV: x @ {Wq,Wk,Wv} + bias -> f32 q/k/v ----------------
__global__ __launch_bounds__(256) void k_qkv_mma(const float* __restrict__ bq,
                                                 const float* __restrict__ bk,
                                                 const float* __restrict__ bv) {
    __shared__ __align__(16) char sm[SMEM_BYTES];
    int tid = threadIdx.x, lane = tid & 31, wid = tid >> 5;
    int wm = wid & 3, wn = wid >> 2;
    int r0g = blockIdx.x * 128;
    int sel = blockIdx.y;
    const bf16* Wh = sel == 0 ? g_Wqh : sel == 1 ? g_Wkh : g_Wvh;
    const bf16* Wl = sel == 0 ? g_Wql : sel == 1 ? g_Wkl : g_Wvl;
    const float* bias = sel == 0 ? bq : sel == 1 ? bk : bv;
    float* out = sel == 0 ? g_q : sel == 1 ? g_k : g_v;

    float acc[2][4][4] = {};
    #pragma unroll
    for (int kc = 0; kc < 2; kc++) {
        stage_A(sm, g_xh, g_xl, r0g, 64, kc*32, tid);
        stage_B(sm, Wh, Wl, 0, 64, 0, kc*32, tid);
        CP_COMMIT(); CP_WAIT0();
        __syncthreads();
        mma_compute(sm, acc, lane, wm, wn);
        __syncthreads();
    }
    int r = lane >> 2, cb = (lane & 3)*2;
    #pragma unroll
    for (int mi = 0; mi < 2; mi++)
        #pragma unroll
        for (int ni = 0; ni < 4; ni++) {
            int m = r0g + wm*32 + mi*16 + r;
            int n = wn*32 + ni*8 + cb;
            float b0 = bias[n], b1 = bias[n+1];
            *(float2*)&out[m*64 + n]     = make_float2(acc[mi][ni][0] + b0, acc[mi][ni][1] + b1);
            *(float2*)&out[(m+8)*64 + n] = make_float2(acc[mi][ni][2] + b0, acc[mi][ni][3] + b1);
        }
}

// ---------------- temporal attention -> att hi/lo ----------------
__global__ __launch_bounds__(256) void k_attn() {
    __shared__ __align__(16) float sqT[64*28];
    __shared__ __align__(16) float skT[64*28];
    __shared__ __align__(16) float sv[Tv*64];
    __shared__ __align__(16) float so[Tv*64];
    __shared__ __align__(16) float ss[Hv*Tv*25];
    int tid = threadIdx.x;
    int n = blockIdx.x, b = blockIdx.y;
    for (int i = tid; i < Tv*64; i += 256) {
        int t = i >> 6, d = i & 63;
        int gidx = ((b*Tv + t)*Nv + n)*64 + d;
        sqT[d*28 + t] = g_q[gidx];
        skT[d*28 + t] = g_k[gidx];
        sv[i]         = g_v[gidx];
    }
    __syncthreads();
    if (tid < Hv*36) {
        int h = tid / 36, blk = tid % 36;
        int tq0 = (blk / 6) * 4, tk0 = (blk % 6) * 4;
        float s[4][4] = {};
        const float* qb = &sqT[h*HDv*28];
        const float* kb = &skT[h*HDv*28];
        #pragma unroll
        for (int e = 0; e < HDv; e++) {
            float4 q4 = *(const float4*)(qb + e*28 + tq0);
            float4 k4 = *(const float4*)(kb + e*28 + tk0);
            float qa[4] = {q4.x, q4.y, q4.z, q4.w};
            float ka[4] = {k4.x, k4.y, k4.z, k4.w};
            #pragma unroll
            for (int i = 0; i < 4; i++)
                #pragma unroll
                for (int j = 0; j < 4; j++)
                    s[i][j] = fmaf(qa[i], ka[j], s[i][j]);
        }
        #pragma unroll
        for (int i = 0; i < 4; i++)
            #pragma unroll
            for (int j = 0; j < 4; j++)
                ss[(h*Tv + tq0 + i)*25 + tk0 + j] = s[i][j] * 0.25f;
    }
    __syncthreads();
    if (tid < Hv*Tv) {
        float* row = &ss[tid*25];
        float mx = -1e30f;
        #pragma unroll
        for (int tk = 0; tk < Tv; tk++) mx = fmaxf(mx, row[tk]);
        float sum = 0.f;
        #pragma unroll
        for (int tk = 0; tk < Tv; tk++) { float e = expf(row[tk]-mx); row[tk] = e; sum += e; }
        float inv = 1.0f / sum;
        #pragma unroll
        for (int tk = 0; tk < Tv; tk++) row[tk] *= inv;
    }
    __syncthreads();
    if (tid < Hv*24) {
        int h = tid / 24, blk = tid % 24;
        int tq0 = (blk / 4) * 4, e0 = (blk % 4) * 4;
        float o[4][4] = {};
        #pragma unroll
        for (int tk = 0; tk < Tv; tk++) {
            float4 v4 = *(const float4*)&sv[tk*64 + h*HDv + e0];
            float va[4] = {v4.x, v4.y, v4.z, v4.w};
            float pa[4];
            #pragma unroll
            for (int i = 0; i < 4; i++) pa[i] = ss[(h*Tv + tq0 + i)*25 + tk];
            #pragma unroll
            for (int i = 0; i < 4; i++)
                #pragma unroll
                for (int j = 0; j < 4; j++)
                    o[i][j] = fmaf(pa[i], va[j], o[i][j]);
        }
        #pragma unroll
        for (int i = 0; i < 4; i++)
            *(float4*)&so[(tq0 + i)*64 + h*HDv + e0] =
                make_float4(o[i][0], o[i][1], o[i][2], o[i][3]);
    }
    __syncthreads();
    for (int i = tid; i < Tv*64; i += 256) {
        int t = i >> 6, d = i & 63;
        int gi = ((b*Tv + t)*Nv + n)*64 + d;
        bf16 h, l; sp2(so[i], h, l);
        g_atth[gi] = h; g_attl[gi] = l;
    }
}

// ---------------- attnout: att @ Wo + bo + x -> LN -> g_h (f32 + hi/lo) ----------------
__global__ __launch_bounds__(256) void k_attnout_mma(const float* __restrict__ x,
    const float* __restrict__ bo,
    const float* __restrict__ gt, const float* __restrict__ bt) {
    __shared__ __align__(16) char sm[SMEM_BYTES];
    int tid = threadIdx.x, lane = tid & 31, wid = tid >> 5;
    int wm = wid & 3, wn = wid >> 2;
    int r0g = blockIdx.x * 128;

    float acc[2][4][4] = {};
    #pragma unroll
    for (int kc = 0; kc < 2; kc++) {
        stage_A(sm, g_atth, g_attl, r0g, 64, kc*32, tid);
        stage_B(sm, g_Woh, g_Wol, 0, 64, 0, kc*32, tid);
        CP_COMMIT(); CP_WAIT0();
        __syncthreads();
        mma_compute(sm, acc, lane, wm, wn);
        __syncthreads();
    }
    float* sO = (float*)sm;
    int r = lane >> 2, cb = (lane & 3)*2;
    #pragma unroll
    for (int mi = 0; mi < 2; mi++)
        #pragma unroll
        for (int ni = 0; ni < 4; ni++) {
            int m = wm*32 + mi*16 + r;
            int n = wn*32 + ni*8 + cb;
            float b0 = bo[n], b1 = bo[n+1];
            float2 x0 = *(const float2*)&x[(r0g + m)*64 + n];
            float2 x1 = *(const float2*)&x[(r0g + m + 8)*64 + n];
            *(float2*)&sO[m*64 + n]     = make_float2(acc[mi][ni][0] + b0 + x0.x, acc[mi][ni][1] + b1 + x0.y);
            *(float2*)&sO[(m+8)*64 + n] = make_float2(acc[mi][ni][2] + b0 + x1.x, acc[mi][ni][3] + b1 + x1.y);
        }
    __syncthreads();
    ln256(sO, r0g, gt, bt, g_h, g_hh, g_hl);
}

// ---------------- prop: out = Ahat @ in (hi/lo -> hi/lo) ----------------
// Double-buffered cp.async pipeline; K-chunk 16, 32 stages.
// Per buffer (stride 16896): Ah 128x24 @0 (6144), Al @6144, Bh 16x72 @12288 (2304), Bl @14592.
__global__ __launch_bounds__(256) void k_prop_mma(int pass) {
    __shared__ __align__(16) char sm[2*16896];
    const bf16* __restrict__ inh = pass ? g_p1h : g_hh;
    const bf16* __restrict__ inl = pass ? g_p1l : g_hl;
    bf16* __restrict__ outh = pass ? g_p2h : g_p1h;
    bf16* __restrict__ outl = pass ? g_p2l : g_p1l;
    int tid = threadIdx.x, lane = tid & 31, wid = tid >> 5;
    int wm = wid & 3, wn = wid >> 2;
    int m0 = blockIdx.x * 128, bt = blockIdx.y;
    uint32_t sb = smem_u32(sm);

    // per-thread staging coords (fixed across stages)
    int sr = tid >> 1, sc16 = tid & 1;               // A: row, 16B-chunk
    int bk = (tid & 127) >> 3, bn8 = (tid & 7) * 8;  // B: k row, col chunk

    auto stage = [&](int kc, int b) {
        uint32_t base = sb + b*16896;
        int k0 = kc*16;
        int gi = (m0 + sr)*Nv + k0 + sc16*8;
        uint32_t so = base + (sr*24 + sc16*8)*2;
        CP16(so,        &g_Ahi[gi]);
        CP16(so + 6144, &g_Alo[gi]);
        int g2 = (bt*Nv + k0 + bk)*64 + bn8;
        if (tid < 128) CP16(base + 12288 + (bk*72 + bn8)*2, &inh[g2]);
        else           CP16(base + 14592 + (bk*72 + bn8)*2, &inl[g2]);
    };

    float acc[2][4][4] = {};
    int arow = wm*32 + (lane & 15);
    int acol = (lane >> 4) * 8;
    int brow = lane & 15;

    stage(0, 0); CP_COMMIT();
    for (int kc = 0; kc < 32; kc++) {
        if (kc + 1 < 32) { stage(kc+1, (kc+1)&1); CP_COMMIT(); CP_WAIT1(); }
        else             { CP_WAIT0(); }
        __syncthreads();
        uint32_t base = sb + (kc&1)*16896;
        uint32_t bAh = base, bAl = base + 6144;
        uint32_t bBh = base + 12288, bBl = base + 14592;
        uint32_t aH[2][4], aL[2][4], bH[4][2], bL[4][2];
        #pragma unroll
        for (int mi = 0; mi < 2; mi++) {
            uint32_t off = ((arow + mi*16)*24 + acol)*2;
            LDMX4(aH[mi], bAh + off);
            LDMX4(aL[mi], bAl + off);
        }
        #pragma unroll
        for (int ni = 0; ni < 4; ni++) {
            uint32_t off = (brow*72 + wn*32 + ni*8)*2;
            LDMX2T(bH[ni], bBh + off);
            LDMX2T(bL[ni], bBl + off);
        }
        #pragma unroll
        for (int mi = 0; mi < 2; mi++)
            #pragma unroll
            for (int ni = 0; ni < 4; ni++) {
                MMA_BF16(acc[mi][ni], aH[mi], bH[ni]);
                MMA_BF16(acc[mi][ni], aH[mi], bL[ni]);
                MMA_BF16(acc[mi][ni], aL[mi], bH[ni]);
            }
        __syncthreads();
    }
    int r = lane >> 2, cb = (lane & 3)*2;
    #pragma unroll
    for (int mi = 0; mi < 2; mi++)
        #pragma unroll
        for (int ni = 0; ni < 4; ni++) {
            int m = m0 + wm*32 + mi*16 + r;
            int n = wn*32 + ni*8 + cb;
            bf16 h0,l0,h1,l1,h2,l2,h3,l3;
            sp2(acc[mi][ni][0], h0, l0); sp2(acc[mi][ni][1], h1, l1);
            sp2(acc[mi][ni][2], h2, l2); sp2(acc[mi][ni][3], h3, l3);
            *(__nv_bfloat162*)&outh[(bt*Nv + m)*64 + n]     = __nv_bfloat162(h0, h1);
            *(__nv_bfloat162*)&outl[(bt*Nv + m)*64 + n]     = __nv_bfloat162(l0, l1);
            *(__nv_bfloat162*)&outh[(bt*Nv + m + 8)*64 + n] = __nv_bfloat162(h2, h3);
            *(__nv_bfloat162*)&outl[(bt*Nv + m + 8)*64 + n] = __nv_bfloat162(l2, l3);
        }
}

// ---------------- gc: h@W0 + p1@W1 + p2@W2 + bias + h -> LN -> g_h2 (f32 + hi/lo) ----
__global__ __launch_bounds__(256) void k_gc_mma(const float* __restrict__ gcb,
    const float* __restrict__ gg, const float* __restrict__ bg) {
    __shared__ __align__(16) char sm[SMEM_BYTES];
    int tid = threadIdx.x, lane = tid & 31, wid = tid >> 5;
    int wm = wid & 3, wn = wid >> 2;
    int r0g = blockIdx.x * 128;

    float acc[2][4][4] = {};
    const bf16* ih[3] = {g_hh, g_p1h, g_p2h};
    const bf16* il[3] = {g_hl, g_p1l, g_p2l};
    #pragma unroll
    for (int mm = 0; mm < 3; mm++)
        #pragma unroll
        for (int kc = 0; kc < 2; kc++) {
            stage_A(sm, ih[mm], il[mm], r0g, 64, kc*32, tid);
            stage_B(sm, g_gcWh + mm*4096, g_gcWl + mm*4096, 0, 64, 0, kc*32, tid);
            CP_COMMIT(); CP_WAIT0();
            __syncthreads();
            mma_compute(sm, acc, lane, wm, wn);
            __syncthreads();
        }
    float* sO = (float*)sm;
    int r = lane >> 2, cb = (lane & 3)*2;
    #pragma unroll
    for (int mi = 0; mi < 2; mi++)
        #pragma unroll
        for (int ni = 0; ni < 4; ni++) {
            int m = wm*32 + mi*16 + r;
            int n = wn*32 + ni*8 + cb;
            float b0 = gcb[n] + gcb[64+n] + gcb[128+n];
            float b1 = gcb[n+1] + gcb[64+n+1] + gcb[128+n+1];
            float2 h0 = *(const float2*)&g_h[(r0g + m)*64 + n];
            float2 h1 = *(const float2*)&g_h[(r0g + m + 8)*64 + n];
            *(float2*)&sO[m*64 + n]     = make_float2(acc[mi][ni][0] + b0 + h0.x, acc[mi][ni][1] + b1 + h0.y);
            *(float2*)&sO[(m+8)*64 + n] = make_float2(acc[mi][ni][2] + b0 + h1.x, acc[mi][ni][3] + b1 + h1.y);
        }
    __syncthreads();
    ln256(sO, r0g, gg, bg, g_h2, g_h2h, g_h2l);
}

// ---------------- ffn1: gelu(h2 @ W1 + b1) -> u hi/lo ----------------
__global__ __launch_bounds__(256) void k_ffn1_mma(const float* __restrict__ b1) {
    __shared__ __align__(16) char sm[SMEM_BYTES];
    int tid = threadIdx.x, lane = tid & 31, wid = tid >> 5;
    int wm = wid & 3, wn = wid >> 2;
    int r0g = blockIdx.x * 128;
    int c0g = blockIdx.y * 64;

    float acc[2][4][4] = {};
    #pragma unroll
    for (int kc = 0; kc < 2; kc++) {
        stage_A(sm, g_h2h, g_h2l, r0g, 64, kc*32, tid);
        stage_B(sm, g_W1h, g_W1l, 0, Fv, c0g, kc*32, tid);
        CP_COMMIT(); CP_WAIT0();
        __syncthreads();
        mma_compute(sm, acc, lane, wm, wn);
        __syncthreads();
    }
    int r = lane >> 2, cb = (lane & 3)*2;
    #pragma unroll
    for (int mi = 0; mi < 2; mi++)
        #pragma unroll
        for (int ni = 0; ni < 4; ni++) {
            int m = r0g + wm*32 + mi*16 + r;
            int n = wn*32 + ni*8 + cb;
            float b0 = b1[c0g + n], b1v = b1[c0g + n + 1];
            float v[4] = {acc[mi][ni][0] + b0, acc[mi][ni][1] + b1v,
                          acc[mi][ni][2] + b0, acc[mi][ni][3] + b1v};
            #pragma unroll
            for (int j = 0; j < 4; j++)
                v[j] = 0.5f * v[j] * (1.0f + erff(v[j] * 0.70710678118654752f));
            bf16 h0,l0,h1,l1,h2,l2,h3,l3;
            sp2(v[0],h0,l0); sp2(v[1],h1,l1); sp2(v[2],h2,l2); sp2(v[3],h3,l3);
            *(__nv_bfloat162*)&g_uh[m*Fv + c0g + n]     = __nv_bfloat162(h0, h1);
            *(__nv_bfloat162*)&g_ul[m*Fv + c0g + n]     = __nv_bfloat162(l0, l1);
            *(__nv_bfloat162*)&g_uh[(m+8)*Fv + c0g + n] = __nv_bfloat162(h2, h3);
            *(__nv_bfloat162*)&g_ul[(m+8)*Fv + c0g + n] = __nv_bfloat162(l2, l3);
        }
}

// ---------------- ffn2: u @ W2 + b2 + h2 -> LN -> out ----------------
__global__ __launch_bounds__(256) void k_ffn2_mma(const float* __restrict__ b2,
    const float* __restrict__ gf, const float* __restrict__ bf,
    float* __restrict__ out) {
    __shared__ __align__(16) char sm[SMEM_BYTES];
    int tid = threadIdx.x, lane = tid & 31, wid = tid >> 5;
    int wm = wid & 3, wn = wid >> 2;
    int r0g = blockIdx.x * 128;

    float acc[2][4][4] = {};
    #pragma unroll
    for (int kc = 0; kc < 8; kc++) {
        stage_A(sm, g_uh, g_ul, r0g, Fv, kc*32, tid);
        stage_B(sm, g_W2h, g_W2l, 0, 64, 0, kc*32, tid);
        CP_COMMIT(); CP_WAIT0();
        __syncthreads();
        mma_compute(sm, acc, lane, wm, wn);
        __syncthreads();
    }
    float* sO = (float*)sm;
    int r = lane >> 2, cb = (lane & 3)*2;
    #pragma unroll
    for (int mi = 0; mi < 2; mi++)
        #pragma unroll
        for (int ni = 0; ni < 4; ni++) {
            int m = wm*32 + mi*16 + r;
            int n = wn*32 + ni*8 + cb;
            float b0 = b2[n], b1 = b2[n+1];
            float2 h0 = *(const float2*)&g_h2[(r0g + m)*64 + n];
            float2 h1 = *(const float2*)&g_h2[(r0g + m + 8)*64 + n];
            *(float2*)&sO[m*64 + n]     = make_float2(acc[mi][ni][0] + b0 + h0.x, acc[mi][ni][1] + b1 + h0.y);
            *(float2*)&sO[(m+8)*64 + n] = make_float2(acc[mi][ni][2] + b0 + h1.x, acc[mi][ni][3] + b1 + h1.y);
        }
    __syncthreads();
    ln256(sO, r0g, gf, bf, out, (bf16*)0, (bf16*)0);
}

// ---------------- launch ----------------
extern "C" void kernel_launch(void* const* d_in, const int* in_sizes, int n_in,
                              void* d_out, int out_size) {
    const float* x   = (const float*)d_in[0];
    const float* adj = (const float*)d_in[1];
    const float* bq  = (const float*)d_in[3];
    const float* bk  = (const float*)d_in[5];
    const float* bv  = (const float*)d_in[7];
    const float* bo  = (const float*)d_in[9];
    const float* gcb = (const float*)d_in[11];
    const float* b1  = (const float*)d_in[13];
    const float* b2  = (const float*)d_in[15];
    const float* g_t = (const float*)d_in[16];
    const float* b_t = (const float*)d_in[17];
    const float* g_g = (const float*)d_in[18];
    const float* b_g = (const float*)d_in[19];
    const float* g_f = (const float*)d_in[20];
    const float* b_f = (const float*)d_in[21];
    float* out = (float*)d_out;

    k_deg   <<<Nv, 128>>>(adj);
    k_ahat  <<<(Nv*Nv)/512, 512>>>(adj);
    k_splitx<<<(BTNv*Dv)/1024, 256>>>(x);
    k_splitw<<<240, 256>>>((const float*)d_in[2], (const float*)d_in[4],
                           (const float*)d_in[6], (const float*)d_in[8],
                           (const float*)d_in[10], (const float*)d_in[12],
                           (const float*)d_in[14]);
    k_qkv_mma<<<dim3(RT128, 3), 256>>>(bq, bk, bv);
    k_attn  <<<dim3(Nv, Bv), 256>>>();
    k_attnout_mma<<<RT128, 256>>>(x, bo, g_t, b_t);
    k_prop_mma<<<dim3(Nv/128, BTv), 256>>>(0);
    k_prop_mma<<<dim3(Nv/128, BTv), 256>>>(1);
    k_gc_mma<<<RT128, 256>>>(gcb, g_g, b_g);
    k_ffn1_mma<<<dim3(RT128, Fv/64), 256>>>(b1);
    k_ffn2_mma<<<RT128, 256>>>(b2, g_f, b_f, out);
}

// round 13
// speedup vs baseline: 2.4206x; 1.0393x over previous
#include <cuda_runtime.h>
#include <cuda_bf16.h>
#include <math.h>
#include <cstdint>

#define Bv   16
#define Tv   24
#define Nv   512
#define Dv   64
#define Hv   4
#define HDv  16
#define Fv   256
#define BTv  (Bv*Tv)           // 384
#define BTNv (BTv*Nv)          // 196608
#define RT128 (BTNv/128)       // 1536

typedef unsigned long long ull;
typedef __nv_bfloat16 bf16;

// ---------------- scratch (static device globals; no allocation) ----------------
__device__ float g_dinv[Nv];
__device__ float g_q  [BTNv*Dv];
__device__ float g_k  [BTNv*Dv];
__device__ float g_v  [BTNv*Dv];
__device__ float g_h  [BTNv*Dv];
__device__ float g_h2 [BTNv*Dv];
// bf16 hi/lo pairs
__device__ bf16 g_Ahi[Nv*Nv],     g_Alo[Nv*Nv];
__device__ bf16 g_A2h[Nv*Nv],     g_A2l[Nv*Nv];
__device__ bf16 g_xh [BTNv*Dv],   g_xl [BTNv*Dv];
__device__ bf16 g_atth[BTNv*Dv],  g_attl[BTNv*Dv];
__device__ bf16 g_hh [BTNv*Dv],   g_hl [BTNv*Dv];
__device__ bf16 g_p1h[BTNv*Dv],   g_p1l[BTNv*Dv];
__device__ bf16 g_p2h[BTNv*Dv],   g_p2l[BTNv*Dv];
__device__ bf16 g_h2h[BTNv*Dv],   g_h2l[BTNv*Dv];
__device__ bf16 g_uh [BTNv*Fv],   g_ul [BTNv*Fv];
// weight splits
__device__ bf16 g_Wqh[4096], g_Wql[4096];
__device__ bf16 g_Wkh[4096], g_Wkl[4096];
__device__ bf16 g_Wvh[4096], g_Wvl[4096];
__device__ bf16 g_Woh[4096], g_Wol[4096];
__device__ bf16 g_gcWh[3*4096], g_gcWl[3*4096];
__device__ bf16 g_W1h[64*Fv], g_W1l[64*Fv];
__device__ bf16 g_W2h[Fv*64], g_W2l[Fv*64];

// ================= mma.sync / cp.async helpers =================
__device__ __forceinline__ uint32_t smem_u32(const void* p) {
    uint32_t a;
    asm("{ .reg .u64 t; cvta.to.shared.u64 t, %1; cvt.u32.u64 %0, t; }" : "=r"(a) : "l"(p));
    return a;
}
#define LDMX4(r, addr) \
    asm volatile("ldmatrix.sync.aligned.m8n8.x4.shared.b16 {%0,%1,%2,%3}, [%4];" \
        : "=r"((r)[0]), "=r"((r)[1]), "=r"((r)[2]), "=r"((r)[3]) : "r"(addr))
#define LDMX4T(r, addr) \
    asm volatile("ldmatrix.sync.aligned.m8n8.x4.trans.shared.b16 {%0,%1,%2,%3}, [%4];" \
        : "=r"((r)[0]), "=r"((r)[1]), "=r"((r)[2]), "=r"((r)[3]) : "r"(addr))
#define LDMX2T(r, addr) \
    asm volatile("ldmatrix.sync.aligned.m8n8.x2.trans.shared.b16 {%0,%1}, [%2];" \
        : "=r"((r)[0]), "=r"((r)[1]) : "r"(addr))
#define MMA_BF16(d, a, b) \
    asm volatile("mma.sync.aligned.m16n8k16.row.col.f32.bf16.bf16.f32 " \
        "{%0,%1,%2,%3}, {%4,%5,%6,%7}, {%8,%9}, {%0,%1,%2,%3};" \
        : "+f"((d)[0]), "+f"((d)[1]), "+f"((d)[2]), "+f"((d)[3]) \
        : "r"((a)[0]), "r"((a)[1]), "r"((a)[2]), "r"((a)[3]), \
          "r"((b)[0]), "r"((b)[1]))
#define CP16(saddr, gptr) \
    asm volatile("cp.async.ca.shared.global [%0], [%1], 16;" :: "r"(saddr), "l"(gptr))
#define CP_COMMIT() asm volatile("cp.async.commit_group;" ::: "memory")
#define CP_WAIT0()  asm volatile("cp.async.wait_group 0;" ::: "memory")
#define CP_WAIT1()  asm volatile("cp.async.wait_group 1;" ::: "memory")

__device__ __forceinline__ void sp2(float x, bf16& h, bf16& l) {
    h = __float2bfloat16(x);
    l = __float2bfloat16(x - __bfloat162float(h));
}

// ---- generic-kernel smem layout (aliased staging / f32 tile) ----
// sAh [128*40] @0 (10240) | sAl @10240 | sBh [32*72] @20480 (4608) | sBl @25088
// sO  [128*64] f32 @0 (32768) -- only after staging dead
#define SMEM_BYTES 33280

__device__ __forceinline__ void stage_A(char* sm, const bf16* __restrict__ gh,
                                        const bf16* __restrict__ gl,
                                        int rowBase, int ldA, int k0, int tid) {
    uint32_t sAh = smem_u32(sm);
    uint32_t sAl = sAh + 10240;
    #pragma unroll
    for (int i = tid; i < 512; i += 256) {
        int r = i >> 2, c8 = (i & 3) * 8;
        int gi = (rowBase + r)*ldA + k0 + c8;
        uint32_t off = (r*40 + c8)*2;
        CP16(sAh + off, &gh[gi]);
        CP16(sAl + off, &gl[gi]);
    }
}
__device__ __forceinline__ void stage_B(char* sm, const bf16* __restrict__ gh,
                                        const bf16* __restrict__ gl,
                                        int rowBase, int ldB, int colBase, int k0, int tid) {
    uint32_t sBh = smem_u32(sm) + 20480;
    uint32_t sBl = sBh + 4608;
    int k = tid >> 3, n8 = (tid & 7) * 8;
    int gi = (rowBase + k0 + k)*ldB + colBase + n8;
    uint32_t off = (k*72 + n8)*2;
    CP16(sBh + off, &gh[gi]);
    CP16(sBl + off, &gl[gi]);
}

__device__ __forceinline__ void mma_compute(char* sm, float acc[2][4][4],
                                            int lane, int wm, int wn) {
    uint32_t baseAh = smem_u32(sm), baseAl = smem_u32(sm + 10240);
    uint32_t baseBh = smem_u32(sm + 20480), baseBl = smem_u32(sm + 25088);
    int arow = wm*32 + (lane & 15);
    int acolL = (lane >> 4) * 8;
    int brow = lane & 15;
    int bcol = wn*32;
    #pragma unroll
    for (int ks = 0; ks < 2; ks++) {
        uint32_t aH[2][4], aL[2][4], bH[4][2], bL[4][2];
        int acol = ks*16 + acolL;
        #pragma unroll
        for (int mi = 0; mi < 2; mi++) {
            uint32_t off = ((arow + mi*16)*40 + acol)*2;
            LDMX4(aH[mi], baseAh + off);
            LDMX4(aL[mi], baseAl + off);
        }
        #pragma unroll
        for (int ni = 0; ni < 4; ni++) {
            uint32_t off = ((ks*16 + brow)*72 + bcol + ni*8)*2;
            LDMX2T(bH[ni], baseBh + off);
            LDMX2T(bL[ni], baseBl + off);
        }
        #pragma unroll
        for (int mi = 0; mi < 2; mi++)
            #pragma unroll
            for (int ni = 0; ni < 4; ni++) {
                MMA_BF16(acc[mi][ni], aH[mi], bH[ni]);
                MMA_BF16(acc[mi][ni], aH[mi], bL[ni]);
                MMA_BF16(acc[mi][ni], aL[mi], bH[ni]);
            }
    }
}

// 256-thread LN over sO[128][64]
__device__ __forceinline__ void ln256(const float* sO, int r0g,
                                      const float* __restrict__ g,
                                      const float* __restrict__ b,
                                      float* outf, bf16* outh, bf16* outl) {
    int wid = threadIdx.x >> 5, lane = threadIdx.x & 31;
    float gg0 = g[lane], gg1 = g[lane + 32];
    float bb0 = b[lane], bb1 = b[lane + 32];
    for (int r = wid; r < 128; r += 8) {
        float v0 = sO[r*64 + lane];
        float v1 = sO[r*64 + lane + 32];
        float s = v0 + v1;
        #pragma unroll
        for (int o = 16; o; o >>= 1) s += __shfl_xor_sync(0xffffffffu, s, o);
        float m = s * (1.0f/64.0f);
        float d0 = v0 - m, d1 = v1 - m;
        float vs = d0*d0 + d1*d1;
        #pragma unroll
        for (int o = 16; o; o >>= 1) vs += __shfl_xor_sync(0xffffffffu, vs, o);
        float rs = rsqrtf(vs * (1.0f/64.0f) + 1e-5f);
        float o0 = d0*rs*gg0 + bb0;
        float o1 = d1*rs*gg1 + bb1;
        int gi0 = (r0g + r)*64 + lane, gi1 = gi0 + 32;
        if (outf) { outf[gi0] = o0; outf[gi1] = o1; }
        if (outh) {
            bf16 h0, l0, h1, l1;
            sp2(o0, h0, l0); sp2(o1, h1, l1);
            outh[gi0] = h0; outl[gi0] = l0;
            outh[gi1] = h1; outl[gi1] = l1;
        }
    }
}

// ---------------- graph normalization ----------------
__global__ __launch_bounds__(128) void k_deg(const float* __restrict__ adj) {
    __shared__ float red[128];
    int m = blockIdx.x;
    float s = 0.f;
    for (int j = threadIdx.x; j < Nv; j += 128) s += adj[m*Nv + j];
    red[threadIdx.x] = s; __syncthreads();
    for (int o = 64; o; o >>= 1) {
        if (threadIdx.x < o) red[threadIdx.x] += red[threadIdx.x + o];
        __syncthreads();
    }
    if (threadIdx.x == 0) g_dinv[m] = rsqrtf(fmaxf(red[0] + 1.0f, 1e-12f));
}

__global__ __launch_bounds__(512) void k_ahat(const float* __restrict__ adj) {
    int i = blockIdx.x * 512 + threadIdx.x;
    int m = i >> 9, n = i & 511;
    float a = adj[i] + (m == n ? 1.0f : 0.0f);
    float v = g_dinv[m] * a * g_dinv[n];
    bf16 h, l; sp2(v, h, l);
    g_Ahi[i] = h; g_Alo[i] = l;
}

// ========== N=128 prop-style pipeline machinery ==========
// Per buffer (stride 20992): Ah 128x16 s24 @0 (6144) | Al @6144 | Bh 16x128 s136 @12288 (4352) | Bl @16640

// ---------------- A2 = Ahat @ Ahat (hi/lo in, f32->hi/lo out) ----------------
__global__ __launch_bounds__(256, 2) void k_asq() {
    __shared__ __align__(16) char sm[2*20992];
    int tid = threadIdx.x, lane = tid & 31, wid = tid >> 5;
    int wm = wid & 3, wn = wid >> 2;
    int m0 = blockIdx.x * 128, n0 = blockIdx.y * 128;
    uint32_t sb = smem_u32(sm);
    int sr = tid >> 1, sc = (tid & 1)*8;
    int bk = tid >> 4, bn = (tid & 15)*8;

    auto stage = [&](int kc, int b) {
        uint32_t base = sb + b*20992;
        int k0 = kc*16;
        uint32_t ao = base + (sr*24 + sc)*2;
        CP16(ao,        &g_Ahi[(m0 + sr)*Nv + k0 + sc]);
        CP16(ao + 6144, &g_Alo[(m0 + sr)*Nv + k0 + sc]);
        int g2 = (k0 + bk)*Nv + n0 + bn;
        uint32_t bo = base + 12288 + (bk*136 + bn)*2;
        CP16(bo,        &g_Ahi[g2]);
        CP16(bo + 4352, &g_Alo[g2]);
    };

    float acc[2][8][4] = {};
    int arow = wm*32 + (lane & 15), acol = (lane >> 4)*8;
    int brow = lane & 15, bsel = (lane >> 4)*8;

    stage(0, 0); CP_COMMIT();
    for (int kc = 0; kc < 32; kc++) {
        if (kc + 1 < 32) { stage(kc+1, (kc+1)&1); CP_COMMIT(); CP_WAIT1(); }
        else             { CP_WAIT0(); }
        __syncthreads();
        uint32_t base = sb + (kc&1)*20992;
        uint32_t aH[2][4], aL[2][4], bH[4][4], bL[4][4];
        #pragma unroll
        for (int mi = 0; mi < 2; mi++) {
            uint32_t off = ((arow + mi*16)*24 + acol)*2;
            LDMX4(aH[mi], base + off);
            LDMX4(aL[mi], base + 6144 + off);
        }
        #pragma unroll
        for (int nj = 0; nj < 4; nj++) {
            uint32_t off = (brow*136 + wn*64 + nj*16 + bsel)*2;
            LDMX4T(bH[nj], base + 12288 + off);
            LDMX4T(bL[nj], base + 16640 + off);
        }
        #pragma unroll
        for (int mi = 0; mi < 2; mi++)
            #pragma unroll
            for (int ni = 0; ni < 8; ni++) {
                MMA_BF16(acc[mi][ni], aH[mi], &bH[ni>>1][(ni&1)*2]);
                MMA_BF16(acc[mi][ni], aH[mi], &bL[ni>>1][(ni&1)*2]);
                MMA_BF16(acc[mi][ni], aL[mi], &bH[ni>>1][(ni&1)*2]);
            }
        __syncthreads();
    }
    int r = lane >> 2, cb = (lane & 3)*2;
    #pragma unroll
    for (int mi = 0; mi < 2; mi++)
        #pragma unroll
        for (int ni = 0; ni < 8; ni++) {
            int m = m0 + wm*32 + mi*16 + r;
            int n = n0 + wn*64 + ni*8 + cb;
            bf16 h0,l0,h1,l1,h2,l2,h3,l3;
            sp2(acc[mi][ni][0], h0, l0); sp2(acc[mi][ni][1], h1, l1);
            sp2(acc[mi][ni][2], h2, l2); sp2(acc[mi][ni][3], h3, l3);
            *(__nv_bfloat162*)&g_A2h[m*Nv + n]     = __nv_bfloat162(h0, h1);
            *(__nv_bfloat162*)&g_A2l[m*Nv + n]     = __nv_bfloat162(l0, l1);
            *(__nv_bfloat162*)&g_A2h[(m+8)*Nv + n] = __nv_bfloat162(h2, h3);
            *(__nv_bfloat162*)&g_A2l[(m+8)*Nv + n] = __nv_bfloat162(l2, l3);
        }
}

// ---------------- input / weight splits ----------------
__global__ __launch_bounds__(256) void k_splitx(const float* __restrict__ x) {
    int i = (blockIdx.x * 256 + threadIdx.x) * 4;
    float4 v = *(const float4*)&x[i];
    bf16 h0,h1,h2,h3,l0,l1,l2,l3;
    sp2(v.x,h0,l0); sp2(v.y,h1,l1); sp2(v.z,h2,l2); sp2(v.w,h3,l3);
    *(__nv_bfloat162*)&g_xh[i]   = __nv_bfloat162(h0,h1);
    *(__nv_bfloat162*)&g_xh[i+2] = __nv_bfloat162(h2,h3);
    *(__nv_bfloat162*)&g_xl[i]   = __nv_bfloat162(l0,l1);
    *(__nv_bfloat162*)&g_xl[i+2] = __nv_bfloat162(l2,l3);
}

__global__ __launch_bounds__(256) void k_splitw(
    const float* __restrict__ Wq, const float* __restrict__ Wk,
    const float* __restrict__ Wv, const float* __restrict__ Wo,
    const float* __restrict__ gcW, const float* __restrict__ W1,
    const float* __restrict__ W2) {
    int i = blockIdx.x * 256 + threadIdx.x;
    const float* src; bf16 *dh, *dl; int off;
    if      (i < 4096)  { src = Wq;  dh = g_Wqh;  dl = g_Wql;  off = i; }
    else if (i < 8192)  { src = Wk;  dh = g_Wkh;  dl = g_Wkl;  off = i - 4096; }
    else if (i < 12288) { src = Wv;  dh = g_Wvh;  dl = g_Wvl;  off = i - 8192; }
    else if (i < 16384) { src = Wo;  dh = g_Woh;  dl = g_Wol;  off = i - 12288; }
    else if (i < 28672) { src = gcW; dh = g_gcWh; dl = g_gcWl; off = i - 16384; }
    else if (i < 45056) { src = W1;  dh = g_W1h;  dl = g_W1l;  off = i - 28672; }
    else if (i < 61440) { src = W2;  dh = g_W2h;  dl = g_W2l;  off = i - 45056; }
    else return;
    bf16 h, l; sp2(src[off], h, l);
    dh[off] = h; dl[off] = l;
}

// ---------------- merged QKV: x @ {Wq,Wk,Wv} + bias -> f32 q/k/v ----------------
// smem: A (generic, 20480) + 3 B sets of 9216 @20480 = 48128 bytes
__global__ __launch_bounds__(256) void k_qkv_mma(const float* __restrict__ bq,
                                                 const float* __restrict__ bk,
                                                 const float* __restrict__ bv) {
    __shared__ __align__(16) char sm[48128];
    int tid = threadIdx.x, lane = tid & 31, wid = tid >> 5;
    int wm = wid & 3, wn = wid >> 2;
    int r0g = blockIdx.x * 128;
    uint32_t sb = smem_u32(sm);

    const bf16* Wh[3] = {g_Wqh, g_Wkh, g_Wvh};
    const bf16* Wl[3] = {g_Wql, g_Wkl, g_Wvl};
    const float* bias[3] = {bq, bk, bv};
    float* outp[3] = {g_q, g_k, g_v};

    float acc[3][2][4][4] = {};
    int arow = wm*32 + (lane & 15);
    int acolL = (lane >> 4)*8;
    int brow = lane & 15, bsel = (lane >> 4)*8;

    #pragma unroll
    for (int kc = 0; kc < 2; kc++) {
        stage_A(sm, g_xh, g_xl, r0g, 64, kc*32, tid);
        {
            int k = tid >> 3, n8 = (tid & 7)*8;
            #pragma unroll
            for (int s = 0; s < 3; s++) {
                uint32_t bo = sb + 20480 + s*9216 + (k*72 + n8)*2;
                int gi = (kc*32 + k)*64 + n8;
                CP16(bo,        &Wh[s][gi]);
                CP16(bo + 4608, &Wl[s][gi]);
            }
        }
        CP_COMMIT(); CP_WAIT0();
        __syncthreads();
        #pragma unroll
        for (int ks = 0; ks < 2; ks++) {
            uint32_t aH[2][4], aL[2][4];
            int acol = ks*16 + acolL;
            #pragma unroll
            for (int mi = 0; mi < 2; mi++) {
                uint32_t off = ((arow + mi*16)*40 + acol)*2;
                LDMX4(aH[mi], sb + off);
                LDMX4(aL[mi], sb + 10240 + off);
            }
            #pragma unroll
            for (int s = 0; s < 3; s++) {
                uint32_t bH[2][4], bL[2][4];
                #pragma unroll
                for (int nj = 0; nj < 2; nj++) {
                    uint32_t off = ((ks*16 + brow)*72 + wn*32 + nj*16 + bsel)*2;
                    LDMX4T(bH[nj], sb + 20480 + s*9216 + off);
                    LDMX4T(bL[nj], sb + 20480 + s*9216 + 4608 + off);
                }
                #pragma unroll
                for (int mi = 0; mi < 2; mi++)
                    #pragma unroll
                    for (int ni = 0; ni < 4; ni++) {
                        MMA_BF16(acc[s][mi][ni], aH[mi], &bH[ni>>1][(ni&1)*2]);
                        MMA_BF16(acc[s][mi][ni], aH[mi], &bL[ni>>1][(ni&1)*2]);
                        MMA_BF16(acc[s][mi][ni], aL[mi], &bH[ni>>1][(ni&1)*2]);
                    }
            }
        }
        __syncthreads();
    }
    int r = lane >> 2, cb = (lane & 3)*2;
    #pragma unroll
    for (int s = 0; s < 3; s++)
        #pragma unroll
        for (int mi = 0; mi < 2; mi++)
            #pragma unroll
            for (int ni = 0; ni < 4; ni++) {
                int m = r0g + wm*32 + mi*16 + r;
                int n = wn*32 + ni*8 + cb;
                float b0 = bias[s][n], b1 = bias[s][n+1];
                *(float2*)&outp[s][m*64 + n]     = make_float2(acc[s][mi][ni][0] + b0, acc[s][mi][ni][1] + b1);
                *(float2*)&outp[s][(m+8)*64 + n] = make_float2(acc[s][mi][ni][2] + b0, acc[s][mi][ni][3] + b1);
            }
}

// ---------------- temporal attention -> att hi/lo ----------------
__global__ __launch_bounds__(256) void k_attn() {
    __shared__ __align__(16) float sqT[64*28];
    __shared__ __align__(16) float skT[64*28];
    __shared__ __align__(16) float sv[Tv*64];
    __shared__ __align__(16) float so[Tv*64];
    __shared__ __align__(16) float ss[Hv*Tv*25];
    int tid = threadIdx.x;
    int n = blockIdx.x, b = blockIdx.y;
    for (int i = tid; i < Tv*64; i += 256) {
        int t = i >> 6, d = i & 63;
        int gidx = ((b*Tv + t)*Nv + n)*64 + d;
        sqT[d*28 + t] = g_q[gidx];
        skT[d*28 + t] = g_k[gidx];
        sv[i]         = g_v[gidx];
    }
    __syncthreads();
    if (tid < Hv*36) {
        int h = tid / 36, blk = tid % 36;
        int tq0 = (blk / 6) * 4, tk0 = (blk % 6) * 4;
        float s[4][4] = {};
        const float* qb = &sqT[h*HDv*28];
        const float* kb = &skT[h*HDv*28];
        #pragma unroll
        for (int e = 0; e < HDv; e++) {
            float4 q4 = *(const float4*)(qb + e*28 + tq0);
            float4 k4 = *(const float4*)(kb + e*28 + tk0);
            float qa[4] = {q4.x, q4.y, q4.z, q4.w};
            float ka[4] = {k4.x, k4.y, k4.z, k4.w};
            #pragma unroll
            for (int i = 0; i < 4; i++)
                #pragma unroll
                for (int j = 0; j < 4; j++)
                    s[i][j] = fmaf(qa[i], ka[j], s[i][j]);
        }
        #pragma unroll
        for (int i = 0; i < 4; i++)
            #pragma unroll
            for (int j = 0; j < 4; j++)
                ss[(h*Tv + tq0 + i)*25 + tk0 + j] = s[i][j] * 0.25f;
    }
    __syncthreads();
    if (tid < Hv*Tv) {
        float* row = &ss[tid*25];
        float mx = -1e30f;
        #pragma unroll
        for (int tk = 0; tk < Tv; tk++) mx = fmaxf(mx, row[tk]);
        float sum = 0.f;
        #pragma unroll
        for (int tk = 0; tk < Tv; tk++) { float e = expf(row[tk]-mx); row[tk] = e; sum += e; }
        float inv = 1.0f / sum;
        #pragma unroll
        for (int tk = 0; tk < Tv; tk++) row[tk] *= inv;
    }
    __syncthreads();
    if (tid < Hv*24) {
        int h = tid / 24, blk = tid % 24;
        int tq0 = (blk / 4) * 4, e0 = (blk % 4) * 4;
        float o[4][4] = {};
        #pragma unroll
        for (int tk = 0; tk < Tv; tk++) {
            float4 v4 = *(const float4*)&sv[tk*64 + h*HDv + e0];
            float va[4] = {v4.x, v4.y, v4.z, v4.w};
            float pa[4];
            #pragma unroll
            for (int i = 0; i < 4; i++) pa[i] = ss[(h*Tv + tq0 + i)*25 + tk];
            #pragma unroll
            for (int i = 0; i < 4; i++)
                #pragma unroll
                for (int j = 0; j < 4; j++)
                    o[i][j] = fmaf(pa[i], va[j], o[i][j]);
        }
        #pragma unroll
        for (int i = 0; i < 4; i++)
            *(float4*)&so[(tq0 + i)*64 + h*HDv + e0] =
                make_float4(o[i][0], o[i][1], o[i][2], o[i][3]);
    }
    __syncthreads();
    for (int i = tid; i < Tv*64; i += 256) {
        int t = i >> 6, d = i & 63;
        int gi = ((b*Tv + t)*Nv + n)*64 + d;
        bf16 h, l; sp2(so[i], h, l);
        g_atth[gi] = h; g_attl[gi] = l;
    }
}

// ---------------- attnout: att @ Wo + bo + x -> LN -> g_h (f32 + hi/lo) ----------------
__global__ __launch_bounds__(256) void k_attnout_mma(const float* __restrict__ x,
    const float* __restrict__ bo,
    const float* __restrict__ gt, const float* __restrict__ bt) {
    __shared__ __align__(16) char sm[SMEM_BYTES];
    int tid = threadIdx.x, lane = tid & 31, wid = tid >> 5;
    int wm = wid & 3, wn = wid >> 2;
    int r0g = blockIdx.x * 128;

    float acc[2][4][4] = {};
    #pragma unroll
    for (int kc = 0; kc < 2; kc++) {
        stage_A(sm, g_atth, g_attl, r0g, 64, kc*32, tid);
        stage_B(sm, g_Woh, g_Wol, 0, 64, 0, kc*32, tid);
        CP_COMMIT(); CP_WAIT0();
        __syncthreads();
        mma_compute(sm, acc, lane, wm, wn);
        __syncthreads();
    }
    float* sO = (float*)sm;
    int r = lane >> 2, cb = (lane & 3)*2;
    #pragma unroll
    for (int mi = 0; mi < 2; mi++)
        #pragma unroll
        for (int ni = 0; ni < 4; ni++) {
            int m = wm*32 + mi*16 + r;
            int n = wn*32 + ni*8 + cb;
            float b0 = bo[n], b1 = bo[n+1];
            float2 x0 = *(const float2*)&x[(r0g + m)*64 + n];
            float2 x1 = *(const float2*)&x[(r0g + m + 8)*64 + n];
            *(float2*)&sO[m*64 + n]     = make_float2(acc[mi][ni][0] + b0 + x0.x, acc[mi][ni][1] + b1 + x0.y);
            *(float2*)&sO[(m+8)*64 + n] = make_float2(acc[mi][ni][2] + b0 + x1.x, acc[mi][ni][3] + b1 + x1.y);
        }
    __syncthreads();
    ln256(sO, r0g, gt, bt, g_h, g_hh, g_hl);
}

// ---------------- prop2: p1 = Ahat@h, p2 = A2@h in one launch ----------------
// grid (8, 192): blockIdx.x 0-3 -> Ahat m-tiles, 4-7 -> A2 m-tiles; N=128 = two bt.
__global__ __launch_bounds__(256, 2) void k_prop2() {
    __shared__ __align__(16) char sm[2*20992];
    int tid = threadIdx.x, lane = tid & 31, wid = tid >> 5;
    int wm = wid & 3, wn = wid >> 2;
    int my = blockIdx.x, btp = blockIdx.y;
    const bf16* __restrict__ Ah_ = my < 4 ? g_Ahi : g_A2h;
    const bf16* __restrict__ Al_ = my < 4 ? g_Alo : g_A2l;
    bf16* __restrict__ outh = my < 4 ? g_p1h : g_p2h;
    bf16* __restrict__ outl = my < 4 ? g_p1l : g_p2l;
    int m0 = (my & 3) * 128;
    uint32_t sb = smem_u32(sm);

    int sr = tid >> 1, sc = (tid & 1)*8;
    int bk = tid >> 4, bn = (tid & 15)*8;
    int bth = bn >> 6, bd = bn & 63;

    auto stage = [&](int kc, int b) {
        uint32_t base = sb + b*20992;
        int k0 = kc*16;
        uint32_t ao = base + (sr*24 + sc)*2;
        CP16(ao,        &Ah_[(m0 + sr)*Nv + k0 + sc]);
        CP16(ao + 6144, &Al_[(m0 + sr)*Nv + k0 + sc]);
        int g2 = ((btp*2 + bth)*Nv + k0 + bk)*64 + bd;
        uint32_t bo = base + 12288 + (bk*136 + bn)*2;
        CP16(bo,        &g_hh[g2]);
        CP16(bo + 4352, &g_hl[g2]);
    };

    float acc[2][8][4] = {};
    int arow = wm*32 + (lane & 15), acol = (lane >> 4)*8;
    int brow = lane & 15, bsel = (lane >> 4)*8;

    stage(0, 0); CP_COMMIT();
    for (int kc = 0; kc < 32; kc++) {
        if (kc + 1 < 32) { stage(kc+1, (kc+1)&1); CP_COMMIT(); CP_WAIT1(); }
        else             { CP_WAIT0(); }
        __syncthreads();
        uint32_t base = sb + (kc&1)*20992;
        uint32_t aH[2][4], aL[2][4], bH[4][4], bL[4][4];
        #pragma unroll
        for (int mi = 0; mi < 2; mi++) {
            uint32_t off = ((arow + mi*16)*24 + acol)*2;
            LDMX4(aH[mi], base + off);
            LDMX4(aL[mi], base + 6144 + off);
        }
        #pragma unroll
        for (int nj = 0; nj < 4; nj++) {
            uint32_t off = (brow*136 + wn*64 + nj*16 + bsel)*2;
            LDMX4T(bH[nj], base + 12288 + off);
            LDMX4T(bL[nj], base + 16640 + off);
        }
        #pragma unroll
        for (int mi = 0; mi < 2; mi++)
            #pragma unroll
            for (int ni = 0; ni < 8; ni++) {
                MMA_BF16(acc[mi][ni], aH[mi], &bH[ni>>1][(ni&1)*2]);
                MMA_BF16(acc[mi][ni], aH[mi], &bL[ni>>1][(ni&1)*2]);
                MMA_BF16(acc[mi][ni], aL[mi], &bH[ni>>1][(ni&1)*2]);
            }
        __syncthreads();
    }
    int r = lane >> 2, cb = (lane & 3)*2;
    #pragma unroll
    for (int mi = 0; mi < 2; mi++)
        #pragma unroll
        for (int ni = 0; ni < 8; ni++) {
            int m = m0 + wm*32 + mi*16 + r;
            int nn = wn*64 + ni*8 + cb;
            int bt = btp*2 + (nn >> 6);
            int d = nn & 63;
            bf16 h0,l0,h1,l1,h2,l2,h3,l3;
            sp2(acc[mi][ni][0], h0, l0); sp2(acc[mi][ni][1], h1, l1);
            sp2(acc[mi][ni][2], h2, l2); sp2(acc[mi][ni][3], h3, l3);
            *(__nv_bfloat162*)&outh[(bt*Nv + m)*64 + d]     = __nv_bfloat162(h0, h1);
            *(__nv_bfloat162*)&outl[(bt*Nv + m)*64 + d]     = __nv_bfloat162(l0, l1);
            *(__nv_bfloat162*)&outh[(bt*Nv + m + 8)*64 + d] = __nv_bfloat162(h2, h3);
            *(__nv_bfloat162*)&outl[(bt*Nv + m + 8)*64 + d] = __nv_bfloat162(l2, l3);
        }
}

// ---------------- gc: h@W0 + p1@W1 + p2@W2 + bias + h -> LN -> g_h2 ----------------
__global__ __launch_bounds__(256) void k_gc_mma(const float* __restrict__ gcb,
    const float* __restrict__ gg, const float* __restrict__ bg) {
    __shared__ __align__(16) char sm[SMEM_BYTES];
    int tid = threadIdx.x, lane = tid & 31, wid = tid >> 5;
    int wm = wid & 3, wn = wid >> 2;
    int r0g = blockIdx.x * 128;

    float acc[2][4][4] = {};
    const bf16* ih[3] = {g_hh, g_p1h, g_p2h};
    const bf16* il[3] = {g_hl, g_p1l, g_p2l};
    #pragma unroll
    for (int mm = 0; mm < 3; mm++)
        #pragma unroll
        for (int kc = 0; kc < 2; kc++) {
            stage_A(sm, ih[mm], il[mm], r0g, 64, kc*32, tid);
            stage_B(sm, g_gcWh + mm*4096, g_gcWl + mm*4096, 0, 64, 0, kc*32, tid);
            CP_COMMIT(); CP_WAIT0();
            __syncthreads();
            mma_compute(sm, acc, lane, wm, wn);
            __syncthreads();
        }
    float* sO = (float*)sm;
    int r = lane >> 2, cb = (lane & 3)*2;
    #pragma unroll
    for (int mi = 0; mi < 2; mi++)
        #pragma unroll
        for (int ni = 0; ni < 4; ni++) {
            int m = wm*32 + mi*16 + r;
            int n = wn*32 + ni*8 + cb;
            float b0 = gcb[n] + gcb[64+n] + gcb[128+n];
            float b1 = gcb[n+1] + gcb[64+n+1] + gcb[128+n+1];
            float2 h0 = *(const float2*)&g_h[(r0g + m)*64 + n];
            float2 h1 = *(const float2*)&g_h[(r0g + m + 8)*64 + n];
            *(float2*)&sO[m*64 + n]     = make_float2(acc[mi][ni][0] + b0 + h0.x, acc[mi][ni][1] + b1 + h0.y);
            *(float2*)&sO[(m+8)*64 + n] = make_float2(acc[mi][ni][2] + b0 + h1.x, acc[mi][ni][3] + b1 + h1.y);
        }
    __syncthreads();
    ln256(sO, r0g, gg, bg, g_h2, g_h2h, g_h2l);
}

// ---------------- ffn1: gelu(h2 @ W1 + b1) -> u hi/lo ----------------
__global__ __launch_bounds__(256) void k_ffn1_mma(const float* __restrict__ b1) {
    __shared__ __align__(16) char sm[SMEM_BYTES];
    int tid = threadIdx.x, lane = tid & 31, wid = tid >> 5;
    int wm = wid & 3, wn = wid >> 2;
    int r0g = blockIdx.x * 128;
    int c0g = blockIdx.y * 64;

    float acc[2][4][4] = {};
    #pragma unroll
    for (int kc = 0; kc < 2; kc++) {
        stage_A(sm, g_h2h, g_h2l, r0g, 64, kc*32, tid);
        stage_B(sm, g_W1h, g_W1l, 0, Fv, c0g, kc*32, tid);
        CP_COMMIT(); CP_WAIT0();
        __syncthreads();
        mma_compute(sm, acc, lane, wm, wn);
        __syncthreads();
    }
    int r = lane >> 2, cb = (lane & 3)*2;
    #pragma unroll
    for (int mi = 0; mi < 2; mi++)
        #pragma unroll
        for (int ni = 0; ni < 4; ni++) {
            int m = r0g + wm*32 + mi*16 + r;
            int n = wn*32 + ni*8 + cb;
            float b0 = b1[c0g + n], b1v = b1[c0g + n + 1];
            float v[4] = {acc[mi][ni][0] + b0, acc[mi][ni][1] + b1v,
                          acc[mi][ni][2] + b0, acc[mi][ni][3] + b1v};
            #pragma unroll
            for (int j = 0; j < 4; j++)
                v[j] = 0.5f * v[j] * (1.0f + erff(v[j] * 0.70710678118654752f));
            bf16 h0,l0,h1,l1,h2,l2,h3,l3;
            sp2(v[0],h0,l0); sp2(v[1],h1,l1); sp2(v[2],h2,l2); sp2(v[3],h3,l3);
            *(__nv_bfloat162*)&g_uh[m*Fv + c0g + n]     = __nv_bfloat162(h0, h1);
            *(__nv_bfloat162*)&g_ul[m*Fv + c0g + n]     = __nv_bfloat162(l0, l1);
            *(__nv_bfloat162*)&g_uh[(m+8)*Fv + c0g + n] = __nv_bfloat162(h2, h3);
            *(__nv_bfloat162*)&g_ul[(m+8)*Fv + c0g + n] = __nv_bfloat162(l2, l3);
        }
}

// ---------------- ffn2: u @ W2 + b2 + h2 -> LN -> out ----------------
__global__ __launch_bounds__(256) void k_ffn2_mma(const float* __restrict__ b2,
    const float* __restrict__ gf, const float* __restrict__ bf,
    float* __restrict__ out) {
    __shared__ __align__(16) char sm[SMEM_BYTES];
    int tid = threadIdx.x, lane = tid & 31, wid = tid >> 5;
    int wm = wid & 3, wn = wid >> 2;
    int r0g = blockIdx.x * 128;

    float acc[2][4][4] = {};
    #pragma unroll
    for (int kc = 0; kc < 8; kc++) {
        stage_A(sm, g_uh, g_ul, r0g, Fv, kc*32, tid);
        stage_B(sm, g_W2h, g_W2l, 0, 64, 0, kc*32, tid);
        CP_COMMIT(); CP_WAIT0();
        __syncthreads();
        mma_compute(sm, acc, lane, wm, wn);
        __syncthreads();
    }
    float* sO = (float*)sm;
    int r = lane >> 2, cb = (lane & 3)*2;
    #pragma unroll
    for (int mi = 0; mi < 2; mi++)
        #pragma unroll
        for (int ni = 0; ni < 4; ni++) {
            int m = wm*32 + mi*16 + r;
            int n = wn*32 + ni*8 + cb;
            float b0 = b2[n], b1 = b2[n+1];
            float2 h0 = *(const float2*)&g_h2[(r0g + m)*64 + n];
            float2 h1 = *(const float2*)&g_h2[(r0g + m + 8)*64 + n];
            *(float2*)&sO[m*64 + n]     = make_float2(acc[mi][ni][0] + b0 + h0.x, acc[mi][ni][1] + b1 + h0.y);
            *(float2*)&sO[(m+8)*64 + n] = make_float2(acc[mi][ni][2] + b0 + h1.x, acc[mi][ni][3] + b1 + h1.y);
        }
    __syncthreads();
    ln256(sO, r0g, gf, bf, out, (bf16*)0, (bf16*)0);
}

// ---------------- launch ----------------
extern "C" void kernel_launch(void* const* d_in, const int* in_sizes, int n_in,
                              void* d_out, int out_size) {
    const float* x   = (const float*)d_in[0];
    const float* adj = (const float*)d_in[1];
    const float* bq  = (const float*)d_in[3];
    const float* bk  = (const float*)d_in[5];
    const float* bv  = (const float*)d_in[7];
    const float* bo  = (const float*)d_in[9];
    const float* gcb = (const float*)d_in[11];
    const float* b1  = (const float*)d_in[13];
    const float* b2  = (const float*)d_in[15];
    const float* g_t = (const float*)d_in[16];
    const float* b_t = (const float*)d_in[17];
    const float* g_g = (const float*)d_in[18];
    const float* b_g = (const float*)d_in[19];
    const float* g_f = (const float*)d_in[20];
    const float* b_f = (const float*)d_in[21];
    float* out = (float*)d_out;

    k_deg   <<<Nv, 128>>>(adj);
    k_ahat  <<<(Nv*Nv)/512, 512>>>(adj);
    k_asq   <<<dim3(4, 4), 256>>>();
    k_splitx<<<(BTNv*Dv)/1024, 256>>>(x);
    k_splitw<<<240, 256>>>((const float*)d_in[2], (const float*)d_in[4],
                           (const float*)d_in[6], (const float*)d_in[8],
                           (const float*)d_in[10], (const float*)d_in[12],
                           (const float*)d_in[14]);
    k_qkv_mma<<<RT128, 256>>>(bq, bk, bv);
    k_attn  <<<dim3(Nv, Bv), 256>>>();
    k_attnout_mma<<<RT128, 256>>>(x, bo, g_t, b_t);
    k_prop2 <<<dim3(8, 192), 256>>>();
    k_gc_mma<<<RT128, 256>>>(gcb, g_g, b_g);
    k_ffn1_mma<<<dim3(RT128, Fv/64), 256>>>(b1);
    k_ffn2_mma<<<RT128, 256>>>(b2, g_f, b_f, out);
}

// round 14
// speedup vs baseline: 2.9774x; 1.2300x over previous
#include <cuda_runtime.h>
#include <cuda_bf16.h>
#include <math.h>
#include <cstdint>

#define Bv   16
#define Tv   24
#define Nv   512
#define Dv   64
#define Hv   4
#define HDv  16
#define Fv   256
#define BTv  (Bv*Tv)           // 384
#define BTNv (BTv*Nv)          // 196608
#define RT128 (BTNv/128)       // 1536

typedef unsigned long long ull;
typedef __nv_bfloat16 bf16;

// ---------------- scratch (static device globals; no allocation) ----------------
__device__ float g_dinv[Nv];
__device__ float g_q  [BTNv*Dv];
__device__ float g_k  [BTNv*Dv];
__device__ float g_v  [BTNv*Dv];
__device__ float g_h  [BTNv*Dv];
__device__ float g_h2 [BTNv*Dv];
// bf16 hi/lo pairs (lo kept only where a 3-product consumer needs it)
__device__ bf16 g_Ahi[Nv*Nv],     g_Alo[Nv*Nv];
__device__ bf16 g_A2h[Nv*Nv];
__device__ bf16 g_xh [BTNv*Dv],   g_xl [BTNv*Dv];
__device__ bf16 g_atth[BTNv*Dv],  g_attl[BTNv*Dv];
__device__ bf16 g_hh [BTNv*Dv],   g_hl [BTNv*Dv];
__device__ bf16 g_p1h[BTNv*Dv],   g_p1l[BTNv*Dv];
__device__ bf16 g_p2h[BTNv*Dv],   g_p2l[BTNv*Dv];
__device__ bf16 g_h2h[BTNv*Dv];
__device__ bf16 g_uh [BTNv*Fv];
// weight splits
__device__ bf16 g_Wqh[4096], g_Wql[4096];
__device__ bf16 g_Wkh[4096], g_Wkl[4096];
__device__ bf16 g_Wvh[4096], g_Wvl[4096];
__device__ bf16 g_Woh[4096], g_Wol[4096];
__device__ bf16 g_gcWh[3*4096], g_gcWl[3*4096];
__device__ bf16 g_W1h[64*Fv], g_W1l[64*Fv];
__device__ bf16 g_W2h[Fv*64], g_W2l[Fv*64];

// ================= mma.sync / cp.async helpers =================
__device__ __forceinline__ uint32_t smem_u32(const void* p) {
    uint32_t a;
    asm("{ .reg .u64 t; cvta.to.shared.u64 t, %1; cvt.u32.u64 %0, t; }" : "=r"(a) : "l"(p));
    return a;
}
#define LDMX4(r, addr) \
    asm volatile("ldmatrix.sync.aligned.m8n8.x4.shared.b16 {%0,%1,%2,%3}, [%4];" \
        : "=r"((r)[0]), "=r"((r)[1]), "=r"((r)[2]), "=r"((r)[3]) : "r"(addr))
#define LDMX4T(r, addr) \
    asm volatile("ldmatrix.sync.aligned.m8n8.x4.trans.shared.b16 {%0,%1,%2,%3}, [%4];" \
        : "=r"((r)[0]), "=r"((r)[1]), "=r"((r)[2]), "=r"((r)[3]) : "r"(addr))
#define LDMX2T(r, addr) \
    asm volatile("ldmatrix.sync.aligned.m8n8.x2.trans.shared.b16 {%0,%1}, [%2];" \
        : "=r"((r)[0]), "=r"((r)[1]) : "r"(addr))
#define MMA_BF16(d, a, b) \
    asm volatile("mma.sync.aligned.m16n8k16.row.col.f32.bf16.bf16.f32 " \
        "{%0,%1,%2,%3}, {%4,%5,%6,%7}, {%8,%9}, {%0,%1,%2,%3};" \
        : "+f"((d)[0]), "+f"((d)[1]), "+f"((d)[2]), "+f"((d)[3]) \
        : "r"((a)[0]), "r"((a)[1]), "r"((a)[2]), "r"((a)[3]), \
          "r"((b)[0]), "r"((b)[1]))
#define CP16(saddr, gptr) \
    asm volatile("cp.async.ca.shared.global [%0], [%1], 16;" :: "r"(saddr), "l"(gptr))
#define CP_COMMIT() asm volatile("cp.async.commit_group;" ::: "memory")
#define CP_WAIT0()  asm volatile("cp.async.wait_group 0;" ::: "memory")
#define CP_WAIT1()  asm volatile("cp.async.wait_group 1;" ::: "memory")

__device__ __forceinline__ void sp2(float x, bf16& h, bf16& l) {
    h = __float2bfloat16(x);
    l = __float2bfloat16(x - __bfloat162float(h));
}

// ---- generic 3-product layout (qkv/attnout/gc) ----
// sAh [128*40] @0 (10240) | sAl @10240 | sBh [32*72] @20480 (4608) | sBl @25088
// sO  [128*64] f32 @0 (32768) -- only after staging dead
#define SMEM_BYTES 33280

__device__ __forceinline__ void stage_A(char* sm, const bf16* __restrict__ gh,
                                        const bf16* __restrict__ gl,
                                        int rowBase, int ldA, int k0, int tid) {
    uint32_t sAh = smem_u32(sm);
    uint32_t sAl = sAh + 10240;
    #pragma unroll
    for (int i = tid; i < 512; i += 256) {
        int r = i >> 2, c8 = (i & 3) * 8;
        int gi = (rowBase + r)*ldA + k0 + c8;
        uint32_t off = (r*40 + c8)*2;
        CP16(sAh + off, &gh[gi]);
        CP16(sAl + off, &gl[gi]);
    }
}
__device__ __forceinline__ void stage_B(char* sm, const bf16* __restrict__ gh,
                                        const bf16* __restrict__ gl,
                                        int rowBase, int ldB, int colBase, int k0, int tid) {
    uint32_t sBh = smem_u32(sm) + 20480;
    uint32_t sBl = sBh + 4608;
    int k = tid >> 3, n8 = (tid & 7) * 8;
    int gi = (rowBase + k0 + k)*ldB + colBase + n8;
    uint32_t off = (k*72 + n8)*2;
    CP16(sBh + off, &gh[gi]);
    CP16(sBl + off, &gl[gi]);
}

__device__ __forceinline__ void mma_compute(char* sm, float acc[2][4][4],
                                            int lane, int wm, int wn) {
    uint32_t baseAh = smem_u32(sm), baseAl = smem_u32(sm + 10240);
    uint32_t baseBh = smem_u32(sm + 20480), baseBl = smem_u32(sm + 25088);
    int arow = wm*32 + (lane & 15);
    int acolL = (lane >> 4) * 8;
    int brow = lane & 15;
    int bcol = wn*32;
    #pragma unroll
    for (int ks = 0; ks < 2; ks++) {
        uint32_t aH[2][4], aL[2][4], bH[4][2], bL[4][2];
        int acol = ks*16 + acolL;
        #pragma unroll
        for (int mi = 0; mi < 2; mi++) {
            uint32_t off = ((arow + mi*16)*40 + acol)*2;
            LDMX4(aH[mi], baseAh + off);
            LDMX4(aL[mi], baseAl + off);
        }
        #pragma unroll
        for (int ni = 0; ni < 4; ni++) {
            uint32_t off = ((ks*16 + brow)*72 + bcol + ni*8)*2;
            LDMX2T(bH[ni], baseBh + off);
            LDMX2T(bL[ni], baseBl + off);
        }
        #pragma unroll
        for (int mi = 0; mi < 2; mi++)
            #pragma unroll
            for (int ni = 0; ni < 4; ni++) {
                MMA_BF16(acc[mi][ni], aH[mi], bH[ni]);
                MMA_BF16(acc[mi][ni], aH[mi], bL[ni]);
                MMA_BF16(acc[mi][ni], aL[mi], bH[ni]);
            }
    }
}

// ---- 2-product layout (ffn1/ffn2): A hi only ----
// sA [128*40] @0 (10240) | sBh [32*72] @10240 (4608) | sBl @14848
__device__ __forceinline__ void stage_A1(char* sm, const bf16* __restrict__ gh,
                                         int rowBase, int ldA, int k0, int tid) {
    uint32_t sA = smem_u32(sm);
    #pragma unroll
    for (int i = tid; i < 512; i += 256) {
        int r = i >> 2, c8 = (i & 3) * 8;
        CP16(sA + (r*40 + c8)*2, &gh[(rowBase + r)*ldA + k0 + c8]);
    }
}
__device__ __forceinline__ void stage_B1(char* sm, const bf16* __restrict__ gh,
                                         const bf16* __restrict__ gl,
                                         int ldB, int colBase, int k0, int tid) {
    uint32_t sBh = smem_u32(sm) + 10240;
    int k = tid >> 3, n8 = (tid & 7) * 8;
    int gi = (k0 + k)*ldB + colBase + n8;
    uint32_t off = (k*72 + n8)*2;
    CP16(sBh + off, &gh[gi]);
    CP16(sBh + 4608 + off, &gl[gi]);
}
__device__ __forceinline__ void mma_compute2(char* sm, float acc[2][4][4],
                                             int lane, int wm, int wn) {
    uint32_t baseA = smem_u32(sm);
    uint32_t baseBh = baseA + 10240, baseBl = baseA + 14848;
    int arow = wm*32 + (lane & 15);
    int acolL = (lane >> 4) * 8;
    int brow = lane & 15;
    int bcol = wn*32;
    #pragma unroll
    for (int ks = 0; ks < 2; ks++) {
        uint32_t aH[2][4], bH[4][2], bL[4][2];
        int acol = ks*16 + acolL;
        #pragma unroll
        for (int mi = 0; mi < 2; mi++)
            LDMX4(aH[mi], baseA + ((arow + mi*16)*40 + acol)*2);
        #pragma unroll
        for (int ni = 0; ni < 4; ni++) {
            uint32_t off = ((ks*16 + brow)*72 + bcol + ni*8)*2;
            LDMX2T(bH[ni], baseBh + off);
            LDMX2T(bL[ni], baseBl + off);
        }
        #pragma unroll
        for (int mi = 0; mi < 2; mi++)
            #pragma unroll
            for (int ni = 0; ni < 4; ni++) {
                MMA_BF16(acc[mi][ni], aH[mi], bH[ni]);
                MMA_BF16(acc[mi][ni], aH[mi], bL[ni]);
            }
    }
}

// 256-thread LN over sO[128][64]; outl may be null (hi-only emit)
__device__ __forceinline__ void ln256(const float* sO, int r0g,
                                      const float* __restrict__ g,
                                      const float* __restrict__ b,
                                      float* outf, bf16* outh, bf16* outl) {
    int wid = threadIdx.x >> 5, lane = threadIdx.x & 31;
    float gg0 = g[lane], gg1 = g[lane + 32];
    float bb0 = b[lane], bb1 = b[lane + 32];
    for (int r = wid; r < 128; r += 8) {
        float v0 = sO[r*64 + lane];
        float v1 = sO[r*64 + lane + 32];
        float s = v0 + v1;
        #pragma unroll
        for (int o = 16; o; o >>= 1) s += __shfl_xor_sync(0xffffffffu, s, o);
        float m = s * (1.0f/64.0f);
        float d0 = v0 - m, d1 = v1 - m;
        float vs = d0*d0 + d1*d1;
        #pragma unroll
        for (int o = 16; o; o >>= 1) vs += __shfl_xor_sync(0xffffffffu, vs, o);
        float rs = rsqrtf(vs * (1.0f/64.0f) + 1e-5f);
        float o0 = d0*rs*gg0 + bb0;
        float o1 = d1*rs*gg1 + bb1;
        int gi0 = (r0g + r)*64 + lane, gi1 = gi0 + 32;
        if (outf) { outf[gi0] = o0; outf[gi1] = o1; }
        if (outh) {
            bf16 h0 = __float2bfloat16(o0);
            bf16 h1 = __float2bfloat16(o1);
            outh[gi0] = h0; outh[gi1] = h1;
            if (outl) {
                outl[gi0] = __float2bfloat16(o0 - __bfloat162float(h0));
                outl[gi1] = __float2bfloat16(o1 - __bfloat162float(h1));
            }
        }
    }
}

// ---------------- graph normalization ----------------
__global__ __launch_bounds__(128) void k_deg(const float* __restrict__ adj) {
    __shared__ float red[128];
    int m = blockIdx.x;
    float s = 0.f;
    for (int j = threadIdx.x; j < Nv; j += 128) s += adj[m*Nv + j];
    red[threadIdx.x] = s; __syncthreads();
    for (int o = 64; o; o >>= 1) {
        if (threadIdx.x < o) red[threadIdx.x] += red[threadIdx.x + o];
        __syncthreads();
    }
    if (threadIdx.x == 0) g_dinv[m] = rsqrtf(fmaxf(red[0] + 1.0f, 1e-12f));
}

__global__ __launch_bounds__(512) void k_ahat(const float* __restrict__ adj) {
    int i = blockIdx.x * 512 + threadIdx.x;
    int m = i >> 9, n = i & 511;
    float a = adj[i] + (m == n ? 1.0f : 0.0f);
    float v = g_dinv[m] * a * g_dinv[n];
    bf16 h, l; sp2(v, h, l);
    g_Ahi[i] = h; g_Alo[i] = l;
}

// ========== N=128 pipeline machinery (2-product: A hi only) ==========
// Per buffer (stride 14848): A 128x16 s24 @0 (6144) | Bh 16x128 s136 @6144 (4352) | Bl @10496

// ---------------- A2 = Ahat @ Ahat (2-product), writes A2 hi only ----------------
__global__ __launch_bounds__(256, 2) void k_asq() {
    __shared__ __align__(16) char sm[2*14848];
    int tid = threadIdx.x, lane = tid & 31, wid = tid >> 5;
    int wm = wid & 3, wn = wid >> 2;
    int m0 = blockIdx.x * 128, n0 = blockIdx.y * 128;
    uint32_t sb = smem_u32(sm);
    int sr = tid >> 1, sc = (tid & 1)*8;
    int bk = tid >> 4, bn = (tid & 15)*8;

    auto stage = [&](int kc, int b) {
        uint32_t base = sb + b*14848;
        int k0 = kc*16;
        CP16(base + (sr*24 + sc)*2, &g_Ahi[(m0 + sr)*Nv + k0 + sc]);
        int g2 = (k0 + bk)*Nv + n0 + bn;
        uint32_t bo = base + 6144 + (bk*136 + bn)*2;
        CP16(bo,        &g_Ahi[g2]);
        CP16(bo + 4352, &g_Alo[g2]);
    };

    float acc[2][8][4] = {};
    int arow = wm*32 + (lane & 15), acol = (lane >> 4)*8;
    int brow = lane & 15, bsel = (lane >> 4)*8;

    stage(0, 0); CP_COMMIT();
    for (int kc = 0; kc < 32; kc++) {
        if (kc + 1 < 32) { stage(kc+1, (kc+1)&1); CP_COMMIT(); CP_WAIT1(); }
        else             { CP_WAIT0(); }
        __syncthreads();
        uint32_t base = sb + (kc&1)*14848;
        uint32_t aH[2][4], bH[4][4], bL[4][4];
        #pragma unroll
        for (int mi = 0; mi < 2; mi++)
            LDMX4(aH[mi], base + ((arow + mi*16)*24 + acol)*2);
        #pragma unroll
        for (int nj = 0; nj < 4; nj++) {
            uint32_t off = (brow*136 + wn*64 + nj*16 + bsel)*2;
            LDMX4T(bH[nj], base + 6144 + off);
            LDMX4T(bL[nj], base + 10496 + off);
        }
        #pragma unroll
        for (int mi = 0; mi < 2; mi++)
            #pragma unroll
            for (int ni = 0; ni < 8; ni++) {
                MMA_BF16(acc[mi][ni], aH[mi], &bH[ni>>1][(ni&1)*2]);
                MMA_BF16(acc[mi][ni], aH[mi], &bL[ni>>1][(ni&1)*2]);
            }
        __syncthreads();
    }
    int r = lane >> 2, cb = (lane & 3)*2;
    #pragma unroll
    for (int mi = 0; mi < 2; mi++)
        #pragma unroll
        for (int ni = 0; ni < 8; ni++) {
            int m = m0 + wm*32 + mi*16 + r;
            int n = n0 + wn*64 + ni*8 + cb;
            *(__nv_bfloat162*)&g_A2h[m*Nv + n] =
                __nv_bfloat162(__float2bfloat16(acc[mi][ni][0]), __float2bfloat16(acc[mi][ni][1]));
            *(__nv_bfloat162*)&g_A2h[(m+8)*Nv + n] =
                __nv_bfloat162(__float2bfloat16(acc[mi][ni][2]), __float2bfloat16(acc[mi][ni][3]));
        }
}

// ---------------- input / weight splits ----------------
__global__ __launch_bounds__(256) void k_splitx(const float* __restrict__ x) {
    int i = (blockIdx.x * 256 + threadIdx.x) * 4;
    float4 v = *(const float4*)&x[i];
    bf16 h0,h1,h2,h3,l0,l1,l2,l3;
    sp2(v.x,h0,l0); sp2(v.y,h1,l1); sp2(v.z,h2,l2); sp2(v.w,h3,l3);
    *(__nv_bfloat162*)&g_xh[i]   = __nv_bfloat162(h0,h1);
    *(__nv_bfloat162*)&g_xh[i+2] = __nv_bfloat162(h2,h3);
    *(__nv_bfloat162*)&g_xl[i]   = __nv_bfloat162(l0,l1);
    *(__nv_bfloat162*)&g_xl[i+2] = __nv_bfloat162(l2,l3);
}

__global__ __launch_bounds__(256) void k_splitw(
    const float* __restrict__ Wq, const float* __restrict__ Wk,
    const float* __restrict__ Wv, const float* __restrict__ Wo,
    const float* __restrict__ gcW, const float* __restrict__ W1,
    const float* __restrict__ W2) {
    int i = blockIdx.x * 256 + threadIdx.x;
    const float* src; bf16 *dh, *dl; int off;
    if      (i < 4096)  { src = Wq;  dh = g_Wqh;  dl = g_Wql;  off = i; }
    else if (i < 8192)  { src = Wk;  dh = g_Wkh;  dl = g_Wkl;  off = i - 4096; }
    else if (i < 12288) { src = Wv;  dh = g_Wvh;  dl = g_Wvl;  off = i - 8192; }
    else if (i < 16384) { src = Wo;  dh = g_Woh;  dl = g_Wol;  off = i - 12288; }
    else if (i < 28672) { src = gcW; dh = g_gcWh; dl = g_gcWl; off = i - 16384; }
    else if (i < 45056) { src = W1;  dh = g_W1h;  dl = g_W1l;  off = i - 28672; }
    else if (i < 61440) { src = W2;  dh = g_W2h;  dl = g_W2l;  off = i - 45056; }
    else return;
    bf16 h, l; sp2(src[off], h, l);
    dh[off] = h; dl[off] = l;
}

// ---------------- merged QKV (3-product) ----------------
__global__ __launch_bounds__(256) void k_qkv_mma(const float* __restrict__ bq,
                                                 const float* __restrict__ bk,
                                                 const float* __restrict__ bv) {
    __shared__ __align__(16) char sm[48128];
    int tid = threadIdx.x, lane = tid & 31, wid = tid >> 5;
    int wm = wid & 3, wn = wid >> 2;
    int r0g = blockIdx.x * 128;
    uint32_t sb = smem_u32(sm);

    const bf16* Wh[3] = {g_Wqh, g_Wkh, g_Wvh};
    const bf16* Wl[3] = {g_Wql, g_Wkl, g_Wvl};
    const float* bias[3] = {bq, bk, bv};
    float* outp[3] = {g_q, g_k, g_v};

    float acc[3][2][4][4] = {};
    int arow = wm*32 + (lane & 15);
    int acolL = (lane >> 4)*8;
    int brow = lane & 15, bsel = (lane >> 4)*8;

    #pragma unroll
    for (int kc = 0; kc < 2; kc++) {
        stage_A(sm, g_xh, g_xl, r0g, 64, kc*32, tid);
        {
            int k = tid >> 3, n8 = (tid & 7)*8;
            #pragma unroll
            for (int s = 0; s < 3; s++) {
                uint32_t bo = sb + 20480 + s*9216 + (k*72 + n8)*2;
                int gi = (kc*32 + k)*64 + n8;
                CP16(bo,        &Wh[s][gi]);
                CP16(bo + 4608, &Wl[s][gi]);
            }
        }
        CP_COMMIT(); CP_WAIT0();
        __syncthreads();
        #pragma unroll
        for (int ks = 0; ks < 2; ks++) {
            uint32_t aH[2][4], aL[2][4];
            int acol = ks*16 + acolL;
            #pragma unroll
            for (int mi = 0; mi < 2; mi++) {
                uint32_t off = ((arow + mi*16)*40 + acol)*2;
                LDMX4(aH[mi], sb + off);
                LDMX4(aL[mi], sb + 10240 + off);
            }
            #pragma unroll
            for (int s = 0; s < 3; s++) {
                uint32_t bH[2][4], bL[2][4];
                #pragma unroll
                for (int nj = 0; nj < 2; nj++) {
                    uint32_t off = ((ks*16 + brow)*72 + wn*32 + nj*16 + bsel)*2;
                    LDMX4T(bH[nj], sb + 20480 + s*9216 + off);
                    LDMX4T(bL[nj], sb + 20480 + s*9216 + 4608 + off);
                }
                #pragma unroll
                for (int mi = 0; mi < 2; mi++)
                    #pragma unroll
                    for (int ni = 0; ni < 4; ni++) {
                        MMA_BF16(acc[s][mi][ni], aH[mi], &bH[ni>>1][(ni&1)*2]);
                        MMA_BF16(acc[s][mi][ni], aH[mi], &bL[ni>>1][(ni&1)*2]);
                        MMA_BF16(acc[s][mi][ni], aL[mi], &bH[ni>>1][(ni&1)*2]);
                    }
            }
        }
        __syncthreads();
    }
    int r = lane >> 2, cb = (lane & 3)*2;
    #pragma unroll
    for (int s = 0; s < 3; s++)
        #pragma unroll
        for (int mi = 0; mi < 2; mi++)
            #pragma unroll
            for (int ni = 0; ni < 4; ni++) {
                int m = r0g + wm*32 + mi*16 + r;
                int n = wn*32 + ni*8 + cb;
                float b0 = bias[s][n], b1 = bias[s][n+1];
                *(float2*)&outp[s][m*64 + n]     = make_float2(acc[s][mi][ni][0] + b0, acc[s][mi][ni][1] + b1);
                *(float2*)&outp[s][(m+8)*64 + n] = make_float2(acc[s][mi][ni][2] + b0, acc[s][mi][ni][3] + b1);
            }
}

// ---------------- temporal attention -> att hi/lo ----------------
__global__ __launch_bounds__(256) void k_attn() {
    __shared__ __align__(16) float sqT[64*28];
    __shared__ __align__(16) float skT[64*28];
    __shared__ __align__(16) float sv[Tv*64];
    __shared__ __align__(16) float so[Tv*64];
    __shared__ __align__(16) float ss[Hv*Tv*25];
    int tid = threadIdx.x;
    int n = blockIdx.x, b = blockIdx.y;
    for (int i = tid; i < Tv*64; i += 256) {
        int t = i >> 6, d = i & 63;
        int gidx = ((b*Tv + t)*Nv + n)*64 + d;
        sqT[d*28 + t] = g_q[gidx];
        skT[d*28 + t] = g_k[gidx];
        sv[i]         = g_v[gidx];
    }
    __syncthreads();
    if (tid < Hv*36) {
        int h = tid / 36, blk = tid % 36;
        int tq0 = (blk / 6) * 4, tk0 = (blk % 6) * 4;
        float s[4][4] = {};
        const float* qb = &sqT[h*HDv*28];
        const float* kb = &skT[h*HDv*28];
        #pragma unroll
        for (int e = 0; e < HDv; e++) {
            float4 q4 = *(const float4*)(qb + e*28 + tq0);
            float4 k4 = *(const float4*)(kb + e*28 + tk0);
            float qa[4] = {q4.x, q4.y, q4.z, q4.w};
            float ka[4] = {k4.x, k4.y, k4.z, k4.w};
            #pragma unroll
            for (int i = 0; i < 4; i++)
                #pragma unroll
                for (int j = 0; j < 4; j++)
                    s[i][j] = fmaf(qa[i], ka[j], s[i][j]);
        }
        #pragma unroll
        for (int i = 0; i < 4; i++)
            #pragma unroll
            for (int j = 0; j < 4; j++)
                ss[(h*Tv + tq0 + i)*25 + tk0 + j] = s[i][j] * 0.25f;
    }
    __syncthreads();
    if (tid < Hv*Tv) {
        float* row = &ss[tid*25];
        float mx = -1e30f;
        #pragma unroll
        for (int tk = 0; tk < Tv; tk++) mx = fmaxf(mx, row[tk]);
        float sum = 0.f;
        #pragma unroll
        for (int tk = 0; tk < Tv; tk++) { float e = expf(row[tk]-mx); row[tk] = e; sum += e; }
        float inv = 1.0f / sum;
        #pragma unroll
        for (int tk = 0; tk < Tv; tk++) row[tk] *= inv;
    }
    __syncthreads();
    if (tid < Hv*24) {
        int h = tid / 24, blk = tid % 24;
        int tq0 = (blk / 4) * 4, e0 = (blk % 4) * 4;
        float o[4][4] = {};
        #pragma unroll
        for (int tk = 0; tk < Tv; tk++) {
            float4 v4 = *(const float4*)&sv[tk*64 + h*HDv + e0];
            float va[4] = {v4.x, v4.y, v4.z, v4.w};
            float pa[4];
            #pragma unroll
            for (int i = 0; i < 4; i++) pa[i] = ss[(h*Tv + tq0 + i)*25 + tk];
            #pragma unroll
            for (int i = 0; i < 4; i++)
                #pragma unroll
                for (int j = 0; j < 4; j++)
                    o[i][j] = fmaf(pa[i], va[j], o[i][j]);
        }
        #pragma unroll
        for (int i = 0; i < 4; i++)
            *(float4*)&so[(tq0 + i)*64 + h*HDv + e0] =
                make_float4(o[i][0], o[i][1], o[i][2], o[i][3]);
    }
    __syncthreads();
    for (int i = tid; i < Tv*64; i += 256) {
        int t = i >> 6, d = i & 63;
        int gi = ((b*Tv + t)*Nv + n)*64 + d;
        bf16 h, l; sp2(so[i], h, l);
        g_atth[gi] = h; g_attl[gi] = l;
    }
}

// ---------------- attnout (3-product): att @ Wo + bo + x -> LN -> g_h ----------------
__global__ __launch_bounds__(256) void k_attnout_mma(const float* __restrict__ x,
    const float* __restrict__ bo,
    const float* __restrict__ gt, const float* __restrict__ bt) {
    __shared__ __align__(16) char sm[SMEM_BYTES];
    int tid = threadIdx.x, lane = tid & 31, wid = tid >> 5;
    int wm = wid & 3, wn = wid >> 2;
    int r0g = blockIdx.x * 128;

    float acc[2][4][4] = {};
    #pragma unroll
    for (int kc = 0; kc < 2; kc++) {
        stage_A(sm, g_atth, g_attl, r0g, 64, kc*32, tid);
        stage_B(sm, g_Woh, g_Wol, 0, 64, 0, kc*32, tid);
        CP_COMMIT(); CP_WAIT0();
        __syncthreads();
        mma_compute(sm, acc, lane, wm, wn);
        __syncthreads();
    }
    float* sO = (float*)sm;
    int r = lane >> 2, cb = (lane & 3)*2;
    #pragma unroll
    for (int mi = 0; mi < 2; mi++)
        #pragma unroll
        for (int ni = 0; ni < 4; ni++) {
            int m = wm*32 + mi*16 + r;
            int n = wn*32 + ni*8 + cb;
            float b0 = bo[n], b1 = bo[n+1];
            float2 x0 = *(const float2*)&x[(r0g + m)*64 + n];
            float2 x1 = *(const float2*)&x[(r0g + m + 8)*64 + n];
            *(float2*)&sO[m*64 + n]     = make_float2(acc[mi][ni][0] + b0 + x0.x, acc[mi][ni][1] + b1 + x0.y);
            *(float2*)&sO[(m+8)*64 + n] = make_float2(acc[mi][ni][2] + b0 + x1.x, acc[mi][ni][3] + b1 + x1.y);
        }
    __syncthreads();
    ln256(sO, r0g, gt, bt, g_h, g_hh, g_hl);
}

// ---------------- prop2 (2-product): p1 = Ahat@h, p2 = A2@h ----------------
__global__ __launch_bounds__(256, 2) void k_prop2() {
    __shared__ __align__(16) char sm[2*14848];
    int tid = threadIdx.x, lane = tid & 31, wid = tid >> 5;
    int wm = wid & 3, wn = wid >> 2;
    int my = blockIdx.x, btp = blockIdx.y;
    const bf16* __restrict__ Ah_ = my < 4 ? g_Ahi : g_A2h;
    bf16* __restrict__ outh = my < 4 ? g_p1h : g_p2h;
    bf16* __restrict__ outl = my < 4 ? g_p1l : g_p2l;
    int m0 = (my & 3) * 128;
    uint32_t sb = smem_u32(sm);

    int sr = tid >> 1, sc = (tid & 1)*8;
    int bk = tid >> 4, bn = (tid & 15)*8;
    int bth = bn >> 6, bd = bn & 63;

    auto stage = [&](int kc, int b) {
        uint32_t base = sb + b*14848;
        int k0 = kc*16;
        CP16(base + (sr*24 + sc)*2, &Ah_[(m0 + sr)*Nv + k0 + sc]);
        int g2 = ((btp*2 + bth)*Nv + k0 + bk)*64 + bd;
        uint32_t bo = base + 6144 + (bk*136 + bn)*2;
        CP16(bo,        &g_hh[g2]);
        CP16(bo + 4352, &g_hl[g2]);
    };

    float acc[2][8][4] = {};
    int arow = wm*32 + (lane & 15), acol = (lane >> 4)*8;
    int brow = lane & 15, bsel = (lane >> 4)*8;

    stage(0, 0); CP_COMMIT();
    for (int kc = 0; kc < 32; kc++) {
        if (kc + 1 < 32) { stage(kc+1, (kc+1)&1); CP_COMMIT(); CP_WAIT1(); }
        else             { CP_WAIT0(); }
        __syncthreads();
        uint32_t base = sb + (kc&1)*14848;
        uint32_t aH[2][4], bH[4][4], bL[4][4];
        #pragma unroll
        for (int mi = 0; mi < 2; mi++)
            LDMX4(aH[mi], base + ((arow + mi*16)*24 + acol)*2);
        #pragma unroll
        for (int nj = 0; nj < 4; nj++) {
            uint32_t off = (brow*136 + wn*64 + nj*16 + bsel)*2;
            LDMX4T(bH[nj], base + 6144 + off);
            LDMX4T(bL[nj], base + 10496 + off);
        }
        #pragma unroll
        for (int mi = 0; mi < 2; mi++)
            #pragma unroll
            for (int ni = 0; ni < 8; ni++) {
                MMA_BF16(acc[mi][ni], aH[mi], &bH[ni>>1][(ni&1)*2]);
                MMA_BF16(acc[mi][ni], aH[mi], &bL[ni>>1][(ni&1)*2]);
            }
        __syncthreads();
    }
    int r = lane >> 2, cb = (lane & 3)*2;
    #pragma unroll
    for (int mi = 0; mi < 2; mi++)
        #pragma unroll
        for (int ni = 0; ni < 8; ni++) {
            int m = m0 + wm*32 + mi*16 + r;
            int nn = wn*64 + ni*8 + cb;
            int bt = btp*2 + (nn >> 6);
            int d = nn & 63;
            bf16 h0,l0,h1,l1,h2,l2,h3,l3;
            sp2(acc[mi][ni][0], h0, l0); sp2(acc[mi][ni][1], h1, l1);
            sp2(acc[mi][ni][2], h2, l2); sp2(acc[mi][ni][3], h3, l3);
            *(__nv_bfloat162*)&outh[(bt*Nv + m)*64 + d]     = __nv_bfloat162(h0, h1);
            *(__nv_bfloat162*)&outl[(bt*Nv + m)*64 + d]     = __nv_bfloat162(l0, l1);
            *(__nv_bfloat162*)&outh[(bt*Nv + m + 8)*64 + d] = __nv_bfloat162(h2, h3);
            *(__nv_bfloat162*)&outl[(bt*Nv + m + 8)*64 + d] = __nv_bfloat162(l2, l3);
        }
}

// ---------------- gc (3-product): h@W0 + p1@W1 + p2@W2 + bias + h -> LN -> g_h2 ----
__global__ __launch_bounds__(256) void k_gc_mma(const float* __restrict__ gcb,
    const float* __restrict__ gg, const float* __restrict__ bg) {
    __shared__ __align__(16) char sm[SMEM_BYTES];
    int tid = threadIdx.x, lane = tid & 31, wid = tid >> 5;
    int wm = wid & 3, wn = wid >> 2;
    int r0g = blockIdx.x * 128;

    float acc[2][4][4] = {};
    const bf16* ih[3] = {g_hh, g_p1h, g_p2h};
    const bf16* il[3] = {g_hl, g_p1l, g_p2l};
    #pragma unroll
    for (int mm = 0; mm < 3; mm++)
        #pragma unroll
        for (int kc = 0; kc < 2; kc++) {
            stage_A(sm, ih[mm], il[mm], r0g, 64, kc*32, tid);
            stage_B(sm, g_gcWh + mm*4096, g_gcWl + mm*4096, 0, 64, 0, kc*32, tid);
            CP_COMMIT(); CP_WAIT0();
            __syncthreads();
            mma_compute(sm, acc, lane, wm, wn);
            __syncthreads();
        }
    float* sO = (float*)sm;
    int r = lane >> 2, cb = (lane & 3)*2;
    #pragma unroll
    for (int mi = 0; mi < 2; mi++)
        #pragma unroll
        for (int ni = 0; ni < 4; ni++) {
            int m = wm*32 + mi*16 + r;
            int n = wn*32 + ni*8 + cb;
            float b0 = gcb[n] + gcb[64+n] + gcb[128+n];
            float b1 = gcb[n+1] + gcb[64+n+1] + gcb[128+n+1];
            float2 h0 = *(const float2*)&g_h[(r0g + m)*64 + n];
            float2 h1 = *(const float2*)&g_h[(r0g + m + 8)*64 + n];
            *(float2*)&sO[m*64 + n]     = make_float2(acc[mi][ni][0] + b0 + h0.x, acc[mi][ni][1] + b1 + h0.y);
            *(float2*)&sO[(m+8)*64 + n] = make_float2(acc[mi][ni][2] + b0 + h1.x, acc[mi][ni][3] + b1 + h1.y);
        }
    __syncthreads();
    ln256(sO, r0g, gg, bg, g_h2, g_h2h, (bf16*)0);
}

// ---------------- ffn1 (2-product): gelu(h2 @ W1 + b1) -> u hi ----------------
__global__ __launch_bounds__(256) void k_ffn1_mma(const float* __restrict__ b1) {
    __shared__ __align__(16) char sm[SMEM_BYTES];
    int tid = threadIdx.x, lane = tid & 31, wid = tid >> 5;
    int wm = wid & 3, wn = wid >> 2;
    int r0g = blockIdx.x * 128;
    int c0g = blockIdx.y * 64;

    float acc[2][4][4] = {};
    #pragma unroll
    for (int kc = 0; kc < 2; kc++) {
        stage_A1(sm, g_h2h, r0g, 64, kc*32, tid);
        stage_B1(sm, g_W1h, g_W1l, Fv, c0g, kc*32, tid);
        CP_COMMIT(); CP_WAIT0();
        __syncthreads();
        mma_compute2(sm, acc, lane, wm, wn);
        __syncthreads();
    }
    int r = lane >> 2, cb = (lane & 3)*2;
    #pragma unroll
    for (int mi = 0; mi < 2; mi++)
        #pragma unroll
        for (int ni = 0; ni < 4; ni++) {
            int m = r0g + wm*32 + mi*16 + r;
            int n = wn*32 + ni*8 + cb;
            float b0 = b1[c0g + n], b1v = b1[c0g + n + 1];
            float v[4] = {acc[mi][ni][0] + b0, acc[mi][ni][1] + b1v,
                          acc[mi][ni][2] + b0, acc[mi][ni][3] + b1v};
            #pragma unroll
            for (int j = 0; j < 4; j++)
                v[j] = 0.5f * v[j] * (1.0f + erff(v[j] * 0.70710678118654752f));
            *(__nv_bfloat162*)&g_uh[m*Fv + c0g + n] =
                __nv_bfloat162(__float2bfloat16(v[0]), __float2bfloat16(v[1]));
            *(__nv_bfloat162*)&g_uh[(m+8)*Fv + c0g + n] =
                __nv_bfloat162(__float2bfloat16(v[2]), __float2bfloat16(v[3]));
        }
}

// ---------------- ffn2 (2-product): u @ W2 + b2 + h2 -> LN -> out ----------------
__global__ __launch_bounds__(256) void k_ffn2_mma(const float* __restrict__ b2,
    const float* __restrict__ gf, const float* __restrict__ bf,
    float* __restrict__ out) {
    __shared__ __align__(16) char sm[SMEM_BYTES];
    int tid = threadIdx.x, lane = tid & 31, wid = tid >> 5;
    int wm = wid & 3, wn = wid >> 2;
    int r0g = blockIdx.x * 128;

    float acc[2][4][4] = {};
    #pragma unroll
    for (int kc = 0; kc < 8; kc++) {
        stage_A1(sm, g_uh, r0g, Fv, kc*32, tid);
        stage_B1(sm, g_W2h, g_W2l, 64, 0, kc*32, tid);
        CP_COMMIT(); CP_WAIT0();
        __syncthreads();
        mma_compute2(sm, acc, lane, wm, wn);
        __syncthreads();
    }
    float* sO = (float*)sm;
    int r = lane >> 2, cb = (lane & 3)*2;
    #pragma unroll
    for (int mi = 0; mi < 2; mi++)
        #pragma unroll
        for (int ni = 0; ni < 4; ni++) {
            int m = wm*32 + mi*16 + r;
            int n = wn*32 + ni*8 + cb;
            float b0 = b2[n], b1 = b2[n+1];
            float2 h0 = *(const float2*)&g_h2[(r0g + m)*64 + n];
            float2 h1 = *(const float2*)&g_h2[(r0g + m + 8)*64 + n];
            *(float2*)&sO[m*64 + n]     = make_float2(acc[mi][ni][0] + b0 + h0.x, acc[mi][ni][1] + b1 + h0.y);
            *(float2*)&sO[(m+8)*64 + n] = make_float2(acc[mi][ni][2] + b0 + h1.x, acc[mi][ni][3] + b1 + h1.y);
        }
    __syncthreads();
    ln256(sO, r0g, gf, bf, out, (bf16*)0, (bf16*)0);
}

// ---------------- launch ----------------
extern "C" void kernel_launch(void* const* d_in, const int* in_sizes, int n_in,
                              void* d_out, int out_size) {
    const float* x   = (const float*)d_in[0];
    const float* adj = (const float*)d_in[1];
    const float* bq  = (const float*)d_in[3];
    const float* bk  = (const float*)d_in[5];
    const float* bv  = (const float*)d_in[7];
    const float* bo  = (const float*)d_in[9];
    const float* gcb = (const float*)d_in[11];
    const float* b1  = (const float*)d_in[13];
    const float* b2  = (const float*)d_in[15];
    const float* g_t = (const float*)d_in[16];
    const float* b_t = (const float*)d_in[17];
    const float* g_g = (const float*)d_in[18];
    const float* b_g = (const float*)d_in[19];
    const float* g_f = (const float*)d_in[20];
    const float* b_f = (const float*)d_in[21];
    float* out = (float*)d_out;

    k_deg   <<<Nv, 128>>>(adj);
    k_ahat  <<<(Nv*Nv)/512, 512>>>(adj);
    k_asq   <<<dim3(4, 4), 256>>>();
    k_splitx<<<(BTNv*Dv)/1024, 256>>>(x);
    k_splitw<<<240, 256>>>((const float*)d_in[2], (const float*)d_in[4],
                           (const float*)d_in[6], (const float*)d_in[8],
                           (const float*)d_in[10], (const float*)d_in[12],
                           (const float*)d_in[14]);
    k_qkv_mma<<<RT128, 256>>>(bq, bk, bv);
    k_attn  <<<dim3(Nv, Bv), 256>>>();
    k_attnout_mma<<<RT128, 256>>>(x, bo, g_t, b_t);
    k_prop2 <<<dim3(8, 192), 256>>>();
    k_gc_mma<<<RT128, 256>>>(gcb, g_g, b_g);
    k_ffn1_mma<<<dim3(RT128, Fv/64), 256>>>(b1);
    k_ffn2_mma<<<RT128, 256>>>(b2, g_f, b_f, out);
}

// round 15
// speedup vs baseline: 3.2616x; 1.0955x over previous
#include <cuda_runtime.h>
#include <cuda_bf16.h>
#include <math.h>
#include <cstdint>

#define Bv   16
#define Tv   24
#define Nv   512
#define Dv   64
#define Hv   4
#define HDv  16
#define Fv   256
#define BTv  (Bv*Tv)           // 384
#define BTNv (BTv*Nv)          // 196608
#define RT128 (BTNv/128)       // 1536

typedef unsigned long long ull;
typedef __nv_bfloat16 bf16;

// ---------------- scratch (static device globals; no allocation) ----------------
__device__ float g_dinv[Nv];
__device__ float g_q  [BTNv*Dv];
__device__ float g_k  [BTNv*Dv];
__device__ float g_v  [BTNv*Dv];
__device__ float g_h  [BTNv*Dv];
__device__ float g_h2 [BTNv*Dv];
// bf16 buffers (lo kept only where a consumer's B-side needs it)
__device__ bf16 g_Ahi[Nv*Nv],     g_Alo[Nv*Nv];
__device__ bf16 g_A2h[Nv*Nv];
__device__ bf16 g_xh [BTNv*Dv];
__device__ bf16 g_atth[BTNv*Dv];
__device__ bf16 g_hh [BTNv*Dv],   g_hl [BTNv*Dv];   // h-lo needed by prop (B side)
__device__ bf16 g_p1h[BTNv*Dv];
__device__ bf16 g_p2h[BTNv*Dv];
__device__ bf16 g_h2h[BTNv*Dv];
__device__ bf16 g_uh [BTNv*Fv];
// weight splits (hi+lo, B side of their GEMMs)
__device__ bf16 g_Wqh[4096], g_Wql[4096];
__device__ bf16 g_Wkh[4096], g_Wkl[4096];
__device__ bf16 g_Wvh[4096], g_Wvl[4096];
__device__ bf16 g_Woh[4096], g_Wol[4096];
__device__ bf16 g_gcWh[3*4096], g_gcWl[3*4096];
__device__ bf16 g_W1h[64*Fv], g_W1l[64*Fv];
__device__ bf16 g_W2h[Fv*64], g_W2l[Fv*64];

// ================= mma.sync / cp.async helpers =================
__device__ __forceinline__ uint32_t smem_u32(const void* p) {
    uint32_t a;
    asm("{ .reg .u64 t; cvta.to.shared.u64 t, %1; cvt.u32.u64 %0, t; }" : "=r"(a) : "l"(p));
    return a;
}
#define LDMX4(r, addr) \
    asm volatile("ldmatrix.sync.aligned.m8n8.x4.shared.b16 {%0,%1,%2,%3}, [%4];" \
        : "=r"((r)[0]), "=r"((r)[1]), "=r"((r)[2]), "=r"((r)[3]) : "r"(addr))
#define LDMX4T(r, addr) \
    asm volatile("ldmatrix.sync.aligned.m8n8.x4.trans.shared.b16 {%0,%1,%2,%3}, [%4];" \
        : "=r"((r)[0]), "=r"((r)[1]), "=r"((r)[2]), "=r"((r)[3]) : "r"(addr))
#define LDMX2T(r, addr) \
    asm volatile("ldmatrix.sync.aligned.m8n8.x2.trans.shared.b16 {%0,%1}, [%2];" \
        : "=r"((r)[0]), "=r"((r)[1]) : "r"(addr))
#define MMA_BF16(d, a, b) \
    asm volatile("mma.sync.aligned.m16n8k16.row.col.f32.bf16.bf16.f32 " \
        "{%0,%1,%2,%3}, {%4,%5,%6,%7}, {%8,%9}, {%0,%1,%2,%3};" \
        : "+f"((d)[0]), "+f"((d)[1]), "+f"((d)[2]), "+f"((d)[3]) \
        : "r"((a)[0]), "r"((a)[1]), "r"((a)[2]), "r"((a)[3]), \
          "r"((b)[0]), "r"((b)[1]))
#define CP16(saddr, gptr) \
    asm volatile("cp.async.ca.shared.global [%0], [%1], 16;" :: "r"(saddr), "l"(gptr))
#define CP_COMMIT() asm volatile("cp.async.commit_group;" ::: "memory")
#define CP_WAIT0()  asm volatile("cp.async.wait_group 0;" ::: "memory")
#define CP_WAIT1()  asm volatile("cp.async.wait_group 1;" ::: "memory")

__device__ __forceinline__ void sp2(float x, bf16& h, bf16& l) {
    h = __float2bfloat16(x);
    l = __float2bfloat16(x - __bfloat162float(h));
}

// ---- 2-product layout (A hi only): sA [128*40] @0 (10240) | sBh [32*72] @10240 (4608) | sBl @14848
// sO [128*64] f32 @0 (32768) -- only after staging dead
#define SMEM_BYTES 33280

__device__ __forceinline__ void stage_A1(char* sm, const bf16* __restrict__ gh,
                                         int rowBase, int ldA, int k0, int tid) {
    uint32_t sA = smem_u32(sm);
    #pragma unroll
    for (int i = tid; i < 512; i += 256) {
        int r = i >> 2, c8 = (i & 3) * 8;
        CP16(sA + (r*40 + c8)*2, &gh[(rowBase + r)*ldA + k0 + c8]);
    }
}
__device__ __forceinline__ void stage_B1(char* sm, const bf16* __restrict__ gh,
                                         const bf16* __restrict__ gl,
                                         int ldB, int colBase, int k0, int tid) {
    uint32_t sBh = smem_u32(sm) + 10240;
    int k = tid >> 3, n8 = (tid & 7) * 8;
    int gi = (k0 + k)*ldB + colBase + n8;
    uint32_t off = (k*72 + n8)*2;
    CP16(sBh + off, &gh[gi]);
    CP16(sBh + 4608 + off, &gl[gi]);
}
__device__ __forceinline__ void mma_compute2(char* sm, float acc[2][4][4],
                                             int lane, int wm, int wn) {
    uint32_t baseA = smem_u32(sm);
    uint32_t baseBh = baseA + 10240, baseBl = baseA + 14848;
    int arow = wm*32 + (lane & 15);
    int acolL = (lane >> 4) * 8;
    int brow = lane & 15;
    int bcol = wn*32;
    #pragma unroll
    for (int ks = 0; ks < 2; ks++) {
        uint32_t aH[2][4], bH[4][2], bL[4][2];
        int acol = ks*16 + acolL;
        #pragma unroll
        for (int mi = 0; mi < 2; mi++)
            LDMX4(aH[mi], baseA + ((arow + mi*16)*40 + acol)*2);
        #pragma unroll
        for (int ni = 0; ni < 4; ni++) {
            uint32_t off = ((ks*16 + brow)*72 + bcol + ni*8)*2;
            LDMX2T(bH[ni], baseBh + off);
            LDMX2T(bL[ni], baseBl + off);
        }
        #pragma unroll
        for (int mi = 0; mi < 2; mi++)
            #pragma unroll
            for (int ni = 0; ni < 4; ni++) {
                MMA_BF16(acc[mi][ni], aH[mi], bH[ni]);
                MMA_BF16(acc[mi][ni], aH[mi], bL[ni]);
            }
    }
}

// 256-thread LN over sO[128][64]; outl may be null (hi-only emit)
__device__ __forceinline__ void ln256(const float* sO, int r0g,
                                      const float* __restrict__ g,
                                      const float* __restrict__ b,
                                      float* outf, bf16* outh, bf16* outl) {
    int wid = threadIdx.x >> 5, lane = threadIdx.x & 31;
    float gg0 = g[lane], gg1 = g[lane + 32];
    float bb0 = b[lane], bb1 = b[lane + 32];
    for (int r = wid; r < 128; r += 8) {
        float v0 = sO[r*64 + lane];
        float v1 = sO[r*64 + lane + 32];
        float s = v0 + v1;
        #pragma unroll
        for (int o = 16; o; o >>= 1) s += __shfl_xor_sync(0xffffffffu, s, o);
        float m = s * (1.0f/64.0f);
        float d0 = v0 - m, d1 = v1 - m;
        float vs = d0*d0 + d1*d1;
        #pragma unroll
        for (int o = 16; o; o >>= 1) vs += __shfl_xor_sync(0xffffffffu, vs, o);
        float rs = rsqrtf(vs * (1.0f/64.0f) + 1e-5f);
        float o0 = d0*rs*gg0 + bb0;
        float o1 = d1*rs*gg1 + bb1;
        int gi0 = (r0g + r)*64 + lane, gi1 = gi0 + 32;
        if (outf) { outf[gi0] = o0; outf[gi1] = o1; }
        if (outh) {
            bf16 h0 = __float2bfloat16(o0);
            bf16 h1 = __float2bfloat16(o1);
            outh[gi0] = h0; outh[gi1] = h1;
            if (outl) {
                outl[gi0] = __float2bfloat16(o0 - __bfloat162float(h0));
                outl[gi1] = __float2bfloat16(o1 - __bfloat162float(h1));
            }
        }
    }
}

// ---------------- graph normalization ----------------
__global__ __launch_bounds__(128) void k_deg(const float* __restrict__ adj) {
    __shared__ float red[128];
    int m = blockIdx.x;
    float s = 0.f;
    for (int j = threadIdx.x; j < Nv; j += 128) s += adj[m*Nv + j];
    red[threadIdx.x] = s; __syncthreads();
    for (int o = 64; o; o >>= 1) {
        if (threadIdx.x < o) red[threadIdx.x] += red[threadIdx.x + o];
        __syncthreads();
    }
    if (threadIdx.x == 0) g_dinv[m] = rsqrtf(fmaxf(red[0] + 1.0f, 1e-12f));
}

__global__ __launch_bounds__(512) void k_ahat(const float* __restrict__ adj) {
    int i = blockIdx.x * 512 + threadIdx.x;
    int m = i >> 9, n = i & 511;
    float a = adj[i] + (m == n ? 1.0f : 0.0f);
    float v = g_dinv[m] * a * g_dinv[n];
    bf16 h, l; sp2(v, h, l);
    g_Ahi[i] = h; g_Alo[i] = l;
}

// ========== N=128 pipeline machinery (2-product: A hi only) ==========
// Per buffer (stride 14848): A 128x16 s24 @0 (6144) | Bh 16x128 s136 @6144 (4352) | Bl @10496

// ---------------- A2 = Ahat @ Ahat (2-product), writes A2 hi only ----------------
__global__ __launch_bounds__(256, 2) void k_asq() {
    __shared__ __align__(16) char sm[2*14848];
    int tid = threadIdx.x, lane = tid & 31, wid = tid >> 5;
    int wm = wid & 3, wn = wid >> 2;
    int m0 = blockIdx.x * 128, n0 = blockIdx.y * 128;
    uint32_t sb = smem_u32(sm);
    int sr = tid >> 1, sc = (tid & 1)*8;
    int bk = tid >> 4, bn = (tid & 15)*8;

    auto stage = [&](int kc, int b) {
        uint32_t base = sb + b*14848;
        int k0 = kc*16;
        CP16(base + (sr*24 + sc)*2, &g_Ahi[(m0 + sr)*Nv + k0 + sc]);
        int g2 = (k0 + bk)*Nv + n0 + bn;
        uint32_t bo = base + 6144 + (bk*136 + bn)*2;
        CP16(bo,        &g_Ahi[g2]);
        CP16(bo + 4352, &g_Alo[g2]);
    };

    float acc[2][8][4] = {};
    int arow = wm*32 + (lane & 15), acol = (lane >> 4)*8;
    int brow = lane & 15, bsel = (lane >> 4)*8;

    stage(0, 0); CP_COMMIT();
    for (int kc = 0; kc < 32; kc++) {
        if (kc + 1 < 32) { stage(kc+1, (kc+1)&1); CP_COMMIT(); CP_WAIT1(); }
        else             { CP_WAIT0(); }
        __syncthreads();
        uint32_t base = sb + (kc&1)*14848;
        uint32_t aH[2][4], bH[4][4], bL[4][4];
        #pragma unroll
        for (int mi = 0; mi < 2; mi++)
            LDMX4(aH[mi], base + ((arow + mi*16)*24 + acol)*2);
        #pragma unroll
        for (int nj = 0; nj < 4; nj++) {
            uint32_t off = (brow*136 + wn*64 + nj*16 + bsel)*2;
            LDMX4T(bH[nj], base + 6144 + off);
            LDMX4T(bL[nj], base + 10496 + off);
        }
        #pragma unroll
        for (int mi = 0; mi < 2; mi++)
            #pragma unroll
            for (int ni = 0; ni < 8; ni++) {
                MMA_BF16(acc[mi][ni], aH[mi], &bH[ni>>1][(ni&1)*2]);
                MMA_BF16(acc[mi][ni], aH[mi], &bL[ni>>1][(ni&1)*2]);
            }
        __syncthreads();
    }
    int r = lane >> 2, cb = (lane & 3)*2;
    #pragma unroll
    for (int mi = 0; mi < 2; mi++)
        #pragma unroll
        for (int ni = 0; ni < 8; ni++) {
            int m = m0 + wm*32 + mi*16 + r;
            int n = n0 + wn*64 + ni*8 + cb;
            *(__nv_bfloat162*)&g_A2h[m*Nv + n] =
                __nv_bfloat162(__float2bfloat16(acc[mi][ni][0]), __float2bfloat16(acc[mi][ni][1]));
            *(__nv_bfloat162*)&g_A2h[(m+8)*Nv + n] =
                __nv_bfloat162(__float2bfloat16(acc[mi][ni][2]), __float2bfloat16(acc[mi][ni][3]));
        }
}

// ---------------- input / weight splits ----------------
__global__ __launch_bounds__(256) void k_splitx(const float* __restrict__ x) {
    int i = (blockIdx.x * 256 + threadIdx.x) * 4;
    float4 v = *(const float4*)&x[i];
    *(__nv_bfloat162*)&g_xh[i]   = __nv_bfloat162(__float2bfloat16(v.x), __float2bfloat16(v.y));
    *(__nv_bfloat162*)&g_xh[i+2] = __nv_bfloat162(__float2bfloat16(v.z), __float2bfloat16(v.w));
}

__global__ __launch_bounds__(256) void k_splitw(
    const float* __restrict__ Wq, const float* __restrict__ Wk,
    const float* __restrict__ Wv, const float* __restrict__ Wo,
    const float* __restrict__ gcW, const float* __restrict__ W1,
    const float* __restrict__ W2) {
    int i = blockIdx.x * 256 + threadIdx.x;
    const float* src; bf16 *dh, *dl; int off;
    if      (i < 4096)  { src = Wq;  dh = g_Wqh;  dl = g_Wql;  off = i; }
    else if (i < 8192)  { src = Wk;  dh = g_Wkh;  dl = g_Wkl;  off = i - 4096; }
    else if (i < 12288) { src = Wv;  dh = g_Wvh;  dl = g_Wvl;  off = i - 8192; }
    else if (i < 16384) { src = Wo;  dh = g_Woh;  dl = g_Wol;  off = i - 12288; }
    else if (i < 28672) { src = gcW; dh = g_gcWh; dl = g_gcWl; off = i - 16384; }
    else if (i < 45056) { src = W1;  dh = g_W1h;  dl = g_W1l;  off = i - 28672; }
    else if (i < 61440) { src = W2;  dh = g_W2h;  dl = g_W2l;  off = i - 45056; }
    else return;
    bf16 h, l; sp2(src[off], h, l);
    dh[off] = h; dl[off] = l;
}

// ---------------- merged QKV (2-product): x @ {Wq,Wk,Wv} + bias -> f32 q/k/v ----------------
// smem: sA [128*40] @0 (10240) | 3x {Bh(4608),Bl(4608)} @10240 -> total 37888
__global__ __launch_bounds__(256) void k_qkv_mma(const float* __restrict__ bq,
                                                 const float* __restrict__ bk,
                                                 const float* __restrict__ bv) {
    __shared__ __align__(16) char sm[37888];
    int tid = threadIdx.x, lane = tid & 31, wid = tid >> 5;
    int wm = wid & 3, wn = wid >> 2;
    int r0g = blockIdx.x * 128;
    uint32_t sb = smem_u32(sm);

    const bf16* Wh[3] = {g_Wqh, g_Wkh, g_Wvh};
    const bf16* Wl[3] = {g_Wql, g_Wkl, g_Wvl};
    const float* bias[3] = {bq, bk, bv};
    float* outp[3] = {g_q, g_k, g_v};

    float acc[3][2][4][4] = {};
    int arow = wm*32 + (lane & 15);
    int acolL = (lane >> 4)*8;
    int brow = lane & 15, bsel = (lane >> 4)*8;

    #pragma unroll
    for (int kc = 0; kc < 2; kc++) {
        stage_A1(sm, g_xh, r0g, 64, kc*32, tid);
        {
            int k = tid >> 3, n8 = (tid & 7)*8;
            #pragma unroll
            for (int s = 0; s < 3; s++) {
                uint32_t bo = sb + 10240 + s*9216 + (k*72 + n8)*2;
                int gi = (kc*32 + k)*64 + n8;
                CP16(bo,        &Wh[s][gi]);
                CP16(bo + 4608, &Wl[s][gi]);
            }
        }
        CP_COMMIT(); CP_WAIT0();
        __syncthreads();
        #pragma unroll
        for (int ks = 0; ks < 2; ks++) {
            uint32_t aH[2][4];
            int acol = ks*16 + acolL;
            #pragma unroll
            for (int mi = 0; mi < 2; mi++)
                LDMX4(aH[mi], sb + ((arow + mi*16)*40 + acol)*2);
            #pragma unroll
            for (int s = 0; s < 3; s++) {
                uint32_t bH[2][4], bL[2][4];
                #pragma unroll
                for (int nj = 0; nj < 2; nj++) {
                    uint32_t off = ((ks*16 + brow)*72 + wn*32 + nj*16 + bsel)*2;
                    LDMX4T(bH[nj], sb + 10240 + s*9216 + off);
                    LDMX4T(bL[nj], sb + 10240 + s*9216 + 4608 + off);
                }
                #pragma unroll
                for (int mi = 0; mi < 2; mi++)
                    #pragma unroll
                    for (int ni = 0; ni < 4; ni++) {
                        MMA_BF16(acc[s][mi][ni], aH[mi], &bH[ni>>1][(ni&1)*2]);
                        MMA_BF16(acc[s][mi][ni], aH[mi], &bL[ni>>1][(ni&1)*2]);
                    }
            }
        }
        __syncthreads();
    }
    int r = lane >> 2, cb = (lane & 3)*2;
    #pragma unroll
    for (int s = 0; s < 3; s++)
        #pragma unroll
        for (int mi = 0; mi < 2; mi++)
            #pragma unroll
            for (int ni = 0; ni < 4; ni++) {
                int m = r0g + wm*32 + mi*16 + r;
                int n = wn*32 + ni*8 + cb;
                float b0 = bias[s][n], b1 = bias[s][n+1];
                *(float2*)&outp[s][m*64 + n]     = make_float2(acc[s][mi][ni][0] + b0, acc[s][mi][ni][1] + b1);
                *(float2*)&outp[s][(m+8)*64 + n] = make_float2(acc[s][mi][ni][2] + b0, acc[s][mi][ni][3] + b1);
            }
}

// ---------------- temporal attention -> att hi ----------------
__global__ __launch_bounds__(256) void k_attn() {
    __shared__ __align__(16) float sqT[64*28];
    __shared__ __align__(16) float skT[64*28];
    __shared__ __align__(16) float sv[Tv*64];
    __shared__ __align__(16) float so[Tv*64];
    __shared__ __align__(16) float ss[Hv*Tv*25];
    int tid = threadIdx.x;
    int n = blockIdx.x, b = blockIdx.y;
    for (int i = tid; i < Tv*64; i += 256) {
        int t = i >> 6, d = i & 63;
        int gidx = ((b*Tv + t)*Nv + n)*64 + d;
        sqT[d*28 + t] = g_q[gidx];
        skT[d*28 + t] = g_k[gidx];
        sv[i]         = g_v[gidx];
    }
    __syncthreads();
    if (tid < Hv*36) {
        int h = tid / 36, blk = tid % 36;
        int tq0 = (blk / 6) * 4, tk0 = (blk % 6) * 4;
        float s[4][4] = {};
        const float* qb = &sqT[h*HDv*28];
        const float* kb = &skT[h*HDv*28];
        #pragma unroll
        for (int e = 0; e < HDv; e++) {
            float4 q4 = *(const float4*)(qb + e*28 + tq0);
            float4 k4 = *(const float4*)(kb + e*28 + tk0);
            float qa[4] = {q4.x, q4.y, q4.z, q4.w};
            float ka[4] = {k4.x, k4.y, k4.z, k4.w};
            #pragma unroll
            for (int i = 0; i < 4; i++)
                #pragma unroll
                for (int j = 0; j < 4; j++)
                    s[i][j] = fmaf(qa[i], ka[j], s[i][j]);
        }
        #pragma unroll
        for (int i = 0; i < 4; i++)
            #pragma unroll
            for (int j = 0; j < 4; j++)
                ss[(h*Tv + tq0 + i)*25 + tk0 + j] = s[i][j] * 0.25f;
    }
    __syncthreads();
    if (tid < Hv*Tv) {
        float* row = &ss[tid*25];
        float mx = -1e30f;
        #pragma unroll
        for (int tk = 0; tk < Tv; tk++) mx = fmaxf(mx, row[tk]);
        float sum = 0.f;
        #pragma unroll
        for (int tk = 0; tk < Tv; tk++) { float e = expf(row[tk]-mx); row[tk] = e; sum += e; }
        float inv = 1.0f / sum;
        #pragma unroll
        for (int tk = 0; tk < Tv; tk++) row[tk] *= inv;
    }
    __syncthreads();
    if (tid < Hv*24) {
        int h = tid / 24, blk = tid % 24;
        int tq0 = (blk / 4) * 4, e0 = (blk % 4) * 4;
        float o[4][4] = {};
        #pragma unroll
        for (int tk = 0; tk < Tv; tk++) {
            float4 v4 = *(const float4*)&sv[tk*64 + h*HDv + e0];
            float va[4] = {v4.x, v4.y, v4.z, v4.w};
            float pa[4];
            #pragma unroll
            for (int i = 0; i < 4; i++) pa[i] = ss[(h*Tv + tq0 + i)*25 + tk];
            #pragma unroll
            for (int i = 0; i < 4; i++)
                #pragma unroll
                for (int j = 0; j < 4; j++)
                    o[i][j] = fmaf(pa[i], va[j], o[i][j]);
        }
        #pragma unroll
        for (int i = 0; i < 4; i++)
            *(float4*)&so[(tq0 + i)*64 + h*HDv + e0] =
                make_float4(o[i][0], o[i][1], o[i][2], o[i][3]);
    }
    __syncthreads();
    for (int i = tid; i < Tv*64; i += 256) {
        int t = i >> 6, d = i & 63;
        g_atth[((b*Tv + t)*Nv + n)*64 + d] = __float2bfloat16(so[i]);
    }
}

// ---------------- attnout (2-product): att @ Wo + bo + x -> LN -> g_h (f32 + hi/lo) ----
__global__ __launch_bounds__(256) void k_attnout_mma(const float* __restrict__ x,
    const float* __restrict__ bo,
    const float* __restrict__ gt, const float* __restrict__ bt) {
    __shared__ __align__(16) char sm[SMEM_BYTES];
    int tid = threadIdx.x, lane = tid & 31, wid = tid >> 5;
    int wm = wid & 3, wn = wid >> 2;
    int r0g = blockIdx.x * 128;

    float acc[2][4][4] = {};
    #pragma unroll
    for (int kc = 0; kc < 2; kc++) {
        stage_A1(sm, g_atth, r0g, 64, kc*32, tid);
        stage_B1(sm, g_Woh, g_Wol, 64, 0, kc*32, tid);
        CP_COMMIT(); CP_WAIT0();
        __syncthreads();
        mma_compute2(sm, acc, lane, wm, wn);
        __syncthreads();
    }
    float* sO = (float*)sm;
    int r = lane >> 2, cb = (lane & 3)*2;
    #pragma unroll
    for (int mi = 0; mi < 2; mi++)
        #pragma unroll
        for (int ni = 0; ni < 4; ni++) {
            int m = wm*32 + mi*16 + r;
            int n = wn*32 + ni*8 + cb;
            float b0 = bo[n], b1 = bo[n+1];
            float2 x0 = *(const float2*)&x[(r0g + m)*64 + n];
            float2 x1 = *(const float2*)&x[(r0g + m + 8)*64 + n];
            *(float2*)&sO[m*64 + n]     = make_float2(acc[mi][ni][0] + b0 + x0.x, acc[mi][ni][1] + b1 + x0.y);
            *(float2*)&sO[(m+8)*64 + n] = make_float2(acc[mi][ni][2] + b0 + x1.x, acc[mi][ni][3] + b1 + x1.y);
        }
    __syncthreads();
    ln256(sO, r0g, gt, bt, g_h, g_hh, g_hl);   // h-lo kept: prop's B side
}

// ---------------- prop2 (2-product): p1 = Ahat@h, p2 = A2@h ; hi-only out ----------------
__global__ __launch_bounds__(256, 2) void k_prop2() {
    __shared__ __align__(16) char sm[2*14848];
    int tid = threadIdx.x, lane = tid & 31, wid = tid >> 5;
    int wm = wid & 3, wn = wid >> 2;
    int my = blockIdx.x, btp = blockIdx.y;
    const bf16* __restrict__ Ah_ = my < 4 ? g_Ahi : g_A2h;
    bf16* __restrict__ outh = my < 4 ? g_p1h : g_p2h;
    int m0 = (my & 3) * 128;
    uint32_t sb = smem_u32(sm);

    int sr = tid >> 1, sc = (tid & 1)*8;
    int bk = tid >> 4, bn = (tid & 15)*8;
    int bth = bn >> 6, bd = bn & 63;

    auto stage = [&](int kc, int b) {
        uint32_t base = sb + b*14848;
        int k0 = kc*16;
        CP16(base + (sr*24 + sc)*2, &Ah_[(m0 + sr)*Nv + k0 + sc]);
        int g2 = ((btp*2 + bth)*Nv + k0 + bk)*64 + bd;
        uint32_t bo = base + 6144 + (bk*136 + bn)*2;
        CP16(bo,        &g_hh[g2]);
        CP16(bo + 4352, &g_hl[g2]);
    };

    float acc[2][8][4] = {};
    int arow = wm*32 + (lane & 15), acol = (lane >> 4)*8;
    int brow = lane & 15, bsel = (lane >> 4)*8;

    stage(0, 0); CP_COMMIT();
    for (int kc = 0; kc < 32; kc++) {
        if (kc + 1 < 32) { stage(kc+1, (kc+1)&1); CP_COMMIT(); CP_WAIT1(); }
        else             { CP_WAIT0(); }
        __syncthreads();
        uint32_t base = sb + (kc&1)*14848;
        uint32_t aH[2][4], bH[4][4], bL[4][4];
        #pragma unroll
        for (int mi = 0; mi < 2; mi++)
            LDMX4(aH[mi], base + ((arow + mi*16)*24 + acol)*2);
        #pragma unroll
        for (int nj = 0; nj < 4; nj++) {
            uint32_t off = (brow*136 + wn*64 + nj*16 + bsel)*2;
            LDMX4T(bH[nj], base + 6144 + off);
            LDMX4T(bL[nj], base + 10496 + off);
        }
        #pragma unroll
        for (int mi = 0; mi < 2; mi++)
            #pragma unroll
            for (int ni = 0; ni < 8; ni++) {
                MMA_BF16(acc[mi][ni], aH[mi], &bH[ni>>1][(ni&1)*2]);
                MMA_BF16(acc[mi][ni], aH[mi], &bL[ni>>1][(ni&1)*2]);
            }
        __syncthreads();
    }
    int r = lane >> 2, cb = (lane & 3)*2;
    #pragma unroll
    for (int mi = 0; mi < 2; mi++)
        #pragma unroll
        for (int ni = 0; ni < 8; ni++) {
            int m = m0 + wm*32 + mi*16 + r;
            int nn = wn*64 + ni*8 + cb;
            int bt = btp*2 + (nn >> 6);
            int d = nn & 63;
            *(__nv_bfloat162*)&outh[(bt*Nv + m)*64 + d] =
                __nv_bfloat162(__float2bfloat16(acc[mi][ni][0]), __float2bfloat16(acc[mi][ni][1]));
            *(__nv_bfloat162*)&outh[(bt*Nv + m + 8)*64 + d] =
                __nv_bfloat162(__float2bfloat16(acc[mi][ni][2]), __float2bfloat16(acc[mi][ni][3]));
        }
}

// ---------------- gc (2-product): h@W0 + p1@W1 + p2@W2 + bias + h -> LN -> g_h2 ----
__global__ __launch_bounds__(256) void k_gc_mma(const float* __restrict__ gcb,
    const float* __restrict__ gg, const float* __restrict__ bg) {
    __shared__ __align__(16) char sm[SMEM_BYTES];
    int tid = threadIdx.x, lane = tid & 31, wid = tid >> 5;
    int wm = wid & 3, wn = wid >> 2;
    int r0g = blockIdx.x * 128;

    float acc[2][4][4] = {};
    const bf16* ih[3] = {g_hh, g_p1h, g_p2h};
    #pragma unroll
    for (int mm = 0; mm < 3; mm++)
        #pragma unroll
        for (int kc = 0; kc < 2; kc++) {
            stage_A1(sm, ih[mm], r0g, 64, kc*32, tid);
            stage_B1(sm, g_gcWh + mm*4096, g_gcWl + mm*4096, 64, 0, kc*32, tid);
            CP_COMMIT(); CP_WAIT0();
            __syncthreads();
            mma_compute2(sm, acc, lane, wm, wn);
            __syncthreads();
        }
    float* sO = (float*)sm;
    int r = lane >> 2, cb = (lane & 3)*2;
    #pragma unroll
    for (int mi = 0; mi < 2; mi++)
        #pragma unroll
        for (int ni = 0; ni < 4; ni++) {
            int m = wm*32 + mi*16 + r;
            int n = wn*32 + ni*8 + cb;
            float b0 = gcb[n] + gcb[64+n] + gcb[128+n];
            float b1 = gcb[n+1] + gcb[64+n+1] + gcb[128+n+1];
            float2 h0 = *(const float2*)&g_h[(r0g + m)*64 + n];
            float2 h1 = *(const float2*)&g_h[(r0g + m + 8)*64 + n];
            *(float2*)&sO[m*64 + n]     = make_float2(acc[mi][ni][0] + b0 + h0.x, acc[mi][ni][1] + b1 + h0.y);
            *(float2*)&sO[(m+8)*64 + n] = make_float2(acc[mi][ni][2] + b0 + h1.x, acc[mi][ni][3] + b1 + h1.y);
        }
    __syncthreads();
    ln256(sO, r0g, gg, bg, g_h2, g_h2h, (bf16*)0);
}

// ---------------- ffn1 (2-product): gelu(h2 @ W1 + b1) -> u hi ----------------
__global__ __launch_bounds__(256) void k_ffn1_mma(const float* __restrict__ b1) {
    __shared__ __align__(16) char sm[SMEM_BYTES];
    int tid = threadIdx.x, lane = tid & 31, wid = tid >> 5;
    int wm = wid & 3, wn = wid >> 2;
    int r0g = blockIdx.x * 128;
    int c0g = blockIdx.y * 64;

    float acc[2][4][4] = {};
    #pragma unroll
    for (int kc = 0; kc < 2; kc++) {
        stage_A1(sm, g_h2h, r0g, 64, kc*32, tid);
        stage_B1(sm, g_W1h, g_W1l, Fv, c0g, kc*32, tid);
        CP_COMMIT(); CP_WAIT0();
        __syncthreads();
        mma_compute2(sm, acc, lane, wm, wn);
        __syncthreads();
    }
    int r = lane >> 2, cb = (lane & 3)*2;
    #pragma unroll
    for (int mi = 0; mi < 2; mi++)
        #pragma unroll
        for (int ni = 0; ni < 4; ni++) {
            int m = r0g + wm*32 + mi*16 + r;
            int n = wn*32 + ni*8 + cb;
            float b0 = b1[c0g + n], b1v = b1[c0g + n + 1];
            float v[4] = {acc[mi][ni][0] + b0, acc[mi][ni][1] + b1v,
                          acc[mi][ni][2] + b0, acc[mi][ni][3] + b1v};
            #pragma unroll
            for (int j = 0; j < 4; j++)
                v[j] = 0.5f * v[j] * (1.0f + erff(v[j] * 0.70710678118654752f));
            *(__nv_bfloat162*)&g_uh[m*Fv + c0g + n] =
                __nv_bfloat162(__float2bfloat16(v[0]), __float2bfloat16(v[1]));
            *(__nv_bfloat162*)&g_uh[(m+8)*Fv + c0g + n] =
                __nv_bfloat162(__float2bfloat16(v[2]), __float2bfloat16(v[3]));
        }
}

// ---------------- ffn2 (2-product): u @ W2 + b2 + h2 -> LN -> out ----------------
__global__ __launch_bounds__(256) void k_ffn2_mma(const float* __restrict__ b2,
    const float* __restrict__ gf, const float* __restrict__ bf,
    float* __restrict__ out) {
    __shared__ __align__(16) char sm[SMEM_BYTES];
    int tid = threadIdx.x, lane = tid & 31, wid = tid >> 5;
    int wm = wid & 3, wn = wid >> 2;
    int r0g = blockIdx.x * 128;

    float acc[2][4][4] = {};
    #pragma unroll
    for (int kc = 0; kc < 8; kc++) {
        stage_A1(sm, g_uh, r0g, Fv, kc*32, tid);
        stage_B1(sm, g_W2h, g_W2l, 64, 0, kc*32, tid);
        CP_COMMIT(); CP_WAIT0();
        __syncthreads();
        mma_compute2(sm, acc, lane, wm, wn);
        __syncthreads();
    }
    float* sO = (float*)sm;
    int r = lane >> 2, cb = (lane & 3)*2;
    #pragma unroll
    for (int mi = 0; mi < 2; mi++)
        #pragma unroll
        for (int ni = 0; ni < 4; ni++) {
            int m = wm*32 + mi*16 + r;
            int n = wn*32 + ni*8 + cb;
            float b0 = b2[n], b1 = b2[n+1];
            float2 h0 = *(const float2*)&g_h2[(r0g + m)*64 + n];
            float2 h1 = *(const float2*)&g_h2[(r0g + m + 8)*64 + n];
            *(float2*)&sO[m*64 + n]     = make_float2(acc[mi][ni][0] + b0 + h0.x, acc[mi][ni][1] + b1 + h0.y);
            *(float2*)&sO[(m+8)*64 + n] = make_float2(acc[mi][ni][2] + b0 + h1.x, acc[mi][ni][3] + b1 + h1.y);
        }
    __syncthreads();
    ln256(sO, r0g, gf, bf, out, (bf16*)0, (bf16*)0);
}

// ---------------- launch ----------------
extern "C" void kernel_launch(void* const* d_in, const int* in_sizes, int n_in,
                              void* d_out, int out_size) {
    const float* x   = (const float*)d_in[0];
    const float* adj = (const float*)d_in[1];
    const float* bq  = (const float*)d_in[3];
    const float* bk  = (const float*)d_in[5];
    const float* bv  = (const float*)d_in[7];
    const float* bo  = (const float*)d_in[9];
    const float* gcb = (const float*)d_in[11];
    const float* b1  = (const float*)d_in[13];
    const float* b2  = (const float*)d_in[15];
    const float* g_t = (const float*)d_in[16];
    const float* b_t = (const float*)d_in[17];
    const float* g_g = (const float*)d_in[18];
    const float* b_g = (const float*)d_in[19];
    const float* g_f = (const float*)d_in[20];
    const float* b_f = (const float*)d_in[21];
    float* out = (float*)d_out;

    k_deg   <<<Nv, 128>>>(adj);
    k_ahat  <<<(Nv*Nv)/512, 512>>>(adj);
    k_asq   <<<dim3(4, 4), 256>>>();
    k_splitx<<<(BTNv*Dv)/1024, 256>>>(x);
    k_splitw<<<240, 256>>>((const float*)d_in[2], (const float*)d_in[4],
                           (const float*)d_in[6], (const float*)d_in[8],
                           (const float*)d_in[10], (const float*)d_in[12],
                           (const float*)d_in[14]);
    k_qkv_mma<<<RT128, 256>>>(bq, bk, bv);
    k_attn  <<<dim3(Nv, Bv), 256>>>();
    k_attnout_mma<<<RT128, 256>>>(x, bo, g_t, b_t);
    k_prop2 <<<dim3(8, 192), 256>>>();
    k_gc_mma<<<RT128, 256>>>(gcb, g_g, b_g);
    k_ffn1_mma<<<dim3(RT128, Fv/64), 256>>>(b1);
    k_ffn2_mma<<<RT128, 256>>>(b2, g_f, b_f, out);
}

// round 16
// speedup vs baseline: 3.3200x; 1.0179x over previous
#include <cuda_runtime.h>
#include <cuda_bf16.h>
#include <math.h>
#include <cstdint>

#define Bv   16
#define Tv   24
#define Nv   512
#define Dv   64
#define Hv   4
#define HDv  16
#define Fv   256
#define BTv  (Bv*Tv)           // 384
#define BTNv (BTv*Nv)          // 196608
#define RT128 (BTNv/128)       // 1536

typedef unsigned long long ull;
typedef __nv_bfloat16 bf16;

// ---------------- scratch (static device globals; no allocation) ----------------
__device__ float g_dinv[Nv];
__device__ float g_q  [BTNv*Dv];
__device__ float g_k  [BTNv*Dv];
__device__ float g_v  [BTNv*Dv];
__device__ float g_h  [BTNv*Dv];
__device__ float g_h2 [BTNv*Dv];
// bf16 buffers (lo kept only where a consumer's B-side needs it)
__device__ bf16 g_Ahi[Nv*Nv],     g_Alo[Nv*Nv];
__device__ bf16 g_A2h[Nv*Nv];
__device__ bf16 g_xh [BTNv*Dv];
__device__ bf16 g_atth[BTNv*Dv];
__device__ bf16 g_hh [BTNv*Dv],   g_hl [BTNv*Dv];   // h-lo needed by prop (B side)
__device__ bf16 g_p1h[BTNv*Dv];
__device__ bf16 g_p2h[BTNv*Dv];
__device__ bf16 g_h2h[BTNv*Dv];
__device__ bf16 g_uh [BTNv*Fv];
// weight splits (hi+lo, B side of their GEMMs)
__device__ bf16 g_Wqh[4096], g_Wql[4096];
__device__ bf16 g_Wkh[4096], g_Wkl[4096];
__device__ bf16 g_Wvh[4096], g_Wvl[4096];
__device__ bf16 g_Woh[4096], g_Wol[4096];
__device__ bf16 g_gcWh[3*4096], g_gcWl[3*4096];
__device__ bf16 g_W1h[64*Fv], g_W1l[64*Fv];
__device__ bf16 g_W2h[Fv*64], g_W2l[Fv*64];

// ================= mma.sync / cp.async helpers =================
__device__ __forceinline__ uint32_t smem_u32(const void* p) {
    uint32_t a;
    asm("{ .reg .u64 t; cvta.to.shared.u64 t, %1; cvt.u32.u64 %0, t; }" : "=r"(a) : "l"(p));
    return a;
}
#define LDMX4(r, addr) \
    asm volatile("ldmatrix.sync.aligned.m8n8.x4.shared.b16 {%0,%1,%2,%3}, [%4];" \
        : "=r"((r)[0]), "=r"((r)[1]), "=r"((r)[2]), "=r"((r)[3]) : "r"(addr))
#define LDMX4T(r, addr) \
    asm volatile("ldmatrix.sync.aligned.m8n8.x4.trans.shared.b16 {%0,%1,%2,%3}, [%4];" \
        : "=r"((r)[0]), "=r"((r)[1]), "=r"((r)[2]), "=r"((r)[3]) : "r"(addr))
#define LDMX2T(r, addr) \
    asm volatile("ldmatrix.sync.aligned.m8n8.x2.trans.shared.b16 {%0,%1}, [%2];" \
        : "=r"((r)[0]), "=r"((r)[1]) : "r"(addr))
#define MMA_BF16(d, a, b) \
    asm volatile("mma.sync.aligned.m16n8k16.row.col.f32.bf16.bf16.f32 " \
        "{%0,%1,%2,%3}, {%4,%5,%6,%7}, {%8,%9}, {%0,%1,%2,%3};" \
        : "+f"((d)[0]), "+f"((d)[1]), "+f"((d)[2]), "+f"((d)[3]) \
        : "r"((a)[0]), "r"((a)[1]), "r"((a)[2]), "r"((a)[3]), \
          "r"((b)[0]), "r"((b)[1]))
#define CP16(saddr, gptr) \
    asm volatile("cp.async.ca.shared.global [%0], [%1], 16;" :: "r"(saddr), "l"(gptr))
#define CP_COMMIT() asm volatile("cp.async.commit_group;" ::: "memory")
#define CP_WAIT0()  asm volatile("cp.async.wait_group 0;" ::: "memory")
#define CP_WAIT1()  asm volatile("cp.async.wait_group 1;" ::: "memory")

__device__ __forceinline__ void sp2(float x, bf16& h, bf16& l) {
    h = __float2bfloat16(x);
    l = __float2bfloat16(x - __bfloat162float(h));
}

// ---- double-buffered 2-product layout ----
// per buffer (stride 19456): sA [128x32 hi, s40] @0 (10240) | sBh [32x64, s72] @10240 (4608) | sBl @14848
// sO [128*64] f32 @0 (32768) -- aliases both buffers, used only after staging dead
#define DB_STRIDE 19456
#define DB_BYTES  38912

__device__ __forceinline__ void db_stageA(uint32_t base, const bf16* __restrict__ gh,
                                          int rowBase, int ldA, int k0, int tid) {
    #pragma unroll
    for (int i = tid; i < 512; i += 256) {
        int r = i >> 2, c8 = (i & 3) * 8;
        CP16(base + (r*40 + c8)*2, &gh[(rowBase + r)*ldA + k0 + c8]);
    }
}
__device__ __forceinline__ void db_stageB(uint32_t base, const bf16* __restrict__ gh,
                                          const bf16* __restrict__ gl,
                                          int ldB, int colBase, int k0, int tid) {
    int k = tid >> 3, n8 = (tid & 7) * 8;
    int gi = (k0 + k)*ldB + colBase + n8;
    uint32_t off = (k*72 + n8)*2;
    CP16(base + 10240 + off, &gh[gi]);
    CP16(base + 14848 + off, &gl[gi]);
}
__device__ __forceinline__ void db_compute(uint32_t base, float acc[2][4][4],
                                           int lane, int wm, int wn) {
    uint32_t baseBh = base + 10240, baseBl = base + 14848;
    int arow = wm*32 + (lane & 15);
    int acolL = (lane >> 4) * 8;
    int brow = lane & 15;
    int bcol = wn*32;
    #pragma unroll
    for (int ks = 0; ks < 2; ks++) {
        uint32_t aH[2][4], bH[4][2], bL[4][2];
        int acol = ks*16 + acolL;
        #pragma unroll
        for (int mi = 0; mi < 2; mi++)
            LDMX4(aH[mi], base + ((arow + mi*16)*40 + acol)*2);
        #pragma unroll
        for (int ni = 0; ni < 4; ni++) {
            uint32_t off = ((ks*16 + brow)*72 + bcol + ni*8)*2;
            LDMX2T(bH[ni], baseBh + off);
            LDMX2T(bL[ni], baseBl + off);
        }
        #pragma unroll
        for (int mi = 0; mi < 2; mi++)
            #pragma unroll
            for (int ni = 0; ni < 4; ni++) {
                MMA_BF16(acc[mi][ni], aH[mi], bH[ni]);
                MMA_BF16(acc[mi][ni], aH[mi], bL[ni]);
            }
    }
}

// 256-thread LN over sO[128][64]; outl may be null (hi-only emit)
__device__ __forceinline__ void ln256(const float* sO, int r0g,
                                      const float* __restrict__ g,
                                      const float* __restrict__ b,
                                      float* outf, bf16* outh, bf16* outl) {
    int wid = threadIdx.x >> 5, lane = threadIdx.x & 31;
    float gg0 = g[lane], gg1 = g[lane + 32];
    float bb0 = b[lane], bb1 = b[lane + 32];
    for (int r = wid; r < 128; r += 8) {
        float v0 = sO[r*64 + lane];
        float v1 = sO[r*64 + lane + 32];
        float s = v0 + v1;
        #pragma unroll
        for (int o = 16; o; o >>= 1) s += __shfl_xor_sync(0xffffffffu, s, o);
        float m = s * (1.0f/64.0f);
        float d0 = v0 - m, d1 = v1 - m;
        float vs = d0*d0 + d1*d1;
        #pragma unroll
        for (int o = 16; o; o >>= 1) vs += __shfl_xor_sync(0xffffffffu, vs, o);
        float rs = rsqrtf(vs * (1.0f/64.0f) + 1e-5f);
        float o0 = d0*rs*gg0 + bb0;
        float o1 = d1*rs*gg1 + bb1;
        int gi0 = (r0g + r)*64 + lane, gi1 = gi0 + 32;
        if (outf) { outf[gi0] = o0; outf[gi1] = o1; }
        if (outh) {
            bf16 h0 = __float2bfloat16(o0);
            bf16 h1 = __float2bfloat16(o1);
            outh[gi0] = h0; outh[gi1] = h1;
            if (outl) {
                outl[gi0] = __float2bfloat16(o0 - __bfloat162float(h0));
                outl[gi1] = __float2bfloat16(o1 - __bfloat162float(h1));
            }
        }
    }
}

// ---------------- graph normalization ----------------
__global__ __launch_bounds__(128) void k_deg(const float* __restrict__ adj) {
    __shared__ float red[128];
    int m = blockIdx.x;
    float s = 0.f;
    for (int j = threadIdx.x; j < Nv; j += 128) s += adj[m*Nv + j];
    red[threadIdx.x] = s; __syncthreads();
    for (int o = 64; o; o >>= 1) {
        if (threadIdx.x < o) red[threadIdx.x] += red[threadIdx.x + o];
        __syncthreads();
    }
    if (threadIdx.x == 0) g_dinv[m] = rsqrtf(fmaxf(red[0] + 1.0f, 1e-12f));
}

__global__ __launch_bounds__(512) void k_ahat(const float* __restrict__ adj) {
    int i = blockIdx.x * 512 + threadIdx.x;
    int m = i >> 9, n = i & 511;
    float a = adj[i] + (m == n ? 1.0f : 0.0f);
    float v = g_dinv[m] * a * g_dinv[n];
    bf16 h, l; sp2(v, h, l);
    g_Ahi[i] = h; g_Alo[i] = l;
}

// ========== N=128 pipeline (2-product) ==========
// Per buffer (stride 14848): A 128x16 s24 @0 (6144) | Bh 16x128 s136 @6144 (4352) | Bl @10496

// ---------------- A2 = Ahat @ Ahat (2-product), A2 hi only ----------------
__global__ __launch_bounds__(256, 2) void k_asq() {
    __shared__ __align__(16) char sm[2*14848];
    int tid = threadIdx.x, lane = tid & 31, wid = tid >> 5;
    int wm = wid & 3, wn = wid >> 2;
    int m0 = blockIdx.x * 128, n0 = blockIdx.y * 128;
    uint32_t sb = smem_u32(sm);
    int sr = tid >> 1, sc = (tid & 1)*8;
    int bk = tid >> 4, bn = (tid & 15)*8;

    auto stage = [&](int kc, int b) {
        uint32_t base = sb + b*14848;
        int k0 = kc*16;
        CP16(base + (sr*24 + sc)*2, &g_Ahi[(m0 + sr)*Nv + k0 + sc]);
        int g2 = (k0 + bk)*Nv + n0 + bn;
        uint32_t bo = base + 6144 + (bk*136 + bn)*2;
        CP16(bo,        &g_Ahi[g2]);
        CP16(bo + 4352, &g_Alo[g2]);
    };

    float acc[2][8][4] = {};
    int arow = wm*32 + (lane & 15), acol = (lane >> 4)*8;
    int brow = lane & 15, bsel = (lane >> 4)*8;

    stage(0, 0); CP_COMMIT();
    for (int kc = 0; kc < 32; kc++) {
        if (kc + 1 < 32) { stage(kc+1, (kc+1)&1); CP_COMMIT(); CP_WAIT1(); }
        else             { CP_WAIT0(); }
        __syncthreads();
        uint32_t base = sb + (kc&1)*14848;
        uint32_t aH[2][4], bH[4][4], bL[4][4];
        #pragma unroll
        for (int mi = 0; mi < 2; mi++)
            LDMX4(aH[mi], base + ((arow + mi*16)*24 + acol)*2);
        #pragma unroll
        for (int nj = 0; nj < 4; nj++) {
            uint32_t off = (brow*136 + wn*64 + nj*16 + bsel)*2;
            LDMX4T(bH[nj], base + 6144 + off);
            LDMX4T(bL[nj], base + 10496 + off);
        }
        #pragma unroll
        for (int mi = 0; mi < 2; mi++)
            #pragma unroll
            for (int ni = 0; ni < 8; ni++) {
                MMA_BF16(acc[mi][ni], aH[mi], &bH[ni>>1][(ni&1)*2]);
                MMA_BF16(acc[mi][ni], aH[mi], &bL[ni>>1][(ni&1)*2]);
            }
        __syncthreads();
    }
    int r = lane >> 2, cb = (lane & 3)*2;
    #pragma unroll
    for (int mi = 0; mi < 2; mi++)
        #pragma unroll
        for (int ni = 0; ni < 8; ni++) {
            int m = m0 + wm*32 + mi*16 + r;
            int n = n0 + wn*64 + ni*8 + cb;
            *(__nv_bfloat162*)&g_A2h[m*Nv + n] =
                __nv_bfloat162(__float2bfloat16(acc[mi][ni][0]), __float2bfloat16(acc[mi][ni][1]));
            *(__nv_bfloat162*)&g_A2h[(m+8)*Nv + n] =
                __nv_bfloat162(__float2bfloat16(acc[mi][ni][2]), __float2bfloat16(acc[mi][ni][3]));
        }
}

// ---------------- input / weight splits ----------------
__global__ __launch_bounds__(256) void k_splitx(const float* __restrict__ x) {
    int i = (blockIdx.x * 256 + threadIdx.x) * 4;
    float4 v = *(const float4*)&x[i];
    *(__nv_bfloat162*)&g_xh[i]   = __nv_bfloat162(__float2bfloat16(v.x), __float2bfloat16(v.y));
    *(__nv_bfloat162*)&g_xh[i+2] = __nv_bfloat162(__float2bfloat16(v.z), __float2bfloat16(v.w));
}

__global__ __launch_bounds__(256) void k_splitw(
    const float* __restrict__ Wq, const float* __restrict__ Wk,
    const float* __restrict__ Wv, const float* __restrict__ Wo,
    const float* __restrict__ gcW, const float* __restrict__ W1,
    const float* __restrict__ W2) {
    int i = blockIdx.x * 256 + threadIdx.x;
    const float* src; bf16 *dh, *dl; int off;
    if      (i < 4096)  { src = Wq;  dh = g_Wqh;  dl = g_Wql;  off = i; }
    else if (i < 8192)  { src = Wk;  dh = g_Wkh;  dl = g_Wkl;  off = i - 4096; }
    else if (i < 12288) { src = Wv;  dh = g_Wvh;  dl = g_Wvl;  off = i - 8192; }
    else if (i < 16384) { src = Wo;  dh = g_Woh;  dl = g_Wol;  off = i - 12288; }
    else if (i < 28672) { src = gcW; dh = g_gcWh; dl = g_gcWl; off = i - 16384; }
    else if (i < 45056) { src = W1;  dh = g_W1h;  dl = g_W1l;  off = i - 28672; }
    else if (i < 61440) { src = W2;  dh = g_W2h;  dl = g_W2l;  off = i - 45056; }
    else return;
    bf16 h, l; sp2(src[off], h, l);
    dh[off] = h; dl[off] = l;
}

// ---------------- merged QKV (2-product, single-buffer) ----------------
// smem: sA [128*40] @0 (10240) | 3x {Bh(4608),Bl(4608)} @10240 -> total 37888
__global__ __launch_bounds__(256) void k_qkv_mma(const float* __restrict__ bq,
                                                 const float* __restrict__ bk,
                                                 const float* __restrict__ bv) {
    __shared__ __align__(16) char sm[37888];
    int tid = threadIdx.x, lane = tid & 31, wid = tid >> 5;
    int wm = wid & 3, wn = wid >> 2;
    int r0g = blockIdx.x * 128;
    uint32_t sb = smem_u32(sm);

    const bf16* Wh[3] = {g_Wqh, g_Wkh, g_Wvh};
    const bf16* Wl[3] = {g_Wql, g_Wkl, g_Wvl};
    const float* bias[3] = {bq, bk, bv};
    float* outp[3] = {g_q, g_k, g_v};

    float acc[3][2][4][4] = {};
    int arow = wm*32 + (lane & 15);
    int acolL = (lane >> 4)*8;
    int brow = lane & 15, bsel = (lane >> 4)*8;

    #pragma unroll
    for (int kc = 0; kc < 2; kc++) {
        db_stageA(sb, g_xh, r0g, 64, kc*32, tid);
        {
            int k = tid >> 3, n8 = (tid & 7)*8;
            #pragma unroll
            for (int s = 0; s < 3; s++) {
                uint32_t bo = sb + 10240 + s*9216 + (k*72 + n8)*2;
                int gi = (kc*32 + k)*64 + n8;
                CP16(bo,        &Wh[s][gi]);
                CP16(bo + 4608, &Wl[s][gi]);
            }
        }
        CP_COMMIT(); CP_WAIT0();
        __syncthreads();
        #pragma unroll
        for (int ks = 0; ks < 2; ks++) {
            uint32_t aH[2][4];
            int acol = ks*16 + acolL;
            #pragma unroll
            for (int mi = 0; mi < 2; mi++)
                LDMX4(aH[mi], sb + ((arow + mi*16)*40 + acol)*2);
            #pragma unroll
            for (int s = 0; s < 3; s++) {
                uint32_t bH[2][4], bL[2][4];
                #pragma unroll
                for (int nj = 0; nj < 2; nj++) {
                    uint32_t off = ((ks*16 + brow)*72 + wn*32 + nj*16 + bsel)*2;
                    LDMX4T(bH[nj], sb + 10240 + s*9216 + off);
                    LDMX4T(bL[nj], sb + 10240 + s*9216 + 4608 + off);
                }
                #pragma unroll
                for (int mi = 0; mi < 2; mi++)
                    #pragma unroll
                    for (int ni = 0; ni < 4; ni++) {
                        MMA_BF16(acc[s][mi][ni], aH[mi], &bH[ni>>1][(ni&1)*2]);
                        MMA_BF16(acc[s][mi][ni], aH[mi], &bL[ni>>1][(ni&1)*2]);
                    }
            }
        }
        __syncthreads();
    }
    int r = lane >> 2, cb = (lane & 3)*2;
    #pragma unroll
    for (int s = 0; s < 3; s++)
        #pragma unroll
        for (int mi = 0; mi < 2; mi++)
            #pragma unroll
            for (int ni = 0; ni < 4; ni++) {
                int m = r0g + wm*32 + mi*16 + r;
                int n = wn*32 + ni*8 + cb;
                float b0 = bias[s][n], b1 = bias[s][n+1];
                *(float2*)&outp[s][m*64 + n]     = make_float2(acc[s][mi][ni][0] + b0, acc[s][mi][ni][1] + b1);
                *(float2*)&outp[s][(m+8)*64 + n] = make_float2(acc[s][mi][ni][2] + b0, acc[s][mi][ni][3] + b1);
            }
}

// ---------------- temporal attention -> att hi ----------------
__global__ __launch_bounds__(256) void k_attn() {
    __shared__ __align__(16) float sqT[64*28];
    __shared__ __align__(16) float skT[64*28];
    __shared__ __align__(16) float sv[Tv*64];
    __shared__ __align__(16) float so[Tv*64];
    __shared__ __align__(16) float ss[Hv*Tv*25];
    int tid = threadIdx.x;
    int n = blockIdx.x, b = blockIdx.y;
    for (int i = tid; i < Tv*64; i += 256) {
        int t = i >> 6, d = i & 63;
        int gidx = ((b*Tv + t)*Nv + n)*64 + d;
        sqT[d*28 + t] = g_q[gidx];
        skT[d*28 + t] = g_k[gidx];
        sv[i]         = g_v[gidx];
    }
    __syncthreads();
    if (tid < Hv*36) {
        int h = tid / 36, blk = tid % 36;
        int tq0 = (blk / 6) * 4, tk0 = (blk % 6) * 4;
        float s[4][4] = {};
        const float* qb = &sqT[h*HDv*28];
        const float* kb = &skT[h*HDv*28];
        #pragma unroll
        for (int e = 0; e < HDv; e++) {
            float4 q4 = *(const float4*)(qb + e*28 + tq0);
            float4 k4 = *(const float4*)(kb + e*28 + tk0);
            float qa[4] = {q4.x, q4.y, q4.z, q4.w};
            float ka[4] = {k4.x, k4.y, k4.z, k4.w};
            #pragma unroll
            for (int i = 0; i < 4; i++)
                #pragma unroll
                for (int j = 0; j < 4; j++)
                    s[i][j] = fmaf(qa[i], ka[j], s[i][j]);
        }
        #pragma unroll
        for (int i = 0; i < 4; i++)
            #pragma unroll
            for (int j = 0; j < 4; j++)
                ss[(h*Tv + tq0 + i)*25 + tk0 + j] = s[i][j] * 0.25f;
    }
    __syncthreads();
    if (tid < Hv*Tv) {
        float* row = &ss[tid*25];
        float mx = -1e30f;
        #pragma unroll
        for (int tk = 0; tk < Tv; tk++) mx = fmaxf(mx, row[tk]);
        float sum = 0.f;
        #pragma unroll
        for (int tk = 0; tk < Tv; tk++) { float e = expf(row[tk]-mx); row[tk] = e; sum += e; }
        float inv = 1.0f / sum;
        #pragma unroll
        for (int tk = 0; tk < Tv; tk++) row[tk] *= inv;
    }
    __syncthreads();
    if (tid < Hv*24) {
        int h = tid / 24, blk = tid % 24;
        int tq0 = (blk / 4) * 4, e0 = (blk % 4) * 4;
        float o[4][4] = {};
        #pragma unroll
        for (int tk = 0; tk < Tv; tk++) {
            float4 v4 = *(const float4*)&sv[tk*64 + h*HDv + e0];
            float va[4] = {v4.x, v4.y, v4.z, v4.w};
            float pa[4];
            #pragma unroll
            for (int i = 0; i < 4; i++) pa[i] = ss[(h*Tv + tq0 + i)*25 + tk];
            #pragma unroll
            for (int i = 0; i < 4; i++)
                #pragma unroll
                for (int j = 0; j < 4; j++)
                    o[i][j] = fmaf(pa[i], va[j], o[i][j]);
        }
        #pragma unroll
        for (int i = 0; i < 4; i++)
            *(float4*)&so[(tq0 + i)*64 + h*HDv + e0] =
                make_float4(o[i][0], o[i][1], o[i][2], o[i][3]);
    }
    __syncthreads();
    for (int i = tid; i < Tv*64; i += 256) {
        int t = i >> 6, d = i & 63;
        g_atth[((b*Tv + t)*Nv + n)*64 + d] = __float2bfloat16(so[i]);
    }
}

// ---------------- attnout (2-product, db): att @ Wo + bo + x -> LN -> g_h ----------------
__global__ __launch_bounds__(256) void k_attnout_mma(const float* __restrict__ x,
    const float* __restrict__ bo,
    const float* __restrict__ gt, const float* __restrict__ bt) {
    __shared__ __align__(16) char sm[DB_BYTES];
    int tid = threadIdx.x, lane = tid & 31, wid = tid >> 5;
    int wm = wid & 3, wn = wid >> 2;
    int r0g = blockIdx.x * 128;
    uint32_t sb = smem_u32(sm);

    float acc[2][4][4] = {};
    db_stageA(sb, g_atth, r0g, 64, 0, tid);
    db_stageB(sb, g_Woh, g_Wol, 64, 0, 0, tid);
    CP_COMMIT();
    #pragma unroll
    for (int c = 0; c < 2; c++) {
        if (c + 1 < 2) {
            uint32_t nb = sb + DB_STRIDE;
            db_stageA(nb, g_atth, r0g, 64, 32, tid);
            db_stageB(nb, g_Woh, g_Wol, 64, 0, 32, tid);
            CP_COMMIT(); CP_WAIT1();
        } else CP_WAIT0();
        __syncthreads();
        db_compute(sb + (c&1)*DB_STRIDE, acc, lane, wm, wn);
        __syncthreads();
    }
    float* sO = (float*)sm;
    int r = lane >> 2, cb = (lane & 3)*2;
    #pragma unroll
    for (int mi = 0; mi < 2; mi++)
        #pragma unroll
        for (int ni = 0; ni < 4; ni++) {
            int m = wm*32 + mi*16 + r;
            int n = wn*32 + ni*8 + cb;
            float b0 = bo[n], b1 = bo[n+1];
            float2 x0 = *(const float2*)&x[(r0g + m)*64 + n];
            float2 x1 = *(const float2*)&x[(r0g + m + 8)*64 + n];
            *(float2*)&sO[m*64 + n]     = make_float2(acc[mi][ni][0] + b0 + x0.x, acc[mi][ni][1] + b1 + x0.y);
            *(float2*)&sO[(m+8)*64 + n] = make_float2(acc[mi][ni][2] + b0 + x1.x, acc[mi][ni][3] + b1 + x1.y);
        }
    __syncthreads();
    ln256(sO, r0g, gt, bt, g_h, g_hh, g_hl);   // h-lo kept: prop's B side
}

// ---------------- prop2 (2-product): p1 = Ahat@h, p2 = A2@h ; hi-only out ----------------
__global__ __launch_bounds__(256, 2) void k_prop2() {
    __shared__ __align__(16) char sm[2*14848];
    int tid = threadIdx.x, lane = tid & 31, wid = tid >> 5;
    int wm = wid & 3, wn = wid >> 2;
    int my = blockIdx.x, btp = blockIdx.y;
    const bf16* __restrict__ Ah_ = my < 4 ? g_Ahi : g_A2h;
    bf16* __restrict__ outh = my < 4 ? g_p1h : g_p2h;
    int m0 = (my & 3) * 128;
    uint32_t sb = smem_u32(sm);

    int sr = tid >> 1, sc = (tid & 1)*8;
    int bk = tid >> 4, bn = (tid & 15)*8;
    int bth = bn >> 6, bd = bn & 63;

    auto stage = [&](int kc, int b) {
        uint32_t base = sb + b*14848;
        int k0 = kc*16;
        CP16(base + (sr*24 + sc)*2, &Ah_[(m0 + sr)*Nv + k0 + sc]);
        int g2 = ((btp*2 + bth)*Nv + k0 + bk)*64 + bd;
        uint32_t bo = base + 6144 + (bk*136 + bn)*2;
        CP16(bo,        &g_hh[g2]);
        CP16(bo + 4352, &g_hl[g2]);
    };

    float acc[2][8][4] = {};
    int arow = wm*32 + (lane & 15), acol = (lane >> 4)*8;
    int brow = lane & 15, bsel = (lane >> 4)*8;

    stage(0, 0); CP_COMMIT();
    for (int kc = 0; kc < 32; kc++) {
        if (kc + 1 < 32) { stage(kc+1, (kc+1)&1); CP_COMMIT(); CP_WAIT1(); }
        else             { CP_WAIT0(); }
        __syncthreads();
        uint32_t base = sb + (kc&1)*14848;
        uint32_t aH[2][4], bH[4][4], bL[4][4];
        #pragma unroll
        for (int mi = 0; mi < 2; mi++)
            LDMX4(aH[mi], base + ((arow + mi*16)*24 + acol)*2);
        #pragma unroll
        for (int nj = 0; nj < 4; nj++) {
            uint32_t off = (brow*136 + wn*64 + nj*16 + bsel)*2;
            LDMX4T(bH[nj], base + 6144 + off);
            LDMX4T(bL[nj], base + 10496 + off);
        }
        #pragma unroll
        for (int mi = 0; mi < 2; mi++)
            #pragma unroll
            for (int ni = 0; ni < 8; ni++) {
                MMA_BF16(acc[mi][ni], aH[mi], &bH[ni>>1][(ni&1)*2]);
                MMA_BF16(acc[mi][ni], aH[mi], &bL[ni>>1][(ni&1)*2]);
            }
        __syncthreads();
    }
    int r = lane >> 2, cb = (lane & 3)*2;
    #pragma unroll
    for (int mi = 0; mi < 2; mi++)
        #pragma unroll
        for (int ni = 0; ni < 8; ni++) {
            int m = m0 + wm*32 + mi*16 + r;
            int nn = wn*64 + ni*8 + cb;
            int bt = btp*2 + (nn >> 6);
            int d = nn & 63;
            *(__nv_bfloat162*)&outh[(bt*Nv + m)*64 + d] =
                __nv_bfloat162(__float2bfloat16(acc[mi][ni][0]), __float2bfloat16(acc[mi][ni][1]));
            *(__nv_bfloat162*)&outh[(bt*Nv + m + 8)*64 + d] =
                __nv_bfloat162(__float2bfloat16(acc[mi][ni][2]), __float2bfloat16(acc[mi][ni][3]));
        }
}

// ---------------- gc (2-product, db): h@W0 + p1@W1 + p2@W2 + bias + h -> LN -> g_h2 ----
__global__ __launch_bounds__(256) void k_gc_mma(const float* __restrict__ gcb,
    const float* __restrict__ gg, const float* __restrict__ bg) {
    __shared__ __align__(16) char sm[DB_BYTES];
    int tid = threadIdx.x, lane = tid & 31, wid = tid >> 5;
    int wm = wid & 3, wn = wid >> 2;
    int r0g = blockIdx.x * 128;
    uint32_t sb = smem_u32(sm);

    const bf16* ih[3] = {g_hh, g_p1h, g_p2h};
    float acc[2][4][4] = {};

    auto stage = [&](int c, int b) {
        int mm = c >> 1, k0 = (c & 1) * 32;
        uint32_t base = sb + b*DB_STRIDE;
        db_stageA(base, ih[mm], r0g, 64, k0, tid);
        db_stageB(base, g_gcWh + mm*4096, g_gcWl + mm*4096, 64, 0, k0, tid);
    };

    stage(0, 0); CP_COMMIT();
    #pragma unroll
    for (int c = 0; c < 6; c++) {
        if (c + 1 < 6) { stage(c+1, (c+1)&1); CP_COMMIT(); CP_WAIT1(); }
        else           { CP_WAIT0(); }
        __syncthreads();
        db_compute(sb + (c&1)*DB_STRIDE, acc, lane, wm, wn);
        __syncthreads();
    }
    float* sO = (float*)sm;
    int r = lane >> 2, cb = (lane & 3)*2;
    #pragma unroll
    for (int mi = 0; mi < 2; mi++)
        #pragma unroll
        for (int ni = 0; ni < 4; ni++) {
            int m = wm*32 + mi*16 + r;
            int n = wn*32 + ni*8 + cb;
            float b0 = gcb[n] + gcb[64+n] + gcb[128+n];
            float b1 = gcb[n+1] + gcb[64+n+1] + gcb[128+n+1];
            float2 h0 = *(const float2*)&g_h[(r0g + m)*64 + n];
            float2 h1 = *(const float2*)&g_h[(r0g + m + 8)*64 + n];
            *(float2*)&sO[m*64 + n]     = make_float2(acc[mi][ni][0] + b0 + h0.x, acc[mi][ni][1] + b1 + h0.y);
            *(float2*)&sO[(m+8)*64 + n] = make_float2(acc[mi][ni][2] + b0 + h1.x, acc[mi][ni][3] + b1 + h1.y);
        }
    __syncthreads();
    ln256(sO, r0g, gg, bg, g_h2, g_h2h, (bf16*)0);
}

// ---------------- ffn1 (2-product, db): gelu(h2 @ W1 + b1) -> u hi ----------------
__global__ __launch_bounds__(256) void k_ffn1_mma(const float* __restrict__ b1) {
    __shared__ __align__(16) char sm[DB_BYTES];
    int tid = threadIdx.x, lane = tid & 31, wid = tid >> 5;
    int wm = wid & 3, wn = wid >> 2;
    int r0g = blockIdx.x * 128;
    int c0g = blockIdx.y * 64;
    uint32_t sb = smem_u32(sm);

    float acc[2][4][4] = {};
    db_stageA(sb, g_h2h, r0g, 64, 0, tid);
    db_stageB(sb, g_W1h, g_W1l, Fv, c0g, 0, tid);
    CP_COMMIT();
    #pragma unroll
    for (int c = 0; c < 2; c++) {
        if (c + 1 < 2) {
            uint32_t nb = sb + DB_STRIDE;
            db_stageA(nb, g_h2h, r0g, 64, 32, tid);
            db_stageB(nb, g_W1h, g_W1l, Fv, c0g, 32, tid);
            CP_COMMIT(); CP_WAIT1();
        } else CP_WAIT0();
        __syncthreads();
        db_compute(sb + (c&1)*DB_STRIDE, acc, lane, wm, wn);
        __syncthreads();
    }
    int r = lane >> 2, cb = (lane & 3)*2;
    #pragma unroll
    for (int mi = 0; mi < 2; mi++)
        #pragma unroll
        for (int ni = 0; ni < 4; ni++) {
            int m = r0g + wm*32 + mi*16 + r;
            int n = wn*32 + ni*8 + cb;
            float b0 = b1[c0g + n], b1v = b1[c0g + n + 1];
            float v[4] = {acc[mi][ni][0] + b0, acc[mi][ni][1] + b1v,
                          acc[mi][ni][2] + b0, acc[mi][ni][3] + b1v};
            #pragma unroll
            for (int j = 0; j < 4; j++)
                v[j] = 0.5f * v[j] * (1.0f + erff(v[j] * 0.70710678118654752f));
            *(__nv_bfloat162*)&g_uh[m*Fv + c0g + n] =
                __nv_bfloat162(__float2bfloat16(v[0]), __float2bfloat16(v[1]));
            *(__nv_bfloat162*)&g_uh[(m+8)*Fv + c0g + n] =
                __nv_bfloat162(__float2bfloat16(v[2]), __float2bfloat16(v[3]));
        }
}

// ---------------- ffn2 (2-product, db): u @ W2 + b2 + h2 -> LN -> out ----------------
__global__ __launch_bounds__(256) void k_ffn2_mma(const float* __restrict__ b2,
    const float* __restrict__ gf, const float* __restrict__ bf,
    float* __restrict__ out) {
    __shared__ __align__(16) char sm[DB_BYTES];
    int tid = threadIdx.x, lane = tid & 31, wid = tid >> 5;
    int wm = wid & 3, wn = wid >> 2;
    int r0g = blockIdx.x * 128;
    uint32_t sb = smem_u32(sm);

    float acc[2][4][4] = {};
    auto stage = [&](int c, int b) {
        uint32_t base = sb + b*DB_STRIDE;
        db_stageA(base, g_uh, r0g, Fv, c*32, tid);
        db_stageB(base, g_W2h, g_W2l, 64, 0, c*32, tid);
    };
    stage(0, 0); CP_COMMIT();
    #pragma unroll
    for (int c = 0; c < 8; c++) {
        if (c + 1 < 8) { stage(c+1, (c+1)&1); CP_COMMIT(); CP_WAIT1(); }
        else           { CP_WAIT0(); }
        __syncthreads();
        db_compute(sb + (c&1)*DB_STRIDE, acc, lane, wm, wn);
        __syncthreads();
    }
    float* sO = (float*)sm;
    int r = lane >> 2, cb = (lane & 3)*2;
    #pragma unroll
    for (int mi = 0; mi < 2; mi++)
        #pragma unroll
        for (int ni = 0; ni < 4; ni++) {
            int m = wm*32 + mi*16 + r;
            int n = wn*32 + ni*8 + cb;
            float b0 = b2[n], b1 = b2[n+1];
            float2 h0 = *(const float2*)&g_h2[(r0g + m)*64 + n];
            float2 h1 = *(const float2*)&g_h2[(r0g + m + 8)*64 + n];
            *(float2*)&sO[m*64 + n]     = make_float2(acc[mi][ni][0] + b0 + h0.x, acc[mi][ni][1] + b1 + h0.y);
            *(float2*)&sO[(m+8)*64 + n] = make_float2(acc[mi][ni][2] + b0 + h1.x, acc[mi][ni][3] + b1 + h1.y);
        }
    __syncthreads();
    ln256(sO, r0g, gf, bf, out, (bf16*)0, (bf16*)0);
}

// ---------------- launch ----------------
extern "C" void kernel_launch(void* const* d_in, const int* in_sizes, int n_in,
                              void* d_out, int out_size) {
    const float* x   = (const float*)d_in[0];
    const float* adj = (const float*)d_in[1];
    const float* bq  = (const float*)d_in[3];
    const float* bk  = (const float*)d_in[5];
    const float* bv  = (const float*)d_in[7];
    const float* bo  = (const float*)d_in[9];
    const float* gcb = (const float*)d_in[11];
    const float* b1  = (const float*)d_in[13];
    const float* b2  = (const float*)d_in[15];
    const float* g_t = (const float*)d_in[16];
    const float* b_t = (const float*)d_in[17];
    const float* g_g = (const float*)d_in[18];
    const float* b_g = (const float*)d_in[19];
    const float* g_f = (const float*)d_in[20];
    const float* b_f = (const float*)d_in[21];
    float* out = (float*)d_out;

    k_deg   <<<Nv, 128>>>(adj);
    k_ahat  <<<(Nv*Nv)/512, 512>>>(adj);
    k_asq   <<<dim3(4, 4), 256>>>();
    k_splitx<<<(BTNv*Dv)/1024, 256>>>(x);
    k_splitw<<<240, 256>>>((const float*)d_in[2], (const float*)d_in[4],
                           (const float*)d_in[6], (const float*)d_in[8],
                           (const float*)d_in[10], (const float*)d_in[12],
                           (const float*)d_in[14]);
    k_qkv_mma<<<RT128, 256>>>(bq, bk, bv);
    k_attn  <<<dim3(Nv, Bv), 256>>>();
    k_attnout_mma<<<RT128, 256>>>(x, bo, g_t, b_t);
    k_prop2 <<<dim3(8, 192), 256>>>();
    k_gc_mma<<<RT128, 256>>>(gcb, g_g, b_g);
    k_ffn1_mma<<<dim3(RT128, Fv/64), 256>>>(b1);
    k_ffn2_mma<<<RT128, 256>>>(b2, g_f, b_f, out);
}